// round 7
// baseline (speedup 1.0000x reference)
#include <cuda_runtime.h>

#define NATOMS 11776
#define NB     368
#define NTOK   512
#define NL     3
#define MB     32
#define SMS2   36

// ---- scratch ----
__device__ float g_sln[NATOMS*128];
__device__ float g_a  [NATOMS*128];
__device__ float g_qkv[NATOMS*384];   // later reused for atom_out
__device__ float g_o  [NATOMS*128];
__device__ float g_ph [NATOMS*16];
__device__ float g_pw [NB*128*16];
__device__ float g_pb [NB*4*32*128];
__device__ float g_tok[NTOK*384];
__device__ float g_u  [NTOK*256];

// ---- packed weights: P[(k/4)*OUT + j] = float4{ W[j][k..k+3] } ----
__device__ float4 gP_cond [32*128];
__device__ float4 gP_ph   [32*16];
__device__ float4 gP_pw   [32*16];
__device__ float4 gP_sln  [NL*32*256];
__device__ float4 gP_qkv  [NL*32*384];
__device__ float4 gP_out  [NL*32*128];
__device__ float4 gP_ada  [NL*32*256];
__device__ float4 gP_ta   [NL*32*512];
__device__ float4 gP_tb   [NL*64*128];
__device__ float4 gP_gate [NL*32*128];
__device__ float4 gP_tok  [32*384];
__device__ float4 gP_trunk[96*384];
__device__ float4 gP_struc[96*384];
__device__ float4 gP_pairin[8*128];
__device__ float4 gP_outer[96*256];

__device__ __forceinline__ float sigf(float x){ return 1.0f/(1.0f+__expf(-x)); }

#define ZERO32(a) { _Pragma("unroll") for(int _m=0;_m<32;_m++) a[_m]=0.f; }
#define ZERON32(a,N) { _Pragma("unroll") for(int _n=0;_n<(N);_n++) ZERO32(a[_n]); }

// Register-blocked GEMV over 32-atom tile: NC output chunks of 128
// (chunk offset COFF float4), x tile in smem [k][m] stride SMS2, packed weights.
template<int K4, int NC, int COFF=128>
__device__ __forceinline__ void gemv32(const float4* __restrict__ Wb, int out4,
                                       const float* __restrict__ sX, float (*acc)[32])
{
    #pragma unroll 2
    for (int k4=0;k4<K4;k4++){
        float4 w[NC];
        #pragma unroll
        for (int n=0;n<NC;n++) w[n]=Wb[k4*out4 + n*COFF];
        #pragma unroll
        for (int c=0;c<4;c++){
            const float4* xp = (const float4*)(sX + (k4*4+c)*SMS2);
            float4 x[8];
            #pragma unroll
            for (int r=0;r<8;r++) x[r]=xp[r];
            #pragma unroll
            for (int n=0;n<NC;n++){
                float wc=(c==0)?w[n].x:(c==1)?w[n].y:(c==2)?w[n].z:w[n].w;
                #pragma unroll
                for (int r=0;r<8;r++){
                    acc[n][r*4]  +=x[r].x*wc;
                    acc[n][r*4+1]+=x[r].y*wc;
                    acc[n][r*4+2]+=x[r].z*wc;
                    acc[n][r*4+3]+=x[r].w*wc;
                }
            }
        }
    }
}

// per-atom mean/rstd over 128 dims for 32 atoms; 128 threads hold v[m]=dim tid
// of atom m. stage needs >= 4544 floats. single-pass E[x^2]-mu^2.
__device__ __forceinline__ void rowstats32(const float v[32], float* stage,
                                           float mu[32], float rs[32])
{
    int tid=threadIdx.x;
    __syncthreads();
    #pragma unroll
    for (int m=0;m<32;m++) stage[m*132+tid]=v[m];
    __syncthreads();
    {
        int row=tid>>2, seg=tid&3;
        float s=0.f, s2=0.f;
        #pragma unroll
        for (int u=0;u<32;u++){ float x=stage[row*132+seg*32+u]; s+=x; s2+=x*x; }
        stage[4224+tid]=s; stage[4352+tid]=s2;
    }
    __syncthreads();
    if (tid<32){
        float s=0.f,s2=0.f;
        #pragma unroll
        for (int u=0;u<4;u++){ s+=stage[4224+tid*4+u]; s2+=stage[4352+tid*4+u]; }
        float m_=s*(1.0f/128.0f), e2=s2*(1.0f/128.0f);
        stage[4480+tid]=m_;
        stage[4512+tid]=rsqrtf(e2-m_*m_+1e-5f);
    }
    __syncthreads();
    #pragma unroll
    for (int m=0;m<32;m++){ mu[m]=stage[4480+m]; rs[m]=stage[4512+m]; }
    __syncthreads();
}

// ---- one-shot weight packer ----
struct PackDesc { const float* src; float* dst; int OUT; int K; int L; };
struct PackArgs { PackDesc d[15]; };
__global__ void k_pack(PackArgs pa)
{
    PackDesc pd = pa.d[blockIdx.y];
    int total = pd.L*pd.OUT*pd.K;
    int K4 = pd.K>>2;
    for (int idx = blockIdx.x*256 + threadIdx.x; idx < total; idx += gridDim.x*256){
        int c = idx&3; int t = idx>>2;
        int j = t % pd.OUT; int q = t / pd.OUT;
        int k4 = q % K4;    int l = q / K4;
        pd.dst[idx] = pd.src[((size_t)l*pd.OUT + j)*pd.K + k4*4 + c];
    }
}

// K1: c = af@Wcond^T ; a=c ; s_ln=LN(c)
__global__ void __launch_bounds__(128) k_cond(const float* __restrict__ af)
{
    __shared__ __align__(16) float sA[128*SMS2];
    int j = threadIdx.x; int a0 = blockIdx.x*MB;
    for (int idx=j; idx<128*MB; idx+=128){
        int m=idx>>7, k=idx&127;
        sA[k*SMS2+m] = af[(size_t)(a0+m)*128 + k];
    }
    __syncthreads();
    float acc[1][32]; ZERON32(acc,1);
    gemv32<32,1>(gP_cond + j, 128, sA, acc);
    #pragma unroll
    for (int m=0;m<32;m++) g_a[(size_t)(a0+m)*128+j]=acc[0][m];
    float mu[32], rs[32];
    rowstats32(acc[0], sA, mu, rs);
    #pragma unroll
    for (int m=0;m<32;m++) g_sln[(size_t)(a0+m)*128+j]=(acc[0][m]-mu[m])*rs[m];
}

// K2: fused ph (blocks < NATOMS/16) and pw (rest)
__global__ void __launch_bounds__(256) k_phpw()
{
    __shared__ float xs[16*132];
    int tid=threadIdx.x;
    bool isph = blockIdx.x < (NATOMS/16);
    int r0 = isph ? blockIdx.x*16 : (blockIdx.x-(NATOMS/16))*16;
    for (int idx=tid; idx<16*128; idx+=256){
        int r=idx>>7,k=idx&127;
        int row=r0+r;
        int atom;
        if (isph) atom=row;
        else { int nb=row>>7, kk=row&127; atom=nb*32+kk-48; atom=max(0,min(atom,NATOMS-1)); }
        xs[r*132+k]=fmaxf(g_sln[(size_t)atom*128+k],0.f);
    }
    __syncthreads();
    int o=tid&15, r=tid>>4;
    const float4* W = isph ? gP_ph : gP_pw;
    float acc=0;
    #pragma unroll 4
    for (int k4=0;k4<32;k4++){
        float4 w = W[k4*16+o];
        const float* xb=&xs[r*132+k4*4];
        acc += xb[0]*w.x+xb[1]*w.y+xb[2]*w.z+xb[3]*w.w;
    }
    if (isph) g_ph[(size_t)(r0+r)*16+o]=acc;
    else      g_pw[(size_t)(r0+r)*16+o]=acc;
}

// K3: pair bias (p + MLP + LN + head proj + mask fold)
__global__ void __launch_bounds__(128) k_pb(const float* __restrict__ W1g,
                                            const float* __restrict__ W2g,
                                            const float* __restrict__ lnw,
                                            const float* __restrict__ lnb,
                                            const float* __restrict__ pbw)
{
    __shared__ float W1[256], W2[256], PBW[64], LW[16], LB[16], PH[16];
    int tid=threadIdx.x;
    int blk=blockIdx.x; int nb=blk>>5, q=blk&31;
    for (int idx=tid; idx<256; idx+=128){ W1[idx]=W1g[idx]; W2[idx]=W2g[idx]; }
    if (tid<64) PBW[tid]=pbw[tid];
    if (tid<16){ LW[tid]=lnw[tid]; LB[tid]=lnb[tid];
                 PH[tid]=g_ph[(size_t)(nb*32+q)*16+tid]; }
    __syncthreads();

    float p[16];
    { const float4* pwp=(const float4*)&g_pw[(size_t)(nb*128+tid)*16];
      float4 a=pwp[0],b=pwp[1],c=pwp[2],d=pwp[3];
      p[0]=a.x;p[1]=a.y;p[2]=a.z;p[3]=a.w; p[4]=b.x;p[5]=b.y;p[6]=b.z;p[7]=b.w;
      p[8]=c.x;p[9]=c.y;p[10]=c.z;p[11]=c.w; p[12]=d.x;p[13]=d.y;p[14]=d.z;p[15]=d.w; }
    #pragma unroll
    for (int i=0;i<16;i++) p[i]+=PH[i];

    float t[16], u[16];
    #pragma unroll
    for (int i=0;i<16;i++) t[i]=fmaxf(p[i],0.f);
    #pragma unroll
    for (int o=0;o<16;o++){
        float s=0;
        #pragma unroll
        for (int i=0;i<16;i++) s+=t[i]*W1[o*16+i];
        u[o]=fmaxf(s,0.f);
    }
    #pragma unroll
    for (int o=0;o<16;o++){
        float s=0;
        #pragma unroll
        for (int i=0;i<16;i++) s+=u[i]*W2[o*16+i];
        p[o]+=s;
    }
    float mu=0;
    #pragma unroll
    for (int i=0;i<16;i++) mu+=p[i];
    mu*=(1.0f/16.0f);
    float var=0;
    #pragma unroll
    for (int i=0;i<16;i++){ float d=p[i]-mu; var+=d*d; }
    float rsd=rsqrtf(var*(1.0f/16.0f)+1e-5f);
    float y[16];
    #pragma unroll
    for (int i=0;i<16;i++) y[i]=(p[i]-mu)*rsd*LW[i]+LB[i];

    int win = nb*32 + tid - 48;
    float neg = (win>=0 && win<NATOMS) ? 0.f : -1.0e9f;
    #pragma unroll
    for (int h=0;h<4;h++){
        float s=0;
        #pragma unroll
        for (int i=0;i<16;i++) s+=y[i]*PBW[h*16+i];
        g_pb[(size_t)((nb*4+h)*32+q)*128+tid]=s+neg;
    }
}

// K4: per-layer stage A
__global__ void __launch_bounds__(128) k_stageA(const float* __restrict__ qbias, int l)
{
    __shared__ __align__(16) float sB[128*SMS2];
    __shared__ __align__(16) float sX[128*SMS2];
    int j=threadIdx.x; int a0=blockIdx.x*MB;
    for (int idx=j; idx<128*MB; idx+=128){
        int m=idx>>7,k=idx&127;
        sB[k*SMS2+m]=g_sln[(size_t)(a0+m)*128+k];
    }
    float av[32];
    #pragma unroll
    for (int m=0;m<32;m++) av[m]=g_a[(size_t)(a0+m)*128+j];

    float mu[32],rs[32];
    rowstats32(av, sX, mu, rs);

    float acc[2][32]; ZERON32(acc,2);
    gemv32<32,2>(gP_sln + (size_t)l*32*256 + j, 256, sB, acc);
    #pragma unroll
    for (int m=0;m<32;m++)
        sX[j*SMS2+m]=sigf(acc[0][m])*((av[m]-mu[m])*rs[m])+acc[1][m];
    __syncthreads();

    float q3[3][32]; ZERON32(q3,3);
    gemv32<32,3>(gP_qkv + (size_t)l*32*384 + j, 384, sX, q3);
    float qb = qbias[l*128+j];
    #pragma unroll
    for (int m=0;m<32;m++){
        size_t b=(size_t)(a0+m)*384;
        g_qkv[b+j]      =q3[0][m]+qb;
        g_qkv[b+128+j]  =q3[1][m];
        g_qkv[b+256+j]  =q3[2][m];
    }
}

// K5: windowed attention per (nb, head) — outer-product register-blocked
__global__ void __launch_bounds__(128) k_attn()
{
    extern __shared__ float sm[];
    float* vb  = sm;           // 128*33 = 4224
    float* qT  = vb + 4224;    // 32*36  = 1152
    float* sc  = qT + 1152;    // 4224 (32*129 used; aliased as red in AV epilogue)
    float* scT = sc + 4224;    // 128*36 = 4608
    int blk=blockIdx.x; int nb=blk>>2, h=blk&3;
    int tid=threadIdx.x;

    for (int idx=tid; idx<128*32; idx+=128){
        int kk=idx>>5, d=idx&31;
        int atom=nb*32+kk-48; atom=max(0,min(atom,NATOMS-1));
        vb[kk*33+d]=g_qkv[(size_t)atom*384+256+h*32+d];
    }
    for (int idx=tid; idx<1024; idx+=128){
        int d=idx>>5, qq=idx&31;
        qT[d*36+qq]=g_qkv[(size_t)(nb*32+qq)*384 + h*32 + d];
    }
    float kreg[32];
    {
        int atom=nb*32+tid-48; atom=max(0,min(atom,NATOMS-1));
        const float4* kr=(const float4*)&g_qkv[(size_t)atom*384+128+h*32];
        #pragma unroll
        for (int i=0;i<8;i++){
            float4 v=kr[i];
            kreg[i*4]=v.x; kreg[i*4+1]=v.y; kreg[i*4+2]=v.z; kreg[i*4+3]=v.w;
        }
    }
    __syncthreads();

    float acc[32];
    #pragma unroll
    for (int i=0;i<32;i++) acc[i]=0.f;
    #pragma unroll 4
    for (int d=0;d<32;d++){
        float kd=kreg[d];
        const float4* qp=(const float4*)&qT[d*36];
        #pragma unroll
        for (int r=0;r<8;r++){
            float4 q4=qp[r];
            acc[r*4]  +=q4.x*kd;
            acc[r*4+1]+=q4.y*kd;
            acc[r*4+2]+=q4.z*kd;
            acc[r*4+3]+=q4.w*kd;
        }
    }
    const float scale=0.1767766952966369f;
    const float* pbp=&g_pb[(size_t)((nb*4+h)*32)*128];
    #pragma unroll 4
    for (int qq=0;qq<32;qq++)
        sc[qq*129+tid]=acc[qq]*scale + pbp[(size_t)qq*128+tid];
    __syncthreads();

    {
        int qq2=tid>>2, sub=tid&3;
        float mx=-1e30f;
        #pragma unroll 4
        for (int i=0;i<32;i++) mx=fmaxf(mx, sc[qq2*129+sub+4*i]);
        mx=fmaxf(mx,__shfl_xor_sync(0xffffffffu,mx,1));
        mx=fmaxf(mx,__shfl_xor_sync(0xffffffffu,mx,2));
        float s=0;
        #pragma unroll 4
        for (int i=0;i<32;i++){
            int id=qq2*129+sub+4*i;
            float e=__expf(sc[id]-mx); sc[id]=e; s+=e;
        }
        s+=__shfl_xor_sync(0xffffffffu,s,1);
        s+=__shfl_xor_sync(0xffffffffu,s,2);
        float inv=1.0f/s;
        #pragma unroll 4
        for (int i=0;i<32;i++) sc[qq2*129+sub+4*i]*=inv;
    }
    __syncthreads();

    for (int idx=tid; idx<4096; idx+=128){
        int qq=idx&31, kk=idx>>5;
        scT[kk*36+qq]=sc[qq*129+kk];
    }
    __syncthreads();

    #pragma unroll
    for (int i=0;i<32;i++) acc[i]=0.f;
    int d=tid&31, kg=tid>>5;
    #pragma unroll 4
    for (int ki=0;ki<32;ki++){
        int k=kg*32+ki;
        float v=vb[k*33+d];
        const float4* sp=(const float4*)&scT[k*36];
        #pragma unroll
        for (int r=0;r<8;r++){
            float4 s4=sp[r];
            acc[r*4]  +=s4.x*v;
            acc[r*4+1]+=s4.y*v;
            acc[r*4+2]+=s4.z*v;
            acc[r*4+3]+=s4.w*v;
        }
    }
    float* red = sc;
    #pragma unroll
    for (int qq=0;qq<32;qq++) red[kg*1056+qq*33+d]=acc[qq];
    __syncthreads();
    for (int idx=tid; idx<1024; idx+=128){
        int qq=idx>>5, dd=idx&31;
        float s=red[qq*33+dd]+red[1056+qq*33+dd]+red[2112+qq*33+dd]+red[3168+qq*33+dd];
        g_o[(size_t)(nb*32+qq)*128 + h*32 + dd]=s;
    }
}

// K7: per-layer stage C (dynamic smem: sA 128*36, sB 128*36, sC 256*36 floats)
__global__ void __launch_bounds__(128) k_stageC(const float* __restrict__ outb,
                                                const float* __restrict__ gateb, int l)
{
    extern __shared__ __align__(16) float smc[];
    float* sA = smc;                 // 128*SMS2 = 4608
    float* sB = sA + 128*SMS2;       // 4608
    float* sC = sB + 128*SMS2;       // 256*SMS2 = 9216
    int j=threadIdx.x; int a0=blockIdx.x*MB;
    for (int idx=j; idx<128*MB; idx+=128){
        int m=idx>>7,k=idx&127;
        sA[k*SMS2+m]=g_o  [(size_t)(a0+m)*128+k];
        sB[k*SMS2+m]=g_sln[(size_t)(a0+m)*128+k];
    }
    float av[32];
    #pragma unroll
    for (int m=0;m<32;m++) av[m]=g_a[(size_t)(a0+m)*128+j];
    __syncthreads();

    float anew[32];
    {
        float o1[1][32]; ZERON32(o1,1);
        gemv32<32,1>(gP_out + (size_t)l*32*128 + j, 128, sA, o1);
        float ob=outb[l*128+j];
        #pragma unroll
        for (int m=0;m<32;m++) anew[m]=av[m]+o1[0][m]+ob;
    }

    float mu[32],rs[32];
    rowstats32(anew, sC, mu, rs);

    {
        float ad[2][32]; ZERON32(ad,2);
        gemv32<32,2>(gP_ada + (size_t)l*32*256 + j, 256, sB, ad);
        #pragma unroll
        for (int m=0;m<32;m++)
            sA[j*SMS2+m]=sigf(ad[0][m])*((anew[m]-mu[m])*rs[m])+ad[1][m];
    }
    __syncthreads();

    #pragma unroll 1
    for (int s=0;s<2;s++){
        float tp[2][32]; ZERON32(tp,2);
        gemv32<32,2,256>(gP_ta + (size_t)l*32*512 + s*128 + j, 512, sA, tp);
        #pragma unroll
        for (int m=0;m<32;m++){
            float a_=tp[0][m];
            sC[(s*128+j)*SMS2+m]=a_*sigf(a_)*tp[1][m];
        }
    }
    __syncthreads();

    float hv[1][32]; ZERON32(hv,1);
    gemv32<64,1>(gP_tb + (size_t)l*64*128 + j, 128, sC, hv);

    float gg[1][32]; ZERON32(gg,1);
    gemv32<32,1>(gP_gate + (size_t)l*32*128 + j, 128, sB, gg);

    float gb_=gateb[l*128+j];
    #pragma unroll
    for (int m=0;m<32;m++)
        g_a[(size_t)(a0+m)*128+j]=anew[m]+sigf(gg[0][m]+gb_)*hv[0][m];
}

// K8: atom_out = relu(a @ W_tok^T) -> g_qkv (reuse)
__global__ void __launch_bounds__(128) k_tokproj()
{
    __shared__ __align__(16) float sA[128*SMS2];
    int j=threadIdx.x; int a0=blockIdx.x*MB;
    for (int idx=j; idx<128*MB; idx+=128){
        int m=idx>>7,k=idx&127;
        sA[k*SMS2+m]=g_a[(size_t)(a0+m)*128+k];
    }
    __syncthreads();
    float q3[3][32]; ZERON32(q3,3);
    gemv32<32,3>(gP_tok + j, 384, sA, q3);
    #pragma unroll
    for (int m=0;m<32;m++){
        size_t b=(size_t)(a0+m)*384;
        g_qkv[b+j]    =fmaxf(q3[0][m],0.f);
        g_qkv[b+128+j]=fmaxf(q3[1][m],0.f);
        g_qkv[b+256+j]=fmaxf(q3[2][m],0.f);
    }
}

// K9: deterministic segment mean
__global__ void __launch_bounds__(128) k_tokmean(const int* __restrict__ a2t)
{
    __shared__ int slo,shi;
    int t=blockIdx.x;
    if (threadIdx.x==0){
        int lo=0,hi=NATOMS;
        while(lo<hi){int mid=(lo+hi)>>1; if(a2t[mid]<t) lo=mid+1; else hi=mid;}
        slo=lo; int lo2=lo; hi=NATOMS;
        while(lo2<hi){int mid=(lo2+hi)>>1; if(a2t[mid]<t+1) lo2=mid+1; else hi=mid;}
        shi=lo2;
    }
    __syncthreads();
    int lo=slo,hi=shi;
    float inv=1.0f/fmaxf((float)(hi-lo),1.0f);
    #pragma unroll
    for (int s=0;s<3;s++){
        int d=s*128+threadIdx.x;
        float sum=0;
        for (int a=lo;a<hi;a++) sum+=g_qkv[(size_t)a*384+d];
        g_tok[(size_t)t*384+d]=sum*inv;
    }
}

// K10: s_trunk, s_struct -> d_out ; u -> g_u  (dynamic smem: 384*SMS2 floats)
__global__ void __launch_bounds__(128) k_trunkstruct(float* __restrict__ out)
{
    extern __shared__ __align__(16) float sT[];
    int j=threadIdx.x; int t0=blockIdx.x*MB;
    for (int idx=j; idx<384*MB; idx+=128){
        int m=idx/384, k=idx%384;
        sT[k*SMS2+m]=g_tok[(size_t)(t0+m)*384+k];
    }
    __syncthreads();
    {
        float c3[3][32]; ZERON32(c3,3);
        gemv32<96,3>(gP_trunk + j, 384, sT, c3);
        #pragma unroll
        for (int m=0;m<32;m++){
            size_t b=(size_t)(t0+m)*384;
            out[b+j]=c3[0][m]; out[b+128+j]=c3[1][m]; out[b+256+j]=c3[2][m];
        }
    }
    {
        float* o2 = out + (size_t)NTOK*384;
        float c3[3][32]; ZERON32(c3,3);
        gemv32<96,3>(gP_struc + j, 384, sT, c3);
        #pragma unroll
        for (int m=0;m<32;m++){
            size_t b=(size_t)(t0+m)*384;
            o2[b+j]=c3[0][m]; o2[b+128+j]=c3[1][m]; o2[b+256+j]=c3[2][m];
        }
    }
    {
        float c2[2][32]; ZERON32(c2,2);
        gemv32<96,2>(gP_outer + j, 256, sT, c2);
        #pragma unroll
        for (int m=0;m<32;m++){
            size_t b=(size_t)(t0+m)*256;
            g_u[b+j]=c2[0][m]; g_u[b+128+j]=c2[1][m];
        }
    }
}

// K11: pair = tpf@W_pairin^T + u_lo[i] + u_hi[j] — weights in registers
__global__ void __launch_bounds__(128) k_pair(const float* __restrict__ tpf,
                                              float* __restrict__ outp)
{
    __shared__ __align__(16) float tj[8*32];
    int i=blockIdx.x, c=threadIdx.x;
    float4 w[8];
    #pragma unroll
    for (int k4=0;k4<8;k4++) w[k4]=gP_pairin[k4*128+c];
    float uiv=g_u[(size_t)i*256+c];
    for (int j0=0;j0<NTOK;j0+=8){
        __syncthreads();
        for (int idx=c; idx<256; idx+=128)
            tj[idx]=tpf[((size_t)i*NTOK+j0)*32 + idx];
        __syncthreads();
        #pragma unroll
        for (int jj=0;jj<8;jj++){
            int j=j0+jj;
            float a=uiv+g_u[(size_t)j*256+128+c];
            const float4* tp=(const float4*)&tj[jj*32];
            #pragma unroll
            for (int k4=0;k4<8;k4++){
                float4 t4=tp[k4];
                a += w[k4].x*t4.x + w[k4].y*t4.y + w[k4].z*t4.z + w[k4].w*t4.w;
            }
            outp[((size_t)i*NTOK+j)*128+c]=a;
        }
    }
}

extern "C" void kernel_launch(void* const* d_in, const int* in_sizes, int n_in,
                              void* d_out, int out_size)
{
    const float* af      = (const float*)d_in[0];
    const float* tpf     = (const float*)d_in[1];
    const float* W_cond  = (const float*)d_in[2];
    const float* W_ph    = (const float*)d_in[3];
    const float* W_pw    = (const float*)d_in[4];
    const float* W_mlp1  = (const float*)d_in[5];
    const float* W_mlp2  = (const float*)d_in[6];
    const float* pb_ln_w = (const float*)d_in[7];
    const float* pb_ln_b = (const float*)d_in[8];
    const float* pb_w    = (const float*)d_in[9];
    const float* sln_w   = (const float*)d_in[10];
    const float* qkv_w   = (const float*)d_in[11];
    const float* q_bias  = (const float*)d_in[12];
    const float* out_w   = (const float*)d_in[13];
    const float* out_b   = (const float*)d_in[14];
    const float* ada_w   = (const float*)d_in[15];
    const float* ta_w    = (const float*)d_in[16];
    const float* tb_w    = (const float*)d_in[17];
    const float* gate_w  = (const float*)d_in[18];
    const float* gate_b  = (const float*)d_in[19];
    const float* W_tok   = (const float*)d_in[20];
    const float* W_trunk = (const float*)d_in[21];
    const float* W_struct= (const float*)d_in[22];
    const float* W_pairin= (const float*)d_in[23];
    const float* W_outer = (const float*)d_in[24];
    const int*   a2t     = (const int*)d_in[28];
    float* out = (float*)d_out;

    PackArgs pa;
    void* p;
    #define SETP(i,sym,srcp,OUTv,Kv,Lv) \
        cudaGetSymbolAddress(&p, sym); \
        pa.d[i] = PackDesc{ srcp, (float*)p, OUTv, Kv, Lv };
    SETP(0,  gP_cond,   W_cond,   128,128,1);
    SETP(1,  gP_ph,     W_ph,      16,128,1);
    SETP(2,  gP_pw,     W_pw,      16,128,1);
    SETP(3,  gP_sln,    sln_w,    256,128,3);
    SETP(4,  gP_qkv,    qkv_w,    384,128,3);
    SETP(5,  gP_out,    out_w,    128,128,3);
    SETP(6,  gP_ada,    ada_w,    256,128,3);
    SETP(7,  gP_ta,     ta_w,     512,128,3);
    SETP(8,  gP_tb,     tb_w,     128,256,3);
    SETP(9,  gP_gate,   gate_w,   128,128,3);
    SETP(10, gP_tok,    W_tok,    384,128,1);
    SETP(11, gP_trunk,  W_trunk,  384,384,1);
    SETP(12, gP_struc,  W_struct, 384,384,1);
    SETP(13, gP_pairin, W_pairin, 128, 32,1);
    SETP(14, gP_outer,  W_outer,  256,384,1);
    #undef SETP
    k_pack<<<dim3(96,15),256>>>(pa);

    const int NBLK = NATOMS/MB;              // 368
    k_cond<<<NBLK,128>>>(af);
    k_phpw<<<NATOMS/16 + NB*128/16,256>>>();
    k_pb  <<<NB*32,128>>>(W_mlp1,W_mlp2,pb_ln_w,pb_ln_b,pb_w);

    const int ATTN_SMEM = (4224+1152+4224+4608)*4;      // 56832 B
    const int STC_SMEM  = (128*SMS2*2 + 256*SMS2)*4;    // 73728 B
    const int TRK_SMEM  = (384*SMS2)*4;                 // 55296 B
    cudaFuncSetAttribute(k_attn, cudaFuncAttributeMaxDynamicSharedMemorySize, ATTN_SMEM);
    cudaFuncSetAttribute(k_stageC, cudaFuncAttributeMaxDynamicSharedMemorySize, STC_SMEM);
    cudaFuncSetAttribute(k_trunkstruct, cudaFuncAttributeMaxDynamicSharedMemorySize, TRK_SMEM);
    for (int l=0;l<NL;l++){
        k_stageA<<<NBLK,128>>>(q_bias,l);
        k_attn  <<<NB*4,128,ATTN_SMEM>>>();
        k_stageC<<<NBLK,128,STC_SMEM>>>(out_b,gate_b,l);
    }

    k_tokproj<<<NBLK,128>>>();
    k_tokmean<<<NTOK,128>>>(a2t);
    k_trunkstruct<<<NTOK/MB,128,TRK_SMEM>>>(out);
    k_pair<<<NTOK,128>>>(tpf, out + (size_t)2*NTOK*384);
}

// round 8
// speedup vs baseline: 1.1074x; 1.1074x over previous
#include <cuda_runtime.h>

#define NATOMS 11776
#define NB     368
#define NTOK   512
#define NL     3
#define MB     16
#define SMS    20

// ---- scratch ----
__device__ float g_sln[NATOMS*128];
__device__ float g_a  [NATOMS*128];
__device__ float g_qkv[NATOMS*384];   // later reused for atom_out
__device__ float g_o  [NATOMS*128];
__device__ float g_ph [NATOMS*16];
__device__ float g_pw [NB*128*16];
__device__ float g_pb [NB*4*32*128];
__device__ float g_tok[NTOK*384];
__device__ float g_u  [NTOK*256];

// ---- packed weights: P[(k/4)*OUT + j] = float4{ W[j][k..k+3] } ----
__device__ float4 gP_cond [32*128];
__device__ float4 gP_ph   [32*16];
__device__ float4 gP_pw   [32*16];
__device__ float4 gP_sln  [NL*32*256];
__device__ float4 gP_qkv  [NL*32*384];
__device__ float4 gP_out  [NL*32*128];
__device__ float4 gP_ada  [NL*32*256];
__device__ float4 gP_ta   [NL*32*512];
__device__ float4 gP_tb   [NL*64*128];
__device__ float4 gP_gate [NL*32*128];
__device__ float4 gP_tok  [32*384];
__device__ float4 gP_trunk[96*384];
__device__ float4 gP_struc[96*384];
__device__ float4 gP_pairin[8*128];
__device__ float4 gP_outer[96*256];

__device__ __forceinline__ float sigf(float x){ return 1.0f/(1.0f+__expf(-x)); }

#define LD16(x0,x1,x2,x3,base) { const float4* _p=(const float4*)(base); \
  x0=_p[0]; x1=_p[1]; x2=_p[2]; x3=_p[3]; }
#define FMA16(acc,wv_,x0,x1,x2,x3) { \
  acc[0]+=x0.x*(wv_);  acc[1]+=x0.y*(wv_);  acc[2]+=x0.z*(wv_);  acc[3]+=x0.w*(wv_); \
  acc[4]+=x1.x*(wv_);  acc[5]+=x1.y*(wv_);  acc[6]+=x1.z*(wv_);  acc[7]+=x1.w*(wv_); \
  acc[8]+=x2.x*(wv_);  acc[9]+=x2.y*(wv_);  acc[10]+=x2.z*(wv_); acc[11]+=x2.w*(wv_); \
  acc[12]+=x3.x*(wv_); acc[13]+=x3.y*(wv_); acc[14]+=x3.z*(wv_); acc[15]+=x3.w*(wv_); }
#define ZERO16(a) { _Pragma("unroll") for(int _m=0;_m<16;_m++) a[_m]=0.f; }
#define ZERON(a,N) { _Pragma("unroll") for(int _n=0;_n<(N);_n++) ZERO16(a[_n]); }

// Register-blocked GEMV: NC output chunks of 128 (chunk offset COFF float4),
// x tile in smem [k][m] (stride SMS), packed weights.
template<int K4, int NC, int COFF=128>
__device__ __forceinline__ void gemvN(const float4* __restrict__ Wb, int out4,
                                      const float* __restrict__ sX, float (*acc)[16])
{
    #pragma unroll 2
    for (int k4=0;k4<K4;k4++){
        float4 w[NC];
        #pragma unroll
        for (int n=0;n<NC;n++) w[n]=Wb[k4*out4 + n*COFF];
        const float* xb = sX + (k4<<2)*SMS;
        #pragma unroll
        for (int c=0;c<4;c++){
            float4 x0,x1,x2,x3; LD16(x0,x1,x2,x3, xb + c*SMS);
            #pragma unroll
            for (int n=0;n<NC;n++){
                float wc = (c==0)?w[n].x : (c==1)?w[n].y : (c==2)?w[n].z : w[n].w;
                FMA16(acc[n],wc,x0,x1,x2,x3);
            }
        }
    }
}

// per-atom mean/rstd over 128 dims; 128 threads hold v[m]=dim tid of atom m.
__device__ __forceinline__ void rowstats128(const float v[16], float* stage,
                                            float mu[16], float rs[16])
{
    const int tid = threadIdx.x;
    const int row = tid>>3, seg = tid&7;
    for (int pass=0; pass<2; pass++){
        __syncthreads();
        #pragma unroll
        for (int m=0;m<16;m++){
            float x = (pass==0)? v[m] : (v[m]-mu[m]);
            stage[m*132+tid] = (pass==0)? x : x*x;
        }
        __syncthreads();
        { float s=0;
          #pragma unroll
          for (int u=0;u<16;u++) s+=stage[row*132+seg*16+u];
          stage[2112+tid]=s; }
        __syncthreads();
        if (tid<16){ float t2=0;
          #pragma unroll
          for (int u=0;u<8;u++) t2+=stage[2112+tid*8+u];
          stage[2240+tid]=t2*(1.0f/128.0f); }
        __syncthreads();
        if (pass==0){
            #pragma unroll
            for (int m=0;m<16;m++) mu[m]=stage[2240+m];
        } else {
            #pragma unroll
            for (int m=0;m<16;m++) rs[m]=rsqrtf(stage[2240+m]+1e-5f);
        }
    }
    __syncthreads();
}

// ---- one-shot weight packer ----
struct PackDesc { const float* src; float* dst; int OUT; int K; int L; };
struct PackArgs { PackDesc d[15]; };
__global__ void k_pack(PackArgs pa)
{
    PackDesc pd = pa.d[blockIdx.y];
    int total = pd.L*pd.OUT*pd.K;
    int K4 = pd.K>>2;
    for (int idx = blockIdx.x*256 + threadIdx.x; idx < total; idx += gridDim.x*256){
        int c = idx&3; int t = idx>>2;
        int j = t % pd.OUT; int q = t / pd.OUT;
        int k4 = q % K4;    int l = q / K4;
        pd.dst[idx] = pd.src[((size_t)l*pd.OUT + j)*pd.K + k4*4 + c];
    }
}

// K1: c = af@Wcond^T ; a=c ; s_ln=LN(c)
__global__ void __launch_bounds__(128) k_cond(const float* __restrict__ af)
{
    __shared__ __align__(16) float sA[128*SMS];
    int j = threadIdx.x; int a0 = blockIdx.x*MB;
    for (int idx=j; idx<128*MB; idx+=128){
        int m=idx>>7, k=idx&127;
        sA[k*SMS+m] = af[(size_t)(a0+m)*128 + k];
    }
    __syncthreads();
    float acc[1][16]; ZERON(acc,1);
    gemvN<32,1>(gP_cond + j, 128, sA, acc);
    #pragma unroll
    for (int m=0;m<16;m++) g_a[(size_t)(a0+m)*128+j]=acc[0][m];
    float mu[16], rs[16];
    rowstats128(acc[0], sA, mu, rs);
    #pragma unroll
    for (int m=0;m<16;m++) g_sln[(size_t)(a0+m)*128+j]=(acc[0][m]-mu[m])*rs[m];
}

// K2: fused ph (blocks < NATOMS/16) and pw (rest)
__global__ void __launch_bounds__(256) k_phpw()
{
    __shared__ float xs[16*132];
    int tid=threadIdx.x;
    bool isph = blockIdx.x < (NATOMS/16);
    int r0 = isph ? blockIdx.x*16 : (blockIdx.x-(NATOMS/16))*16;
    for (int idx=tid; idx<16*128; idx+=256){
        int r=idx>>7,k=idx&127;
        int row=r0+r;
        int atom;
        if (isph) atom=row;
        else { int nb=row>>7, kk=row&127; atom=nb*32+kk-48; atom=max(0,min(atom,NATOMS-1)); }
        xs[r*132+k]=fmaxf(g_sln[(size_t)atom*128+k],0.f);
    }
    __syncthreads();
    int o=tid&15, r=tid>>4;
    const float4* W = isph ? gP_ph : gP_pw;
    float acc=0;
    #pragma unroll 4
    for (int k4=0;k4<32;k4++){
        float4 w = W[k4*16+o];
        const float* xb=&xs[r*132+k4*4];
        acc += xb[0]*w.x+xb[1]*w.y+xb[2]*w.z+xb[3]*w.w;
    }
    if (isph) g_ph[(size_t)(r0+r)*16+o]=acc;
    else      g_pw[(size_t)(r0+r)*16+o]=acc;
}

// K3: pair bias (p + MLP + LN + head proj + mask fold)
__global__ void __launch_bounds__(128) k_pb(const float* __restrict__ W1g,
                                            const float* __restrict__ W2g,
                                            const float* __restrict__ lnw,
                                            const float* __restrict__ lnb,
                                            const float* __restrict__ pbw)
{
    __shared__ float W1[256], W2[256], PBW[64], LW[16], LB[16], PH[16];
    int tid=threadIdx.x;
    int blk=blockIdx.x; int nb=blk>>5, q=blk&31;
    for (int idx=tid; idx<256; idx+=128){ W1[idx]=W1g[idx]; W2[idx]=W2g[idx]; }
    if (tid<64) PBW[tid]=pbw[tid];
    if (tid<16){ LW[tid]=lnw[tid]; LB[tid]=lnb[tid];
                 PH[tid]=g_ph[(size_t)(nb*32+q)*16+tid]; }
    __syncthreads();

    float p[16];
    { const float4* pwp=(const float4*)&g_pw[(size_t)(nb*128+tid)*16];
      float4 a=pwp[0],b=pwp[1],c=pwp[2],d=pwp[3];
      p[0]=a.x;p[1]=a.y;p[2]=a.z;p[3]=a.w; p[4]=b.x;p[5]=b.y;p[6]=b.z;p[7]=b.w;
      p[8]=c.x;p[9]=c.y;p[10]=c.z;p[11]=c.w; p[12]=d.x;p[13]=d.y;p[14]=d.z;p[15]=d.w; }
    #pragma unroll
    for (int i=0;i<16;i++) p[i]+=PH[i];

    float t[16], u[16];
    #pragma unroll
    for (int i=0;i<16;i++) t[i]=fmaxf(p[i],0.f);
    #pragma unroll
    for (int o=0;o<16;o++){
        float s=0;
        #pragma unroll
        for (int i=0;i<16;i++) s+=t[i]*W1[o*16+i];
        u[o]=fmaxf(s,0.f);
    }
    #pragma unroll
    for (int o=0;o<16;o++){
        float s=0;
        #pragma unroll
        for (int i=0;i<16;i++) s+=u[i]*W2[o*16+i];
        p[o]+=s;
    }
    float mu=0;
    #pragma unroll
    for (int i=0;i<16;i++) mu+=p[i];
    mu*=(1.0f/16.0f);
    float var=0;
    #pragma unroll
    for (int i=0;i<16;i++){ float d=p[i]-mu; var+=d*d; }
    float rsd=rsqrtf(var*(1.0f/16.0f)+1e-5f);
    float y[16];
    #pragma unroll
    for (int i=0;i<16;i++) y[i]=(p[i]-mu)*rsd*LW[i]+LB[i];

    int win = nb*32 + tid - 48;
    float neg = (win>=0 && win<NATOMS) ? 0.f : -1.0e9f;
    #pragma unroll
    for (int h=0;h<4;h++){
        float s=0;
        #pragma unroll
        for (int i=0;i<16;i++) s+=y[i]*PBW[h*16+i];
        g_pb[(size_t)((nb*4+h)*32+q)*128+tid]=s+neg;
    }
}

// K4: per-layer stage A
__global__ void __launch_bounds__(128) k_stageA(const float* __restrict__ qbias, int l)
{
    __shared__ __align__(16) float sB[128*SMS];
    __shared__ __align__(16) float sX[128*SMS];
    int j=threadIdx.x; int a0=blockIdx.x*MB;
    for (int idx=j; idx<128*MB; idx+=128){
        int m=idx>>7,k=idx&127;
        sB[k*SMS+m]=g_sln[(size_t)(a0+m)*128+k];
    }
    float av[16];
    #pragma unroll
    for (int m=0;m<16;m++) av[m]=g_a[(size_t)(a0+m)*128+j];
    __syncthreads();

    float mu[16],rs[16];
    rowstats128(av, sX, mu, rs);

    float acc[2][16]; ZERON(acc,2);
    gemvN<32,2>(gP_sln + (size_t)l*32*256 + j, 256, sB, acc);
    #pragma unroll
    for (int m=0;m<16;m++)
        sX[j*SMS+m]=sigf(acc[0][m])*((av[m]-mu[m])*rs[m])+acc[1][m];
    __syncthreads();

    float q3[3][16]; ZERON(q3,3);
    gemvN<32,3>(gP_qkv + (size_t)l*32*384 + j, 384, sX, q3);
    float qb = qbias[l*128+j];
    #pragma unroll
    for (int m=0;m<16;m++){
        size_t b=(size_t)(a0+m)*384;
        g_qkv[b+j]      =q3[0][m]+qb;
        g_qkv[b+128+j]  =q3[1][m];
        g_qkv[b+256+j]  =q3[2][m];
    }
}

// K5: windowed attention per (nb, head) — outer-product register-blocked
__global__ void __launch_bounds__(128) k_attn()
{
    extern __shared__ float sm[];
    float* vb  = sm;           // 128*33 = 4224
    float* qT  = vb + 4224;    // 32*36  = 1152
    float* sc  = qT + 1152;    // 4224 (32*129 used; aliased as red in AV epilogue)
    float* scT = sc + 4224;    // 128*36 = 4608
    int blk=blockIdx.x; int nb=blk>>2, h=blk&3;
    int tid=threadIdx.x;

    for (int idx=tid; idx<128*32; idx+=128){
        int kk=idx>>5, d=idx&31;
        int atom=nb*32+kk-48; atom=max(0,min(atom,NATOMS-1));
        vb[kk*33+d]=g_qkv[(size_t)atom*384+256+h*32+d];
    }
    for (int idx=tid; idx<1024; idx+=128){
        int d=idx>>5, qq=idx&31;
        qT[d*36+qq]=g_qkv[(size_t)(nb*32+qq)*384 + h*32 + d];
    }
    float kreg[32];
    {
        int atom=nb*32+tid-48; atom=max(0,min(atom,NATOMS-1));
        const float4* kr=(const float4*)&g_qkv[(size_t)atom*384+128+h*32];
        #pragma unroll
        for (int i=0;i<8;i++){
            float4 v=kr[i];
            kreg[i*4]=v.x; kreg[i*4+1]=v.y; kreg[i*4+2]=v.z; kreg[i*4+3]=v.w;
        }
    }
    __syncthreads();

    float acc[32];
    #pragma unroll
    for (int i=0;i<32;i++) acc[i]=0.f;
    #pragma unroll 4
    for (int d=0;d<32;d++){
        float kd=kreg[d];
        const float4* qp=(const float4*)&qT[d*36];
        #pragma unroll
        for (int r=0;r<8;r++){
            float4 q4=qp[r];
            acc[r*4]  +=q4.x*kd;
            acc[r*4+1]+=q4.y*kd;
            acc[r*4+2]+=q4.z*kd;
            acc[r*4+3]+=q4.w*kd;
        }
    }
    const float scale=0.1767766952966369f;
    const float* pbp=&g_pb[(size_t)((nb*4+h)*32)*128];
    #pragma unroll 4
    for (int qq=0;qq<32;qq++)
        sc[qq*129+tid]=acc[qq]*scale + pbp[(size_t)qq*128+tid];
    __syncthreads();

    {
        int qq2=tid>>2, sub=tid&3;
        float mx=-1e30f;
        #pragma unroll 4
        for (int i=0;i<32;i++) mx=fmaxf(mx, sc[qq2*129+sub+4*i]);
        mx=fmaxf(mx,__shfl_xor_sync(0xffffffffu,mx,1));
        mx=fmaxf(mx,__shfl_xor_sync(0xffffffffu,mx,2));
        float s=0;
        #pragma unroll 4
        for (int i=0;i<32;i++){
            int id=qq2*129+sub+4*i;
            float e=__expf(sc[id]-mx); sc[id]=e; s+=e;
        }
        s+=__shfl_xor_sync(0xffffffffu,s,1);
        s+=__shfl_xor_sync(0xffffffffu,s,2);
        float inv=1.0f/s;
        #pragma unroll 4
        for (int i=0;i<32;i++) sc[qq2*129+sub+4*i]*=inv;
    }
    __syncthreads();

    for (int idx=tid; idx<4096; idx+=128){
        int qq=idx&31, kk=idx>>5;
        scT[kk*36+qq]=sc[qq*129+kk];
    }
    __syncthreads();

    #pragma unroll
    for (int i=0;i<32;i++) acc[i]=0.f;
    int d=tid&31, kg=tid>>5;
    #pragma unroll 4
    for (int ki=0;ki<32;ki++){
        int k=kg*32+ki;
        float v=vb[k*33+d];
        const float4* sp=(const float4*)&scT[k*36];
        #pragma unroll
        for (int r=0;r<8;r++){
            float4 s4=sp[r];
            acc[r*4]  +=s4.x*v;
            acc[r*4+1]+=s4.y*v;
            acc[r*4+2]+=s4.z*v;
            acc[r*4+3]+=s4.w*v;
        }
    }
    float* red = sc;
    #pragma unroll
    for (int qq=0;qq<32;qq++) red[kg*1056+qq*33+d]=acc[qq];
    __syncthreads();
    for (int idx=tid; idx<1024; idx+=128){
        int qq=idx>>5, dd=idx&31;
        float s=red[qq*33+dd]+red[1056+qq*33+dd]+red[2112+qq*33+dd]+red[3168+qq*33+dd];
        g_o[(size_t)(nb*32+qq)*128 + h*32 + dd]=s;
    }
}

// K7: per-layer stage C
__global__ void __launch_bounds__(128) k_stageC(const float* __restrict__ outb,
                                                const float* __restrict__ gateb, int l)
{
    __shared__ __align__(16) float sA[128*SMS];
    __shared__ __align__(16) float sB[128*SMS];
    __shared__ __align__(16) float sC[256*SMS];
    int j=threadIdx.x; int a0=blockIdx.x*MB;
    for (int idx=j; idx<128*MB; idx+=128){
        int m=idx>>7,k=idx&127;
        sA[k*SMS+m]=g_o  [(size_t)(a0+m)*128+k];
        sB[k*SMS+m]=g_sln[(size_t)(a0+m)*128+k];
    }
    float av[16];
    #pragma unroll
    for (int m=0;m<16;m++) av[m]=g_a[(size_t)(a0+m)*128+j];
    __syncthreads();

    float o1[1][16]; ZERON(o1,1);
    gemvN<32,1>(gP_out + (size_t)l*32*128 + j, 128, sA, o1);
    float gg[1][16]; ZERON(gg,1);
    gemvN<32,1>(gP_gate + (size_t)l*32*128 + j, 128, sB, gg);

    float ob=outb[l*128+j];
    float anew[16];
    #pragma unroll
    for (int m=0;m<16;m++) anew[m]=av[m]+o1[0][m]+ob;

    float mu[16],rs[16];
    rowstats128(anew, sC, mu, rs);

    float ad[2][16]; ZERON(ad,2);
    gemvN<32,2>(gP_ada + (size_t)l*32*256 + j, 256, sB, ad);
    #pragma unroll
    for (int m=0;m<16;m++)
        sA[j*SMS+m]=sigf(ad[0][m])*((anew[m]-mu[m])*rs[m])+ad[1][m];
    __syncthreads();

    #pragma unroll 1
    for (int s=0;s<2;s++){
        float tp[2][16]; ZERON(tp,2);
        gemvN<32,2,256>(gP_ta + (size_t)l*32*512 + s*128 + j, 512, sA, tp);
        #pragma unroll
        for (int m=0;m<16;m++){
            float a_=tp[0][m];
            sC[(s*128+j)*SMS+m]=a_*sigf(a_)*tp[1][m];
        }
    }
    __syncthreads();

    float hv[1][16]; ZERON(hv,1);
    gemvN<64,1>(gP_tb + (size_t)l*64*128 + j, 128, sC, hv);

    float gb_=gateb[l*128+j];
    #pragma unroll
    for (int m=0;m<16;m++)
        g_a[(size_t)(a0+m)*128+j]=anew[m]+sigf(gg[0][m]+gb_)*hv[0][m];
}

// K8: atom_out = relu(a @ W_tok^T) -> g_qkv (reuse)
__global__ void __launch_bounds__(128) k_tokproj()
{
    __shared__ __align__(16) float sA[128*SMS];
    int j=threadIdx.x; int a0=blockIdx.x*MB;
    for (int idx=j; idx<128*MB; idx+=128){
        int m=idx>>7,k=idx&127;
        sA[k*SMS+m]=g_a[(size_t)(a0+m)*128+k];
    }
    __syncthreads();
    float q3[3][16]; ZERON(q3,3);
    gemvN<32,3>(gP_tok + j, 384, sA, q3);
    #pragma unroll
    for (int m=0;m<16;m++){
        size_t b=(size_t)(a0+m)*384;
        g_qkv[b+j]    =fmaxf(q3[0][m],0.f);
        g_qkv[b+128+j]=fmaxf(q3[1][m],0.f);
        g_qkv[b+256+j]=fmaxf(q3[2][m],0.f);
    }
}

// K9: deterministic segment mean
__global__ void __launch_bounds__(128) k_tokmean(const int* __restrict__ a2t)
{
    __shared__ int slo,shi;
    int t=blockIdx.x;
    if (threadIdx.x==0){
        int lo=0,hi=NATOMS;
        while(lo<hi){int mid=(lo+hi)>>1; if(a2t[mid]<t) lo=mid+1; else hi=mid;}
        slo=lo; int lo2=lo; hi=NATOMS;
        while(lo2<hi){int mid=(lo2+hi)>>1; if(a2t[mid]<t+1) lo2=mid+1; else hi=mid;}
        shi=lo2;
    }
    __syncthreads();
    int lo=slo,hi=shi;
    float inv=1.0f/fmaxf((float)(hi-lo),1.0f);
    #pragma unroll
    for (int s=0;s<3;s++){
        int d=s*128+threadIdx.x;
        float sum=0;
        for (int a=lo;a<hi;a++) sum+=g_qkv[(size_t)a*384+d];
        g_tok[(size_t)t*384+d]=sum*inv;
    }
}

// K10: s_trunk, s_struct -> d_out ; u -> g_u
__global__ void __launch_bounds__(128) k_trunkstruct(float* __restrict__ out)
{
    __shared__ __align__(16) float sT[384*SMS];
    int j=threadIdx.x; int t0=blockIdx.x*MB;
    for (int idx=j; idx<384*MB; idx+=128){
        int m=idx/384, k=idx%384;
        sT[k*SMS+m]=g_tok[(size_t)(t0+m)*384+k];
    }
    __syncthreads();
    {
        float c3[3][16]; ZERON(c3,3);
        gemvN<96,3>(gP_trunk + j, 384, sT, c3);
        #pragma unroll
        for (int m=0;m<16;m++){
            size_t b=(size_t)(t0+m)*384;
            out[b+j]=c3[0][m]; out[b+128+j]=c3[1][m]; out[b+256+j]=c3[2][m];
        }
    }
    {
        float* o2 = out + (size_t)NTOK*384;
        float c3[3][16]; ZERON(c3,3);
        gemvN<96,3>(gP_struc + j, 384, sT, c3);
        #pragma unroll
        for (int m=0;m<16;m++){
            size_t b=(size_t)(t0+m)*384;
            o2[b+j]=c3[0][m]; o2[b+128+j]=c3[1][m]; o2[b+256+j]=c3[2][m];
        }
    }
    {
        float c2[2][16]; ZERON(c2,2);
        gemvN<96,2>(gP_outer + j, 256, sT, c2);
        #pragma unroll
        for (int m=0;m<16;m++){
            size_t b=(size_t)(t0+m)*256;
            g_u[b+j]=c2[0][m]; g_u[b+128+j]=c2[1][m];
        }
    }
}

// K11: pair = tpf@W_pairin^T + u_lo[i] + u_hi[j] — weights in registers
__global__ void __launch_bounds__(128) k_pair(const float* __restrict__ tpf,
                                              float* __restrict__ outp)
{
    __shared__ __align__(16) float tj[8*32];
    int i=blockIdx.x, c=threadIdx.x;
    float4 w[8];
    #pragma unroll
    for (int k4=0;k4<8;k4++) w[k4]=gP_pairin[k4*128+c];
    float uiv=g_u[(size_t)i*256+c];
    for (int j0=0;j0<NTOK;j0+=8){
        __syncthreads();
        for (int idx=c; idx<256; idx+=128)
            tj[idx]=tpf[((size_t)i*NTOK+j0)*32 + idx];
        __syncthreads();
        #pragma unroll
        for (int jj=0;jj<8;jj++){
            int j=j0+jj;
            float a=uiv+g_u[(size_t)j*256+128+c];
            const float4* tp=(const float4*)&tj[jj*32];
            #pragma unroll
            for (int k4=0;k4<8;k4++){
                float4 t4=tp[k4];
                a += w[k4].x*t4.x + w[k4].y*t4.y + w[k4].z*t4.z + w[k4].w*t4.w;
            }
            outp[((size_t)i*NTOK+j)*128+c]=a;
        }
    }
}

extern "C" void kernel_launch(void* const* d_in, const int* in_sizes, int n_in,
                              void* d_out, int out_size)
{
    const float* af      = (const float*)d_in[0];
    const float* tpf     = (const float*)d_in[1];
    const float* W_cond  = (const float*)d_in[2];
    const float* W_ph    = (const float*)d_in[3];
    const float* W_pw    = (const float*)d_in[4];
    const float* W_mlp1  = (const float*)d_in[5];
    const float* W_mlp2  = (const float*)d_in[6];
    const float* pb_ln_w = (const float*)d_in[7];
    const float* pb_ln_b = (const float*)d_in[8];
    const float* pb_w    = (const float*)d_in[9];
    const float* sln_w   = (const float*)d_in[10];
    const float* qkv_w   = (const float*)d_in[11];
    const float* q_bias  = (const float*)d_in[12];
    const float* out_w   = (const float*)d_in[13];
    const float* out_b   = (const float*)d_in[14];
    const float* ada_w   = (const float*)d_in[15];
    const float* ta_w    = (const float*)d_in[16];
    const float* tb_w    = (const float*)d_in[17];
    const float* gate_w  = (const float*)d_in[18];
    const float* gate_b  = (const float*)d_in[19];
    const float* W_tok   = (const float*)d_in[20];
    const float* W_trunk = (const float*)d_in[21];
    const float* W_struct= (const float*)d_in[22];
    const float* W_pairin= (const float*)d_in[23];
    const float* W_outer = (const float*)d_in[24];
    const int*   a2t     = (const int*)d_in[28];
    float* out = (float*)d_out;

    PackArgs pa;
    void* p;
    #define SETP(i,sym,srcp,OUTv,Kv,Lv) \
        cudaGetSymbolAddress(&p, sym); \
        pa.d[i] = PackDesc{ srcp, (float*)p, OUTv, Kv, Lv };
    SETP(0,  gP_cond,   W_cond,   128,128,1);
    SETP(1,  gP_ph,     W_ph,      16,128,1);
    SETP(2,  gP_pw,     W_pw,      16,128,1);
    SETP(3,  gP_sln,    sln_w,    256,128,3);
    SETP(4,  gP_qkv,    qkv_w,    384,128,3);
    SETP(5,  gP_out,    out_w,    128,128,3);
    SETP(6,  gP_ada,    ada_w,    256,128,3);
    SETP(7,  gP_ta,     ta_w,     512,128,3);
    SETP(8,  gP_tb,     tb_w,     128,256,3);
    SETP(9,  gP_gate,   gate_w,   128,128,3);
    SETP(10, gP_tok,    W_tok,    384,128,1);
    SETP(11, gP_trunk,  W_trunk,  384,384,1);
    SETP(12, gP_struc,  W_struct, 384,384,1);
    SETP(13, gP_pairin, W_pairin, 128, 32,1);
    SETP(14, gP_outer,  W_outer,  256,384,1);
    #undef SETP

    const int NBLK = NATOMS/MB;              // 736
    const int ATTN_SMEM = (4224+1152+4224+4608)*4;  // 56832 B
    cudaFuncSetAttribute(k_attn, cudaFuncAttributeMaxDynamicSharedMemorySize, ATTN_SMEM);

    // Launch order: stageA(l=0) is the 4th launch (profiler samples launch #4).
    // phpw/pb only depend on k_cond; attn (first consumer of pb) comes after pb.
    k_pack<<<dim3(96,15),256>>>(pa);                 // 1
    k_cond<<<NBLK,128>>>(af);                        // 2
    k_phpw<<<NATOMS/16 + NB*128/16,256>>>();         // 3
    k_stageA<<<NBLK,128>>>(q_bias,0);                // 4  <-- profiled
    k_pb  <<<NB*32,128>>>(W_mlp1,W_mlp2,pb_ln_w,pb_ln_b,pb_w);  // 5

    for (int l=0;l<NL;l++){
        if (l>0) k_stageA<<<NBLK,128>>>(q_bias,l);
        k_attn  <<<NB*4,128,ATTN_SMEM>>>();
        k_stageC<<<NBLK,128>>>(out_b,gate_b,l);
    }

    k_tokproj<<<NBLK,128>>>();
    k_tokmean<<<NTOK,128>>>(a2t);
    k_trunkstruct<<<NTOK/MB,128>>>(out);
    k_pair<<<NTOK,128>>>(tpf, out + (size_t)2*NTOK*384);
}

// round 9
// speedup vs baseline: 1.2000x; 1.0836x over previous
#include <cuda_runtime.h>

#define NATOMS 11776
#define NB     368
#define NTOK   512
#define NL     3
#define MB     16
#define SMS    20

// ---- scratch ----
__device__ float g_sln[NATOMS*128];
__device__ float g_a  [NATOMS*128];
__device__ float g_qkv[NATOMS*384];   // later reused for atom_out
__device__ float g_o  [NATOMS*128];
__device__ float g_ph [NATOMS*16];
__device__ float g_pw [NB*128*16];
__device__ float g_pb [NB*4*32*128];
__device__ float g_tok[NTOK*384];
__device__ float g_u  [NTOK*256];

// ---- packed weights: P[(k/4)*OUT + j] = float4{ W[j][k..k+3] } ----
__device__ float4 gP_cond [32*128];
__device__ float4 gP_ph   [32*16];
__device__ float4 gP_pw   [32*16];
__device__ float4 gP_sln  [NL*32*256];
__device__ float4 gP_qkv  [NL*32*384];
__device__ float4 gP_out  [NL*32*128];
__device__ float4 gP_ada  [NL*32*256];
__device__ float4 gP_ta   [NL*32*512];
__device__ float4 gP_tb   [NL*64*128];
__device__ float4 gP_gate [NL*32*128];
__device__ float4 gP_tok  [32*384];
__device__ float4 gP_trunk[96*384];
__device__ float4 gP_struc[96*384];
__device__ float4 gP_pairin[8*128];
__device__ float4 gP_outer[96*256];

__device__ __forceinline__ float sigf(float x){ return 1.0f/(1.0f+__expf(-x)); }

#define ZERO8(a) { _Pragma("unroll") for(int _m=0;_m<8;_m++) a[_m]=0.f; }
#define ZERON8(a,N) { _Pragma("unroll") for(int _n=0;_n<(N);_n++) ZERO8(a[_n]); }

// Register-blocked GEMV, 256-thread m-split: thread = (j = tid&127, half = tid>>7),
// computes 8 atoms (moff = half*8). sXm = smem x-tile base + moff.
// NC output chunks of 128 (chunk offset COFF float4), packed weights at Wb (+j baked in).
template<int K4, int NC, int COFF=128>
__device__ __forceinline__ void gemv8(const float4* __restrict__ Wb, int out4,
                                      const float* __restrict__ sXm, float (*acc)[8])
{
    #pragma unroll 2
    for (int k4=0;k4<K4;k4++){
        float4 w[NC];
        #pragma unroll
        for (int n=0;n<NC;n++) w[n]=Wb[k4*out4 + n*COFF];
        const float* xb = sXm + (k4<<2)*SMS;
        #pragma unroll
        for (int c=0;c<4;c++){
            const float4* _p=(const float4*)(xb + c*SMS);
            float4 x0=_p[0], x1=_p[1];
            #pragma unroll
            for (int n=0;n<NC;n++){
                float wc=(c==0)?w[n].x:(c==1)?w[n].y:(c==2)?w[n].z:w[n].w;
                acc[n][0]+=x0.x*wc; acc[n][1]+=x0.y*wc; acc[n][2]+=x0.z*wc; acc[n][3]+=x0.w*wc;
                acc[n][4]+=x1.x*wc; acc[n][5]+=x1.y*wc; acc[n][6]+=x1.z*wc; acc[n][7]+=x1.w*wc;
            }
        }
    }
}

// per-atom mean/rstd over 128 dims, 16 atoms, 256 threads.
// thread (j, half) holds v[mi] = value of dim j for atom moff+mi.
// stage needs >= 2384 floats. Two-pass (same math as validated version).
__device__ __forceinline__ void rowstats256(const float v[8], int moff, float* stage,
                                            float mu[8], float rs[8])
{
    const int tid=threadIdx.x, j=tid&127;
    for (int pass=0; pass<2; pass++){
        __syncthreads();
        #pragma unroll
        for (int mi=0;mi<8;mi++){
            float x=(pass==0)? v[mi] : (v[mi]-mu[mi]);
            stage[(moff+mi)*132 + j] = (pass==0)? x : x*x;
        }
        __syncthreads();
        { int row=tid>>4, seg=tid&15;
          float s=0;
          #pragma unroll
          for (int u=0;u<8;u++) s+=stage[row*132 + seg*8 + u];
          stage[2112+tid]=s; }
        __syncthreads();
        if (tid<16){ float t2=0;
          #pragma unroll
          for (int u=0;u<16;u++) t2+=stage[2112+tid*16+u];
          stage[2368+tid]=t2*(1.0f/128.0f); }
        __syncthreads();
        if (pass==0){
            #pragma unroll
            for (int mi=0;mi<8;mi++) mu[mi]=stage[2368+moff+mi];
        } else {
            #pragma unroll
            for (int mi=0;mi<8;mi++) rs[mi]=rsqrtf(stage[2368+moff+mi]+1e-5f);
        }
    }
    __syncthreads();
}

// ---- one-shot weight packer ----
struct PackDesc { const float* src; float* dst; int OUT; int K; int L; };
struct PackArgs { PackDesc d[15]; };
__global__ void k_pack(PackArgs pa)
{
    PackDesc pd = pa.d[blockIdx.y];
    int total = pd.L*pd.OUT*pd.K;
    int K4 = pd.K>>2;
    for (int idx = blockIdx.x*256 + threadIdx.x; idx < total; idx += gridDim.x*256){
        int c = idx&3; int t = idx>>2;
        int j = t % pd.OUT; int q = t / pd.OUT;
        int k4 = q % K4;    int l = q / K4;
        pd.dst[idx] = pd.src[((size_t)l*pd.OUT + j)*pd.K + k4*4 + c];
    }
}

// K1: c = af@Wcond^T ; a=c ; s_ln=LN(c)
__global__ void __launch_bounds__(256) k_cond(const float* __restrict__ af)
{
    __shared__ __align__(16) float sA[128*SMS];
    int tid=threadIdx.x, j=tid&127, moff=(tid>>7)*8;
    int a0 = blockIdx.x*MB;
    for (int idx=tid; idx<128*MB; idx+=256){
        int m=idx>>7, k=idx&127;
        sA[k*SMS+m] = af[(size_t)(a0+m)*128 + k];
    }
    __syncthreads();
    float acc[1][8]; ZERON8(acc,1);
    gemv8<32,1>(gP_cond + j, 128, sA+moff, acc);
    #pragma unroll
    for (int mi=0;mi<8;mi++) g_a[(size_t)(a0+moff+mi)*128+j]=acc[0][mi];
    float mu[8], rs[8];
    rowstats256(acc[0], moff, sA, mu, rs);
    #pragma unroll
    for (int mi=0;mi<8;mi++) g_sln[(size_t)(a0+moff+mi)*128+j]=(acc[0][mi]-mu[mi])*rs[mi];
}

// K2: fused ph (blocks < NATOMS/16) and pw (rest)
__global__ void __launch_bounds__(256) k_phpw()
{
    __shared__ float xs[16*132];
    int tid=threadIdx.x;
    bool isph = blockIdx.x < (NATOMS/16);
    int r0 = isph ? blockIdx.x*16 : (blockIdx.x-(NATOMS/16))*16;
    for (int idx=tid; idx<16*128; idx+=256){
        int r=idx>>7,k=idx&127;
        int row=r0+r;
        int atom;
        if (isph) atom=row;
        else { int nb=row>>7, kk=row&127; atom=nb*32+kk-48; atom=max(0,min(atom,NATOMS-1)); }
        xs[r*132+k]=fmaxf(g_sln[(size_t)atom*128+k],0.f);
    }
    __syncthreads();
    int o=tid&15, r=tid>>4;
    const float4* W = isph ? gP_ph : gP_pw;
    float acc=0;
    #pragma unroll 4
    for (int k4=0;k4<32;k4++){
        float4 w = W[k4*16+o];
        const float* xb=&xs[r*132+k4*4];
        acc += xb[0]*w.x+xb[1]*w.y+xb[2]*w.z+xb[3]*w.w;
    }
    if (isph) g_ph[(size_t)(r0+r)*16+o]=acc;
    else      g_pw[(size_t)(r0+r)*16+o]=acc;
}

// K3: pair bias (p + MLP + LN + head proj + mask fold)
__global__ void __launch_bounds__(128) k_pb(const float* __restrict__ W1g,
                                            const float* __restrict__ W2g,
                                            const float* __restrict__ lnw,
                                            const float* __restrict__ lnb,
                                            const float* __restrict__ pbw)
{
    __shared__ float W1[256], W2[256], PBW[64], LW[16], LB[16], PH[16];
    int tid=threadIdx.x;
    int blk=blockIdx.x; int nb=blk>>5, q=blk&31;
    for (int idx=tid; idx<256; idx+=128){ W1[idx]=W1g[idx]; W2[idx]=W2g[idx]; }
    if (tid<64) PBW[tid]=pbw[tid];
    if (tid<16){ LW[tid]=lnw[tid]; LB[tid]=lnb[tid];
                 PH[tid]=g_ph[(size_t)(nb*32+q)*16+tid]; }
    __syncthreads();

    float p[16];
    { const float4* pwp=(const float4*)&g_pw[(size_t)(nb*128+tid)*16];
      float4 a=pwp[0],b=pwp[1],c=pwp[2],d=pwp[3];
      p[0]=a.x;p[1]=a.y;p[2]=a.z;p[3]=a.w; p[4]=b.x;p[5]=b.y;p[6]=b.z;p[7]=b.w;
      p[8]=c.x;p[9]=c.y;p[10]=c.z;p[11]=c.w; p[12]=d.x;p[13]=d.y;p[14]=d.z;p[15]=d.w; }
    #pragma unroll
    for (int i=0;i<16;i++) p[i]+=PH[i];

    float t[16], u[16];
    #pragma unroll
    for (int i=0;i<16;i++) t[i]=fmaxf(p[i],0.f);
    #pragma unroll
    for (int o=0;o<16;o++){
        float s=0;
        #pragma unroll
        for (int i=0;i<16;i++) s+=t[i]*W1[o*16+i];
        u[o]=fmaxf(s,0.f);
    }
    #pragma unroll
    for (int o=0;o<16;o++){
        float s=0;
        #pragma unroll
        for (int i=0;i<16;i++) s+=u[i]*W2[o*16+i];
        p[o]+=s;
    }
    float mu=0;
    #pragma unroll
    for (int i=0;i<16;i++) mu+=p[i];
    mu*=(1.0f/16.0f);
    float var=0;
    #pragma unroll
    for (int i=0;i<16;i++){ float d=p[i]-mu; var+=d*d; }
    float rsd=rsqrtf(var*(1.0f/16.0f)+1e-5f);
    float y[16];
    #pragma unroll
    for (int i=0;i<16;i++) y[i]=(p[i]-mu)*rsd*LW[i]+LB[i];

    int win = nb*32 + tid - 48;
    float neg = (win>=0 && win<NATOMS) ? 0.f : -1.0e9f;
    #pragma unroll
    for (int h=0;h<4;h++){
        float s=0;
        #pragma unroll
        for (int i=0;i<16;i++) s+=y[i]*PBW[h*16+i];
        g_pb[(size_t)((nb*4+h)*32+q)*128+tid]=s+neg;
    }
}

// K4: per-layer stage A (256 threads, m-split)
__global__ void __launch_bounds__(256) k_stageA(const float* __restrict__ qbias, int l)
{
    __shared__ __align__(16) float sB[128*SMS];
    __shared__ __align__(16) float sX[128*SMS];
    int tid=threadIdx.x, j=tid&127, moff=(tid>>7)*8;
    int a0=blockIdx.x*MB;
    for (int idx=tid; idx<128*MB; idx+=256){
        int m=idx>>7,k=idx&127;
        sB[k*SMS+m]=g_sln[(size_t)(a0+m)*128+k];
    }
    float av[8];
    #pragma unroll
    for (int mi=0;mi<8;mi++) av[mi]=g_a[(size_t)(a0+moff+mi)*128+j];

    float mu[8],rs[8];
    rowstats256(av, moff, sX, mu, rs);

    float acc[2][8]; ZERON8(acc,2);
    gemv8<32,2>(gP_sln + (size_t)l*32*256 + j, 256, sB+moff, acc);
    #pragma unroll
    for (int mi=0;mi<8;mi++)
        sX[j*SMS+moff+mi]=sigf(acc[0][mi])*((av[mi]-mu[mi])*rs[mi])+acc[1][mi];
    __syncthreads();

    float q3[3][8]; ZERON8(q3,3);
    gemv8<32,3>(gP_qkv + (size_t)l*32*384 + j, 384, sX+moff, q3);
    float qb = qbias[l*128+j];
    #pragma unroll
    for (int mi=0;mi<8;mi++){
        size_t b=(size_t)(a0+moff+mi)*384;
        g_qkv[b+j]      =q3[0][mi]+qb;
        g_qkv[b+128+j]  =q3[1][mi];
        g_qkv[b+256+j]  =q3[2][mi];
    }
}

// K5: windowed attention per (nb, head) — outer-product register-blocked
__global__ void __launch_bounds__(128) k_attn()
{
    extern __shared__ float sm[];
    float* vb  = sm;           // 128*33 = 4224
    float* qT  = vb + 4224;    // 32*36  = 1152
    float* sc  = qT + 1152;    // 4224 (32*129 used; aliased as red in AV epilogue)
    float* scT = sc + 4224;    // 128*36 = 4608
    int blk=blockIdx.x; int nb=blk>>2, h=blk&3;
    int tid=threadIdx.x;

    for (int idx=tid; idx<128*32; idx+=128){
        int kk=idx>>5, d=idx&31;
        int atom=nb*32+kk-48; atom=max(0,min(atom,NATOMS-1));
        vb[kk*33+d]=g_qkv[(size_t)atom*384+256+h*32+d];
    }
    for (int idx=tid; idx<1024; idx+=128){
        int d=idx>>5, qq=idx&31;
        qT[d*36+qq]=g_qkv[(size_t)(nb*32+qq)*384 + h*32 + d];
    }
    float kreg[32];
    {
        int atom=nb*32+tid-48; atom=max(0,min(atom,NATOMS-1));
        const float4* kr=(const float4*)&g_qkv[(size_t)atom*384+128+h*32];
        #pragma unroll
        for (int i=0;i<8;i++){
            float4 v=kr[i];
            kreg[i*4]=v.x; kreg[i*4+1]=v.y; kreg[i*4+2]=v.z; kreg[i*4+3]=v.w;
        }
    }
    __syncthreads();

    float acc[32];
    #pragma unroll
    for (int i=0;i<32;i++) acc[i]=0.f;
    #pragma unroll 4
    for (int d=0;d<32;d++){
        float kd=kreg[d];
        const float4* qp=(const float4*)&qT[d*36];
        #pragma unroll
        for (int r=0;r<8;r++){
            float4 q4=qp[r];
            acc[r*4]  +=q4.x*kd;
            acc[r*4+1]+=q4.y*kd;
            acc[r*4+2]+=q4.z*kd;
            acc[r*4+3]+=q4.w*kd;
        }
    }
    const float scale=0.1767766952966369f;
    const float* pbp=&g_pb[(size_t)((nb*4+h)*32)*128];
    #pragma unroll 4
    for (int qq=0;qq<32;qq++)
        sc[qq*129+tid]=acc[qq]*scale + pbp[(size_t)qq*128+tid];
    __syncthreads();

    {
        int qq2=tid>>2, sub=tid&3;
        float mx=-1e30f;
        #pragma unroll 4
        for (int i=0;i<32;i++) mx=fmaxf(mx, sc[qq2*129+sub+4*i]);
        mx=fmaxf(mx,__shfl_xor_sync(0xffffffffu,mx,1));
        mx=fmaxf(mx,__shfl_xor_sync(0xffffffffu,mx,2));
        float s=0;
        #pragma unroll 4
        for (int i=0;i<32;i++){
            int id=qq2*129+sub+4*i;
            float e=__expf(sc[id]-mx); sc[id]=e; s+=e;
        }
        s+=__shfl_xor_sync(0xffffffffu,s,1);
        s+=__shfl_xor_sync(0xffffffffu,s,2);
        float inv=1.0f/s;
        #pragma unroll 4
        for (int i=0;i<32;i++) sc[qq2*129+sub+4*i]*=inv;
    }
    __syncthreads();

    for (int idx=tid; idx<4096; idx+=128){
        int qq=idx&31, kk=idx>>5;
        scT[kk*36+qq]=sc[qq*129+kk];
    }
    __syncthreads();

    #pragma unroll
    for (int i=0;i<32;i++) acc[i]=0.f;
    int d=tid&31, kg=tid>>5;
    #pragma unroll 4
    for (int ki=0;ki<32;ki++){
        int k=kg*32+ki;
        float v=vb[k*33+d];
        const float4* sp=(const float4*)&scT[k*36];
        #pragma unroll
        for (int r=0;r<8;r++){
            float4 s4=sp[r];
            acc[r*4]  +=s4.x*v;
            acc[r*4+1]+=s4.y*v;
            acc[r*4+2]+=s4.z*v;
            acc[r*4+3]+=s4.w*v;
        }
    }
    float* red = sc;
    #pragma unroll
    for (int qq=0;qq<32;qq++) red[kg*1056+qq*33+d]=acc[qq];
    __syncthreads();
    for (int idx=tid; idx<1024; idx+=128){
        int qq=idx>>5, dd=idx&31;
        float s=red[qq*33+dd]+red[1056+qq*33+dd]+red[2112+qq*33+dd]+red[3168+qq*33+dd];
        g_o[(size_t)(nb*32+qq)*128 + h*32 + dd]=s;
    }
}

// K7: per-layer stage C (256 threads, m-split)
__global__ void __launch_bounds__(256) k_stageC(const float* __restrict__ outb,
                                                const float* __restrict__ gateb, int l)
{
    __shared__ __align__(16) float sA[128*SMS];
    __shared__ __align__(16) float sB[128*SMS];
    __shared__ __align__(16) float sC[256*SMS];
    int tid=threadIdx.x, j=tid&127, moff=(tid>>7)*8;
    int a0=blockIdx.x*MB;
    for (int idx=tid; idx<128*MB; idx+=256){
        int m=idx>>7,k=idx&127;
        sA[k*SMS+m]=g_o  [(size_t)(a0+m)*128+k];
        sB[k*SMS+m]=g_sln[(size_t)(a0+m)*128+k];
    }
    float av[8];
    #pragma unroll
    for (int mi=0;mi<8;mi++) av[mi]=g_a[(size_t)(a0+moff+mi)*128+j];
    __syncthreads();

    float o1[1][8]; ZERON8(o1,1);
    gemv8<32,1>(gP_out + (size_t)l*32*128 + j, 128, sA+moff, o1);
    float gg[1][8]; ZERON8(gg,1);
    gemv8<32,1>(gP_gate + (size_t)l*32*128 + j, 128, sB+moff, gg);

    float ob=outb[l*128+j];
    float anew[8];
    #pragma unroll
    for (int mi=0;mi<8;mi++) anew[mi]=av[mi]+o1[0][mi]+ob;

    float mu[8],rs[8];
    rowstats256(anew, moff, sC, mu, rs);

    float ad[2][8]; ZERON8(ad,2);
    gemv8<32,2>(gP_ada + (size_t)l*32*256 + j, 256, sB+moff, ad);
    #pragma unroll
    for (int mi=0;mi<8;mi++)
        sA[j*SMS+moff+mi]=sigf(ad[0][mi])*((anew[mi]-mu[mi])*rs[mi])+ad[1][mi];
    __syncthreads();

    #pragma unroll 1
    for (int s=0;s<2;s++){
        float tp[2][8]; ZERON8(tp,2);
        gemv8<32,2,256>(gP_ta + (size_t)l*32*512 + s*128 + j, 512, sA+moff, tp);
        #pragma unroll
        for (int mi=0;mi<8;mi++){
            float a_=tp[0][mi];
            sC[(s*128+j)*SMS+moff+mi]=a_*sigf(a_)*tp[1][mi];
        }
    }
    __syncthreads();

    float hv[1][8]; ZERON8(hv,1);
    gemv8<64,1>(gP_tb + (size_t)l*64*128 + j, 128, sC+moff, hv);

    float gb_=gateb[l*128+j];
    #pragma unroll
    for (int mi=0;mi<8;mi++)
        g_a[(size_t)(a0+moff+mi)*128+j]=anew[mi]+sigf(gg[0][mi]+gb_)*hv[0][mi];
}

// K8: atom_out = relu(a @ W_tok^T) -> g_qkv (reuse)
__global__ void __launch_bounds__(256) k_tokproj()
{
    __shared__ __align__(16) float sA[128*SMS];
    int tid=threadIdx.x, j=tid&127, moff=(tid>>7)*8;
    int a0=blockIdx.x*MB;
    for (int idx=tid; idx<128*MB; idx+=256){
        int m=idx>>7,k=idx&127;
        sA[k*SMS+m]=g_a[(size_t)(a0+m)*128+k];
    }
    __syncthreads();
    float q3[3][8]; ZERON8(q3,3);
    gemv8<32,3>(gP_tok + j, 384, sA+moff, q3);
    #pragma unroll
    for (int mi=0;mi<8;mi++){
        size_t b=(size_t)(a0+moff+mi)*384;
        g_qkv[b+j]    =fmaxf(q3[0][mi],0.f);
        g_qkv[b+128+j]=fmaxf(q3[1][mi],0.f);
        g_qkv[b+256+j]=fmaxf(q3[2][mi],0.f);
    }
}

// K9: deterministic segment mean
__global__ void __launch_bounds__(128) k_tokmean(const int* __restrict__ a2t)
{
    __shared__ int slo,shi;
    int t=blockIdx.x;
    if (threadIdx.x==0){
        int lo=0,hi=NATOMS;
        while(lo<hi){int mid=(lo+hi)>>1; if(a2t[mid]<t) lo=mid+1; else hi=mid;}
        slo=lo; int lo2=lo; hi=NATOMS;
        while(lo2<hi){int mid=(lo2+hi)>>1; if(a2t[mid]<t+1) lo2=mid+1; else hi=mid;}
        shi=lo2;
    }
    __syncthreads();
    int lo=slo,hi=shi;
    float inv=1.0f/fmaxf((float)(hi-lo),1.0f);
    #pragma unroll
    for (int s=0;s<3;s++){
        int d=s*128+threadIdx.x;
        float sum=0;
        for (int a=lo;a<hi;a++) sum+=g_qkv[(size_t)a*384+d];
        g_tok[(size_t)t*384+d]=sum*inv;
    }
}

// K10: s_trunk, s_struct -> d_out ; u -> g_u (256 threads, m-split)
__global__ void __launch_bounds__(256) k_trunkstruct(float* __restrict__ out)
{
    __shared__ __align__(16) float sT[384*SMS];
    int tid=threadIdx.x, j=tid&127, moff=(tid>>7)*8;
    int t0=blockIdx.x*MB;
    for (int idx=tid; idx<384*MB; idx+=256){
        int m=idx/384, k=idx%384;
        sT[k*SMS+m]=g_tok[(size_t)(t0+m)*384+k];
    }
    __syncthreads();
    {
        float c3[3][8]; ZERON8(c3,3);
        gemv8<96,3>(gP_trunk + j, 384, sT+moff, c3);
        #pragma unroll
        for (int mi=0;mi<8;mi++){
            size_t b=(size_t)(t0+moff+mi)*384;
            out[b+j]=c3[0][mi]; out[b+128+j]=c3[1][mi]; out[b+256+j]=c3[2][mi];
        }
    }
    {
        float* o2 = out + (size_t)NTOK*384;
        float c3[3][8]; ZERON8(c3,3);
        gemv8<96,3>(gP_struc + j, 384, sT+moff, c3);
        #pragma unroll
        for (int mi=0;mi<8;mi++){
            size_t b=(size_t)(t0+moff+mi)*384;
            o2[b+j]=c3[0][mi]; o2[b+128+j]=c3[1][mi]; o2[b+256+j]=c3[2][mi];
        }
    }
    {
        float c2[2][8]; ZERON8(c2,2);
        gemv8<96,2>(gP_outer + j, 256, sT+moff, c2);
        #pragma unroll
        for (int mi=0;mi<8;mi++){
            size_t b=(size_t)(t0+moff+mi)*256;
            g_u[b+j]=c2[0][mi]; g_u[b+128+j]=c2[1][mi];
        }
    }
}

// K11: pair = tpf@W_pairin^T + u_lo[i] + u_hi[j] — weights in registers
__global__ void __launch_bounds__(128) k_pair(const float* __restrict__ tpf,
                                              float* __restrict__ outp)
{
    __shared__ __align__(16) float tj[8*32];
    int i=blockIdx.x, c=threadIdx.x;
    float4 w[8];
    #pragma unroll
    for (int k4=0;k4<8;k4++) w[k4]=gP_pairin[k4*128+c];
    float uiv=g_u[(size_t)i*256+c];
    for (int j0=0;j0<NTOK;j0+=8){
        __syncthreads();
        for (int idx=c; idx<256; idx+=128)
            tj[idx]=tpf[((size_t)i*NTOK+j0)*32 + idx];
        __syncthreads();
        #pragma unroll
        for (int jj=0;jj<8;jj++){
            int j=j0+jj;
            float a=uiv+g_u[(size_t)j*256+128+c];
            const float4* tp=(const float4*)&tj[jj*32];
            #pragma unroll
            for (int k4=0;k4<8;k4++){
                float4 t4=tp[k4];
                a += w[k4].x*t4.x + w[k4].y*t4.y + w[k4].z*t4.z + w[k4].w*t4.w;
            }
            outp[((size_t)i*NTOK+j)*128+c]=a;
        }
    }
}

extern "C" void kernel_launch(void* const* d_in, const int* in_sizes, int n_in,
                              void* d_out, int out_size)
{
    const float* af      = (const float*)d_in[0];
    const float* tpf     = (const float*)d_in[1];
    const float* W_cond  = (const float*)d_in[2];
    const float* W_ph    = (const float*)d_in[3];
    const float* W_pw    = (const float*)d_in[4];
    const float* W_mlp1  = (const float*)d_in[5];
    const float* W_mlp2  = (const float*)d_in[6];
    const float* pb_ln_w = (const float*)d_in[7];
    const float* pb_ln_b = (const float*)d_in[8];
    const float* pb_w    = (const float*)d_in[9];
    const float* sln_w   = (const float*)d_in[10];
    const float* qkv_w   = (const float*)d_in[11];
    const float* q_bias  = (const float*)d_in[12];
    const float* out_w   = (const float*)d_in[13];
    const float* out_b   = (const float*)d_in[14];
    const float* ada_w   = (const float*)d_in[15];
    const float* ta_w    = (const float*)d_in[16];
    const float* tb_w    = (const float*)d_in[17];
    const float* gate_w  = (const float*)d_in[18];
    const float* gate_b  = (const float*)d_in[19];
    const float* W_tok   = (const float*)d_in[20];
    const float* W_trunk = (const float*)d_in[21];
    const float* W_struct= (const float*)d_in[22];
    const float* W_pairin= (const float*)d_in[23];
    const float* W_outer = (const float*)d_in[24];
    const int*   a2t     = (const int*)d_in[28];
    float* out = (float*)d_out;

    PackArgs pa;
    void* p;
    #define SETP(i,sym,srcp,OUTv,Kv,Lv) \
        cudaGetSymbolAddress(&p, sym); \
        pa.d[i] = PackDesc{ srcp, (float*)p, OUTv, Kv, Lv };
    SETP(0,  gP_cond,   W_cond,   128,128,1);
    SETP(1,  gP_ph,     W_ph,      16,128,1);
    SETP(2,  gP_pw,     W_pw,      16,128,1);
    SETP(3,  gP_sln,    sln_w,    256,128,3);
    SETP(4,  gP_qkv,    qkv_w,    384,128,3);
    SETP(5,  gP_out,    out_w,    128,128,3);
    SETP(6,  gP_ada,    ada_w,    256,128,3);
    SETP(7,  gP_ta,     ta_w,     512,128,3);
    SETP(8,  gP_tb,     tb_w,     128,256,3);
    SETP(9,  gP_gate,   gate_w,   128,128,3);
    SETP(10, gP_tok,    W_tok,    384,128,1);
    SETP(11, gP_trunk,  W_trunk,  384,384,1);
    SETP(12, gP_struc,  W_struct, 384,384,1);
    SETP(13, gP_pairin, W_pairin, 128, 32,1);
    SETP(14, gP_outer,  W_outer,  256,384,1);
    #undef SETP

    const int NBLK = NATOMS/MB;              // 736
    const int ATTN_SMEM = (4224+1152+4224+4608)*4;  // 56832 B
    cudaFuncSetAttribute(k_attn, cudaFuncAttributeMaxDynamicSharedMemorySize, ATTN_SMEM);

    // stageA(l=0) stays the 4th launch (profiler samples launch #4).
    k_pack<<<dim3(96,15),256>>>(pa);                 // 1
    k_cond<<<NBLK,256>>>(af);                        // 2
    k_phpw<<<NATOMS/16 + NB*128/16,256>>>();         // 3
    k_stageA<<<NBLK,256>>>(q_bias,0);                // 4  <-- profiled
    k_pb  <<<NB*32,128>>>(W_mlp1,W_mlp2,pb_ln_w,pb_ln_b,pb_w);  // 5

    for (int l=0;l<NL;l++){
        if (l>0) k_stageA<<<NBLK,256>>>(q_bias,l);
        k_attn  <<<NB*4,128,ATTN_SMEM>>>();
        k_stageC<<<NBLK,256>>>(out_b,gate_b,l);
    }

    k_tokproj<<<NBLK,256>>>();
    k_tokmean<<<NTOK,128>>>(a2t);
    k_trunkstruct<<<NTOK/MB,256>>>(out);
    k_pair<<<NTOK,128>>>(tpf, out + (size_t)2*NTOK*384);
}

// round 10
// speedup vs baseline: 1.2081x; 1.0067x over previous
#include <cuda_runtime.h>

#define NATOMS 11776
#define NB     368
#define NTOK   512
#define NL     3
#define MB     16
#define SMS    20

// ---- scratch ----
__device__ float g_sln[NATOMS*128];
__device__ float g_a  [NATOMS*128];
__device__ float g_qkv[NATOMS*384];   // later reused for atom_out
__device__ float g_o  [NATOMS*128];
__device__ float g_ph [NATOMS*16];
__device__ float g_pw [NB*128*16];
__device__ float g_pb [NB*4*32*128];
__device__ float g_tok[NTOK*384];
__device__ float g_u  [NTOK*256];

// ---- packed weights: P[(k/4)*OUT + j] = float4{ W[j][k..k+3] } ----
__device__ float4 gP_cond [32*128];
__device__ float4 gP_ph   [32*16];
__device__ float4 gP_pw   [32*16];
__device__ float4 gP_sln  [NL*32*256];
__device__ float4 gP_qkv  [NL*32*384];
__device__ float4 gP_out  [NL*32*128];
__device__ float4 gP_ga   [NL*32*384];   // gate (cols 0-127) ‖ ada (cols 128-383)
__device__ float4 gP_ta   [NL*32*512];
__device__ float4 gP_tb   [NL*64*128];
__device__ float4 gP_tok  [32*384];
__device__ float4 gP_trunk[96*384];
__device__ float4 gP_struc[96*384];
__device__ float4 gP_pairin[8*128];
__device__ float4 gP_outer[96*256];

__device__ __forceinline__ float sigf(float x){ return 1.0f/(1.0f+__expf(-x)); }

#define ZERO8(a) { _Pragma("unroll") for(int _m=0;_m<8;_m++) a[_m]=0.f; }
#define ZERON8(a,N) { _Pragma("unroll") for(int _n=0;_n<(N);_n++) ZERO8(a[_n]); }

// Register-blocked GEMV, 256-thread m-split: thread = (j = tid&127, half = tid>>7),
// computes 8 atoms (moff = half*8). sXm = smem x-tile base + moff.
// NC output chunks of 128 (chunk offset COFF float4), packed weights at Wb (+j baked in).
template<int K4, int NC, int COFF=128>
__device__ __forceinline__ void gemv8(const float4* __restrict__ Wb, int out4,
                                      const float* __restrict__ sXm, float (*acc)[8])
{
    #pragma unroll 2
    for (int k4=0;k4<K4;k4++){
        float4 w[NC];
        #pragma unroll
        for (int n=0;n<NC;n++) w[n]=Wb[k4*out4 + n*COFF];
        const float* xb = sXm + (k4<<2)*SMS;
        #pragma unroll
        for (int c=0;c<4;c++){
            const float4* _p=(const float4*)(xb + c*SMS);
            float4 x0=_p[0], x1=_p[1];
            #pragma unroll
            for (int n=0;n<NC;n++){
                float wc=(c==0)?w[n].x:(c==1)?w[n].y:(c==2)?w[n].z:w[n].w;
                acc[n][0]+=x0.x*wc; acc[n][1]+=x0.y*wc; acc[n][2]+=x0.z*wc; acc[n][3]+=x0.w*wc;
                acc[n][4]+=x1.x*wc; acc[n][5]+=x1.y*wc; acc[n][6]+=x1.z*wc; acc[n][7]+=x1.w*wc;
            }
        }
    }
}

// per-atom mean/rstd over 128 dims, 16 atoms, 256 threads.
__device__ __forceinline__ void rowstats256(const float v[8], int moff, float* stage,
                                            float mu[8], float rs[8])
{
    const int tid=threadIdx.x, j=tid&127;
    for (int pass=0; pass<2; pass++){
        __syncthreads();
        #pragma unroll
        for (int mi=0;mi<8;mi++){
            float x=(pass==0)? v[mi] : (v[mi]-mu[mi]);
            stage[(moff+mi)*132 + j] = (pass==0)? x : x*x;
        }
        __syncthreads();
        { int row=tid>>4, seg=tid&15;
          float s=0;
          #pragma unroll
          for (int u=0;u<8;u++) s+=stage[row*132 + seg*8 + u];
          stage[2112+tid]=s; }
        __syncthreads();
        if (tid<16){ float t2=0;
          #pragma unroll
          for (int u=0;u<16;u++) t2+=stage[2112+tid*16+u];
          stage[2368+tid]=t2*(1.0f/128.0f); }
        __syncthreads();
        if (pass==0){
            #pragma unroll
            for (int mi=0;mi<8;mi++) mu[mi]=stage[2368+moff+mi];
        } else {
            #pragma unroll
            for (int mi=0;mi<8;mi++) rs[mi]=rsqrtf(stage[2368+moff+mi]+1e-5f);
        }
    }
    __syncthreads();
}

// ---- one-shot weight packer (strided dst: dstOut columns, write at joff+j) ----
struct PackDesc { const float* src; float* dst; int OUT; int K; int L; int dstOut; int joff; };
struct PackArgs { PackDesc d[15]; };
__global__ void k_pack(PackArgs pa)
{
    PackDesc pd = pa.d[blockIdx.y];
    int total = pd.L*pd.OUT*pd.K;
    int K4 = pd.K>>2;
    for (int idx = blockIdx.x*256 + threadIdx.x; idx < total; idx += gridDim.x*256){
        int c = idx&3; int t = idx>>2;
        int j = t % pd.OUT; int q = t / pd.OUT;
        int k4 = q % K4;    int l = q / K4;
        size_t daddr = (((size_t)l*K4 + k4)*pd.dstOut + pd.joff + j)*4 + c;
        pd.dst[daddr] = pd.src[((size_t)l*pd.OUT + j)*pd.K + k4*4 + c];
    }
}

// K1: c = af@Wcond^T ; a=c ; s_ln=LN(c)
__global__ void __launch_bounds__(256) k_cond(const float* __restrict__ af)
{
    __shared__ __align__(16) float sA[128*SMS];
    int tid=threadIdx.x, j=tid&127, moff=(tid>>7)*8;
    int a0 = blockIdx.x*MB;
    for (int idx=tid; idx<128*MB; idx+=256){
        int m=idx>>7, k=idx&127;
        sA[k*SMS+m] = af[(size_t)(a0+m)*128 + k];
    }
    __syncthreads();
    float acc[1][8]; ZERON8(acc,1);
    gemv8<32,1>(gP_cond + j, 128, sA+moff, acc);
    #pragma unroll
    for (int mi=0;mi<8;mi++) g_a[(size_t)(a0+moff+mi)*128+j]=acc[0][mi];
    float mu[8], rs[8];
    rowstats256(acc[0], moff, sA, mu, rs);
    #pragma unroll
    for (int mi=0;mi<8;mi++) g_sln[(size_t)(a0+moff+mi)*128+j]=(acc[0][mi]-mu[mi])*rs[mi];
}

// K2: fused ph (blocks < NATOMS/16) and pw (rest)
__global__ void __launch_bounds__(256) k_phpw()
{
    __shared__ float xs[16*132];
    int tid=threadIdx.x;
    bool isph = blockIdx.x < (NATOMS/16);
    int r0 = isph ? blockIdx.x*16 : (blockIdx.x-(NATOMS/16))*16;
    for (int idx=tid; idx<16*128; idx+=256){
        int r=idx>>7,k=idx&127;
        int row=r0+r;
        int atom;
        if (isph) atom=row;
        else { int nb=row>>7, kk=row&127; atom=nb*32+kk-48; atom=max(0,min(atom,NATOMS-1)); }
        xs[r*132+k]=fmaxf(g_sln[(size_t)atom*128+k],0.f);
    }
    __syncthreads();
    int o=tid&15, r=tid>>4;
    const float4* W = isph ? gP_ph : gP_pw;
    float acc=0;
    #pragma unroll 4
    for (int k4=0;k4<32;k4++){
        float4 w = W[k4*16+o];
        const float* xb=&xs[r*132+k4*4];
        acc += xb[0]*w.x+xb[1]*w.y+xb[2]*w.z+xb[3]*w.w;
    }
    if (isph) g_ph[(size_t)(r0+r)*16+o]=acc;
    else      g_pw[(size_t)(r0+r)*16+o]=acc;
}

// K3: pair bias (p + MLP + LN + head proj + mask fold)
__global__ void __launch_bounds__(128) k_pb(const float* __restrict__ W1g,
                                            const float* __restrict__ W2g,
                                            const float* __restrict__ lnw,
                                            const float* __restrict__ lnb,
                                            const float* __restrict__ pbw)
{
    __shared__ float W1[256], W2[256], PBW[64], LW[16], LB[16], PH[16];
    int tid=threadIdx.x;
    int blk=blockIdx.x; int nb=blk>>5, q=blk&31;
    for (int idx=tid; idx<256; idx+=128){ W1[idx]=W1g[idx]; W2[idx]=W2g[idx]; }
    if (tid<64) PBW[tid]=pbw[tid];
    if (tid<16){ LW[tid]=lnw[tid]; LB[tid]=lnb[tid];
                 PH[tid]=g_ph[(size_t)(nb*32+q)*16+tid]; }
    __syncthreads();

    float p[16];
    { const float4* pwp=(const float4*)&g_pw[(size_t)(nb*128+tid)*16];
      float4 a=pwp[0],b=pwp[1],c=pwp[2],d=pwp[3];
      p[0]=a.x;p[1]=a.y;p[2]=a.z;p[3]=a.w; p[4]=b.x;p[5]=b.y;p[6]=b.z;p[7]=b.w;
      p[8]=c.x;p[9]=c.y;p[10]=c.z;p[11]=c.w; p[12]=d.x;p[13]=d.y;p[14]=d.z;p[15]=d.w; }
    #pragma unroll
    for (int i=0;i<16;i++) p[i]+=PH[i];

    float t[16], u[16];
    #pragma unroll
    for (int i=0;i<16;i++) t[i]=fmaxf(p[i],0.f);
    #pragma unroll
    for (int o=0;o<16;o++){
        float s=0;
        #pragma unroll
        for (int i=0;i<16;i++) s+=t[i]*W1[o*16+i];
        u[o]=fmaxf(s,0.f);
    }
    #pragma unroll
    for (int o=0;o<16;o++){
        float s=0;
        #pragma unroll
        for (int i=0;i<16;i++) s+=u[i]*W2[o*16+i];
        p[o]+=s;
    }
    float mu=0;
    #pragma unroll
    for (int i=0;i<16;i++) mu+=p[i];
    mu*=(1.0f/16.0f);
    float var=0;
    #pragma unroll
    for (int i=0;i<16;i++){ float d=p[i]-mu; var+=d*d; }
    float rsd=rsqrtf(var*(1.0f/16.0f)+1e-5f);
    float y[16];
    #pragma unroll
    for (int i=0;i<16;i++) y[i]=(p[i]-mu)*rsd*LW[i]+LB[i];

    int win = nb*32 + tid - 48;
    float neg = (win>=0 && win<NATOMS) ? 0.f : -1.0e9f;
    #pragma unroll
    for (int h=0;h<4;h++){
        float s=0;
        #pragma unroll
        for (int i=0;i<16;i++) s+=y[i]*PBW[h*16+i];
        g_pb[(size_t)((nb*4+h)*32+q)*128+tid]=s+neg;
    }
}

// K4: per-layer stage A (256 threads, m-split)
__global__ void __launch_bounds__(256) k_stageA(const float* __restrict__ qbias, int l)
{
    __shared__ __align__(16) float sB[128*SMS];
    __shared__ __align__(16) float sX[128*SMS];
    int tid=threadIdx.x, j=tid&127, moff=(tid>>7)*8;
    int a0=blockIdx.x*MB;
    for (int idx=tid; idx<128*MB; idx+=256){
        int m=idx>>7,k=idx&127;
        sB[k*SMS+m]=g_sln[(size_t)(a0+m)*128+k];
    }
    float av[8];
    #pragma unroll
    for (int mi=0;mi<8;mi++) av[mi]=g_a[(size_t)(a0+moff+mi)*128+j];

    float mu[8],rs[8];
    rowstats256(av, moff, sX, mu, rs);

    float acc[2][8]; ZERON8(acc,2);
    gemv8<32,2>(gP_sln + (size_t)l*32*256 + j, 256, sB+moff, acc);
    #pragma unroll
    for (int mi=0;mi<8;mi++)
        sX[j*SMS+moff+mi]=sigf(acc[0][mi])*((av[mi]-mu[mi])*rs[mi])+acc[1][mi];
    __syncthreads();

    float q3[3][8]; ZERON8(q3,3);
    gemv8<32,3>(gP_qkv + (size_t)l*32*384 + j, 384, sX+moff, q3);
    float qb = qbias[l*128+j];
    #pragma unroll
    for (int mi=0;mi<8;mi++){
        size_t b=(size_t)(a0+moff+mi)*384;
        g_qkv[b+j]      =q3[0][mi]+qb;
        g_qkv[b+128+j]  =q3[1][mi];
        g_qkv[b+256+j]  =q3[2][mi];
    }
}

// K5: windowed attention per (nb, head) — outer-product register-blocked
__global__ void __launch_bounds__(128) k_attn()
{
    extern __shared__ float sm[];
    float* vb  = sm;           // 128*33 = 4224
    float* qT  = vb + 4224;    // 32*36  = 1152
    float* sc  = qT + 1152;    // 4224 (32*129 used; aliased as red in AV epilogue)
    float* scT = sc + 4224;    // 128*36 = 4608
    int blk=blockIdx.x; int nb=blk>>2, h=blk&3;
    int tid=threadIdx.x;

    for (int idx=tid; idx<128*32; idx+=128){
        int kk=idx>>5, d=idx&31;
        int atom=nb*32+kk-48; atom=max(0,min(atom,NATOMS-1));
        vb[kk*33+d]=g_qkv[(size_t)atom*384+256+h*32+d];
    }
    for (int idx=tid; idx<1024; idx+=128){
        int d=idx>>5, qq=idx&31;
        qT[d*36+qq]=g_qkv[(size_t)(nb*32+qq)*384 + h*32 + d];
    }
    float kreg[32];
    {
        int atom=nb*32+tid-48; atom=max(0,min(atom,NATOMS-1));
        const float4* kr=(const float4*)&g_qkv[(size_t)atom*384+128+h*32];
        #pragma unroll
        for (int i=0;i<8;i++){
            float4 v=kr[i];
            kreg[i*4]=v.x; kreg[i*4+1]=v.y; kreg[i*4+2]=v.z; kreg[i*4+3]=v.w;
        }
    }
    __syncthreads();

    float acc[32];
    #pragma unroll
    for (int i=0;i<32;i++) acc[i]=0.f;
    #pragma unroll 4
    for (int d=0;d<32;d++){
        float kd=kreg[d];
        const float4* qp=(const float4*)&qT[d*36];
        #pragma unroll
        for (int r=0;r<8;r++){
            float4 q4=qp[r];
            acc[r*4]  +=q4.x*kd;
            acc[r*4+1]+=q4.y*kd;
            acc[r*4+2]+=q4.z*kd;
            acc[r*4+3]+=q4.w*kd;
        }
    }
    const float scale=0.1767766952966369f;
    const float* pbp=&g_pb[(size_t)((nb*4+h)*32)*128];
    #pragma unroll 4
    for (int qq=0;qq<32;qq++)
        sc[qq*129+tid]=acc[qq]*scale + pbp[(size_t)qq*128+tid];
    __syncthreads();

    {
        int qq2=tid>>2, sub=tid&3;
        float mx=-1e30f;
        #pragma unroll 4
        for (int i=0;i<32;i++) mx=fmaxf(mx, sc[qq2*129+sub+4*i]);
        mx=fmaxf(mx,__shfl_xor_sync(0xffffffffu,mx,1));
        mx=fmaxf(mx,__shfl_xor_sync(0xffffffffu,mx,2));
        float s=0;
        #pragma unroll 4
        for (int i=0;i<32;i++){
            int id=qq2*129+sub+4*i;
            float e=__expf(sc[id]-mx); sc[id]=e; s+=e;
        }
        s+=__shfl_xor_sync(0xffffffffu,s,1);
        s+=__shfl_xor_sync(0xffffffffu,s,2);
        float inv=1.0f/s;
        #pragma unroll 4
        for (int i=0;i<32;i++) sc[qq2*129+sub+4*i]*=inv;
    }
    __syncthreads();

    for (int idx=tid; idx<4096; idx+=128){
        int qq=idx&31, kk=idx>>5;
        scT[kk*36+qq]=sc[qq*129+kk];
    }
    __syncthreads();

    #pragma unroll
    for (int i=0;i<32;i++) acc[i]=0.f;
    int d=tid&31, kg=tid>>5;
    #pragma unroll 4
    for (int ki=0;ki<32;ki++){
        int k=kg*32+ki;
        float v=vb[k*33+d];
        const float4* sp=(const float4*)&scT[k*36];
        #pragma unroll
        for (int r=0;r<8;r++){
            float4 s4=sp[r];
            acc[r*4]  +=s4.x*v;
            acc[r*4+1]+=s4.y*v;
            acc[r*4+2]+=s4.z*v;
            acc[r*4+3]+=s4.w*v;
        }
    }
    float* red = sc;
    #pragma unroll
    for (int qq=0;qq<32;qq++) red[kg*1056+qq*33+d]=acc[qq];
    __syncthreads();
    for (int idx=tid; idx<1024; idx+=128){
        int qq=idx>>5, dd=idx&31;
        float s=red[qq*33+dd]+red[1056+qq*33+dd]+red[2112+qq*33+dd]+red[3168+qq*33+dd];
        g_o[(size_t)(nb*32+qq)*128 + h*32 + dd]=s;
    }
}

// K7: per-layer stage C (256 threads, m-split; fused gate+ada NC=3, fused ta NC=4)
__global__ void __launch_bounds__(256) k_stageC(const float* __restrict__ outb,
                                                const float* __restrict__ gateb, int l)
{
    __shared__ __align__(16) float sA[128*SMS];
    __shared__ __align__(16) float sB[128*SMS];
    __shared__ __align__(16) float sC[256*SMS];
    int tid=threadIdx.x, j=tid&127, moff=(tid>>7)*8;
    int a0=blockIdx.x*MB;
    for (int idx=tid; idx<128*MB; idx+=256){
        int m=idx>>7,k=idx&127;
        sA[k*SMS+m]=g_o  [(size_t)(a0+m)*128+k];
        sB[k*SMS+m]=g_sln[(size_t)(a0+m)*128+k];
    }
    float av[8];
    #pragma unroll
    for (int mi=0;mi<8;mi++) av[mi]=g_a[(size_t)(a0+moff+mi)*128+j];
    __syncthreads();

    // out proj (sA, NC=1)
    float o1[1][8]; ZERON8(o1,1);
    gemv8<32,1>(gP_out + (size_t)l*32*128 + j, 128, sA+moff, o1);

    // fused gate+ada (sB, NC=3): ga[0]=gate, ga[1]=ada_lo, ga[2]=ada_hi
    float ga[3][8]; ZERON8(ga,3);
    gemv8<32,3>(gP_ga + (size_t)l*32*384 + j, 384, sB+moff, ga);

    float ob=outb[l*128+j];
    float anew[8];
    #pragma unroll
    for (int mi=0;mi<8;mi++) anew[mi]=av[mi]+o1[0][mi]+ob;

    float mu[8],rs[8];
    rowstats256(anew, moff, sC, mu, rs);

    // xt -> sA
    #pragma unroll
    for (int mi=0;mi<8;mi++)
        sA[j*SMS+moff+mi]=sigf(ga[1][mi])*((anew[mi]-mu[mi])*rs[mi])+ga[2][mi];
    __syncthreads();

    // ta fused NC=4: tp[0]=lo_s0(j), tp[1]=lo_s1(j+128), tp[2]=hi_s0(j+256), tp[3]=hi_s1(j+384)
    {
        float tp[4][8]; ZERON8(tp,4);
        gemv8<32,4>(gP_ta + (size_t)l*32*512 + j, 512, sA+moff, tp);
        #pragma unroll
        for (int mi=0;mi<8;mi++){
            float a0_=tp[0][mi], a1_=tp[1][mi];
            sC[(j)*SMS+moff+mi]      = a0_*sigf(a0_)*tp[2][mi];
            sC[(128+j)*SMS+moff+mi]  = a1_*sigf(a1_)*tp[3][mi];
        }
    }
    __syncthreads();

    float hv[1][8]; ZERON8(hv,1);
    gemv8<64,1>(gP_tb + (size_t)l*64*128 + j, 128, sC+moff, hv);

    float gb_=gateb[l*128+j];
    #pragma unroll
    for (int mi=0;mi<8;mi++)
        g_a[(size_t)(a0+moff+mi)*128+j]=anew[mi]+sigf(ga[0][mi]+gb_)*hv[0][mi];
}

// K8: atom_out = relu(a @ W_tok^T) -> g_qkv (reuse)
__global__ void __launch_bounds__(256) k_tokproj()
{
    __shared__ __align__(16) float sA[128*SMS];
    int tid=threadIdx.x, j=tid&127, moff=(tid>>7)*8;
    int a0=blockIdx.x*MB;
    for (int idx=tid; idx<128*MB; idx+=256){
        int m=idx>>7,k=idx&127;
        sA[k*SMS+m]=g_a[(size_t)(a0+m)*128+k];
    }
    __syncthreads();
    float q3[3][8]; ZERON8(q3,3);
    gemv8<32,3>(gP_tok + j, 384, sA+moff, q3);
    #pragma unroll
    for (int mi=0;mi<8;mi++){
        size_t b=(size_t)(a0+moff+mi)*384;
        g_qkv[b+j]    =fmaxf(q3[0][mi],0.f);
        g_qkv[b+128+j]=fmaxf(q3[1][mi],0.f);
        g_qkv[b+256+j]=fmaxf(q3[2][mi],0.f);
    }
}

// K9: deterministic segment mean
__global__ void __launch_bounds__(128) k_tokmean(const int* __restrict__ a2t)
{
    __shared__ int slo,shi;
    int t=blockIdx.x;
    if (threadIdx.x==0){
        int lo=0,hi=NATOMS;
        while(lo<hi){int mid=(lo+hi)>>1; if(a2t[mid]<t) lo=mid+1; else hi=mid;}
        slo=lo; int lo2=lo; hi=NATOMS;
        while(lo2<hi){int mid=(lo2+hi)>>1; if(a2t[mid]<t+1) lo2=mid+1; else hi=mid;}
        shi=lo2;
    }
    __syncthreads();
    int lo=slo,hi=shi;
    float inv=1.0f/fmaxf((float)(hi-lo),1.0f);
    #pragma unroll
    for (int s=0;s<3;s++){
        int d=s*128+threadIdx.x;
        float sum=0;
        for (int a=lo;a<hi;a++) sum+=g_qkv[(size_t)a*384+d];
        g_tok[(size_t)t*384+d]=sum*inv;
    }
}

// K10: s_trunk, s_struct -> d_out ; u -> g_u (256 threads, m-split)
__global__ void __launch_bounds__(256) k_trunkstruct(float* __restrict__ out)
{
    __shared__ __align__(16) float sT[384*SMS];
    int tid=threadIdx.x, j=tid&127, moff=(tid>>7)*8;
    int t0=blockIdx.x*MB;
    for (int idx=tid; idx<384*MB; idx+=256){
        int m=idx/384, k=idx%384;
        sT[k*SMS+m]=g_tok[(size_t)(t0+m)*384+k];
    }
    __syncthreads();
    {
        float c3[3][8]; ZERON8(c3,3);
        gemv8<96,3>(gP_trunk + j, 384, sT+moff, c3);
        #pragma unroll
        for (int mi=0;mi<8;mi++){
            size_t b=(size_t)(t0+moff+mi)*384;
            out[b+j]=c3[0][mi]; out[b+128+j]=c3[1][mi]; out[b+256+j]=c3[2][mi];
        }
    }
    {
        float* o2 = out + (size_t)NTOK*384;
        float c3[3][8]; ZERON8(c3,3);
        gemv8<96,3>(gP_struc + j, 384, sT+moff, c3);
        #pragma unroll
        for (int mi=0;mi<8;mi++){
            size_t b=(size_t)(t0+moff+mi)*384;
            o2[b+j]=c3[0][mi]; o2[b+128+j]=c3[1][mi]; o2[b+256+j]=c3[2][mi];
        }
    }
    {
        float c2[2][8]; ZERON8(c2,2);
        gemv8<96,2>(gP_outer + j, 256, sT+moff, c2);
        #pragma unroll
        for (int mi=0;mi<8;mi++){
            size_t b=(size_t)(t0+moff+mi)*256;
            g_u[b+j]=c2[0][mi]; g_u[b+128+j]=c2[1][mi];
        }
    }
}

// K11: pair = tpf@W_pairin^T + u_lo[i] + u_hi[j] — weights in registers
__global__ void __launch_bounds__(128) k_pair(const float* __restrict__ tpf,
                                              float* __restrict__ outp)
{
    __shared__ __align__(16) float tj[8*32];
    int i=blockIdx.x, c=threadIdx.x;
    float4 w[8];
    #pragma unroll
    for (int k4=0;k4<8;k4++) w[k4]=gP_pairin[k4*128+c];
    float uiv=g_u[(size_t)i*256+c];
    for (int j0=0;j0<NTOK;j0+=8){
        __syncthreads();
        for (int idx=c; idx<256; idx+=128)
            tj[idx]=tpf[((size_t)i*NTOK+j0)*32 + idx];
        __syncthreads();
        #pragma unroll
        for (int jj=0;jj<8;jj++){
            int j=j0+jj;
            float a=uiv+g_u[(size_t)j*256+128+c];
            const float4* tp=(const float4*)&tj[jj*32];
            #pragma unroll
            for (int k4=0;k4<8;k4++){
                float4 t4=tp[k4];
                a += w[k4].x*t4.x + w[k4].y*t4.y + w[k4].z*t4.z + w[k4].w*t4.w;
            }
            outp[((size_t)i*NTOK+j)*128+c]=a;
        }
    }
}

extern "C" void kernel_launch(void* const* d_in, const int* in_sizes, int n_in,
                              void* d_out, int out_size)
{
    const float* af      = (const float*)d_in[0];
    const float* tpf     = (const float*)d_in[1];
    const float* W_cond  = (const float*)d_in[2];
    const float* W_ph    = (const float*)d_in[3];
    const float* W_pw    = (const float*)d_in[4];
    const float* W_mlp1  = (const float*)d_in[5];
    const float* W_mlp2  = (const float*)d_in[6];
    const float* pb_ln_w = (const float*)d_in[7];
    const float* pb_ln_b = (const float*)d_in[8];
    const float* pb_w    = (const float*)d_in[9];
    const float* sln_w   = (const float*)d_in[10];
    const float* qkv_w   = (const float*)d_in[11];
    const float* q_bias  = (const float*)d_in[12];
    const float* out_w   = (const float*)d_in[13];
    const float* out_b   = (const float*)d_in[14];
    const float* ada_w   = (const float*)d_in[15];
    const float* ta_w    = (const float*)d_in[16];
    const float* tb_w    = (const float*)d_in[17];
    const float* gate_w  = (const float*)d_in[18];
    const float* gate_b  = (const float*)d_in[19];
    const float* W_tok   = (const float*)d_in[20];
    const float* W_trunk = (const float*)d_in[21];
    const float* W_struct= (const float*)d_in[22];
    const float* W_pairin= (const float*)d_in[23];
    const float* W_outer = (const float*)d_in[24];
    const int*   a2t     = (const int*)d_in[28];
    float* out = (float*)d_out;

    PackArgs pa;
    void* p;
    #define SETP(i,sym,srcp,OUTv,Kv,Lv,DOUTv,JOFFv) \
        cudaGetSymbolAddress(&p, sym); \
        pa.d[i] = PackDesc{ srcp, (float*)p, OUTv, Kv, Lv, DOUTv, JOFFv };
    SETP(0,  gP_cond,   W_cond,   128,128,1, 128,0);
    SETP(1,  gP_ph,     W_ph,      16,128,1,  16,0);
    SETP(2,  gP_pw,     W_pw,      16,128,1,  16,0);
    SETP(3,  gP_sln,    sln_w,    256,128,3, 256,0);
    SETP(4,  gP_qkv,    qkv_w,    384,128,3, 384,0);
    SETP(5,  gP_out,    out_w,    128,128,3, 128,0);
    SETP(6,  gP_ga,     gate_w,   128,128,3, 384,0);     // gate -> cols [0,128)
    SETP(7,  gP_ga,     ada_w,    256,128,3, 384,128);   // ada  -> cols [128,384)
    SETP(8,  gP_ta,     ta_w,     512,128,3, 512,0);
    SETP(9,  gP_tb,     tb_w,     128,256,3, 128,0);
    SETP(10, gP_tok,    W_tok,    384,128,1, 384,0);
    SETP(11, gP_trunk,  W_trunk,  384,384,1, 384,0);
    SETP(12, gP_struc,  W_struct, 384,384,1, 384,0);
    SETP(13, gP_pairin, W_pairin, 128, 32,1, 128,0);
    SETP(14, gP_outer,  W_outer,  256,384,1, 256,0);
    #undef SETP

    const int NBLK = NATOMS/MB;              // 736
    const int ATTN_SMEM = (4224+1152+4224+4608)*4;  // 56832 B
    cudaFuncSetAttribute(k_attn, cudaFuncAttributeMaxDynamicSharedMemorySize, ATTN_SMEM);

    // stageA(l=0) stays the 4th launch (profiler samples launch #4).
    k_pack<<<dim3(96,15),256>>>(pa);                 // 1
    k_cond<<<NBLK,256>>>(af);                        // 2
    k_phpw<<<NATOMS/16 + NB*128/16,256>>>();         // 3
    k_stageA<<<NBLK,256>>>(q_bias,0);                // 4  <-- profiled
    k_pb  <<<NB*32,128>>>(W_mlp1,W_mlp2,pb_ln_w,pb_ln_b,pb_w);  // 5

    for (int l=0;l<NL;l++){
        if (l>0) k_stageA<<<NBLK,256>>>(q_bias,l);
        k_attn  <<<NB*4,128,ATTN_SMEM>>>();
        k_stageC<<<NBLK,256>>>(out_b,gate_b,l);
    }

    k_tokproj<<<NBLK,256>>>();
    k_tokmean<<<NTOK,128>>>(a2t);
    k_trunkstruct<<<NTOK/MB,256>>>(out);
    k_pair<<<NTOK,128>>>(tpf, out + (size_t)2*NTOK*384);
}

// round 11
// speedup vs baseline: 1.2483x; 1.0333x over previous
#include <cuda_runtime.h>

#define NATOMS 11776
#define NB     368
#define NTOK   512
#define NL     3
#define MB     16
#define SMS    20

// ---- scratch ----
__device__ float g_sln[NATOMS*128];
__device__ float g_a  [NATOMS*128];
__device__ float g_qkv[NATOMS*384];
__device__ float g_o  [NATOMS*128];
__device__ float g_ph [NATOMS*16];
__device__ float g_pw [NB*128*16];
__device__ float g_pb [NB*4*32*128];
__device__ float g_tok[NTOK*384];
__device__ float g_u  [NTOK*256];

// ---- packed weights (FFMA path): P[(k/4)*OUT + j] = float4{ W[j][k..k+3] } ----
__device__ float4 gP_cond [32*128];
__device__ float4 gP_ph   [32*16];
__device__ float4 gP_pw   [32*16];
__device__ float4 gP_out  [NL*32*128];
__device__ float4 gP_ga   [NL*32*384];   // gate (cols 0-127) ‖ ada (cols 128-383)
__device__ float4 gP_ta   [NL*32*512];
__device__ float4 gP_tb   [NL*64*128];
__device__ float4 gP_tok  [32*384];
__device__ float4 gP_trunk[96*384];
__device__ float4 gP_struc[96*384];
__device__ float4 gP_pairin[8*128];
__device__ float4 gP_outer[96*256];

// ---- mma fragment-packed weights (tf32x3): dst[((l*K8+k4)*NT+nt)*32+lane] =
//      float4{ b0hi, b1hi, b0lo, b1lo }, b0=W[nt*8+lane/4][k4*8+lane%4], b1=+4k ----
__device__ float4 gPM_sln[NL*16*32*32];   // OUT=256 -> NT=32
__device__ float4 gPM_qkv[NL*16*48*32];   // OUT=384 -> NT=48

__device__ __forceinline__ float sigf(float x){ return 1.0f/(1.0f+__expf(-x)); }
__device__ __forceinline__ unsigned int f2tf32u(float x){
    unsigned int r; asm("cvt.rna.tf32.f32 %0, %1;" : "=r"(r) : "f"(x)); return r;
}
#define MMA8(cc,A0,A1,A2,A3,B0,B1) \
  asm volatile("mma.sync.aligned.m16n8k8.row.col.f32.tf32.tf32.f32 " \
    "{%0,%1,%2,%3},{%4,%5,%6,%7},{%8,%9},{%0,%1,%2,%3};" \
    : "+f"(cc[0]),"+f"(cc[1]),"+f"(cc[2]),"+f"(cc[3]) \
    : "r"(A0),"r"(A1),"r"(A2),"r"(A3),"r"(B0),"r"(B1));

#define ZERO8(a) { _Pragma("unroll") for(int _m=0;_m<8;_m++) a[_m]=0.f; }
#define ZERON8(a,N) { _Pragma("unroll") for(int _n=0;_n<(N);_n++) ZERO8(a[_n]); }

// FFMA register-blocked GEMV (unchanged, used by non-mma kernels)
template<int K4, int NC, int COFF=128>
__device__ __forceinline__ void gemv8(const float4* __restrict__ Wb, int out4,
                                      const float* __restrict__ sXm, float (*acc)[8])
{
    #pragma unroll 2
    for (int k4=0;k4<K4;k4++){
        float4 w[NC];
        #pragma unroll
        for (int n=0;n<NC;n++) w[n]=Wb[k4*out4 + n*COFF];
        const float* xb = sXm + (k4<<2)*SMS;
        #pragma unroll
        for (int c=0;c<4;c++){
            const float4* _p=(const float4*)(xb + c*SMS);
            float4 x0=_p[0], x1=_p[1];
            #pragma unroll
            for (int n=0;n<NC;n++){
                float wc=(c==0)?w[n].x:(c==1)?w[n].y:(c==2)?w[n].z:w[n].w;
                acc[n][0]+=x0.x*wc; acc[n][1]+=x0.y*wc; acc[n][2]+=x0.z*wc; acc[n][3]+=x0.w*wc;
                acc[n][4]+=x1.x*wc; acc[n][5]+=x1.y*wc; acc[n][6]+=x1.z*wc; acc[n][7]+=x1.w*wc;
            }
        }
    }
}

// per-atom mean/rstd over 128 dims, 16 atoms, 256 threads (for FFMA kernels)
__device__ __forceinline__ void rowstats256(const float v[8], int moff, float* stage,
                                            float mu[8], float rs[8])
{
    const int tid=threadIdx.x, j=tid&127;
    for (int pass=0; pass<2; pass++){
        __syncthreads();
        #pragma unroll
        for (int mi=0;mi<8;mi++){
            float x=(pass==0)? v[mi] : (v[mi]-mu[mi]);
            stage[(moff+mi)*132 + j] = (pass==0)? x : x*x;
        }
        __syncthreads();
        { int row=tid>>4, seg=tid&15;
          float s=0;
          #pragma unroll
          for (int u=0;u<8;u++) s+=stage[row*132 + seg*8 + u];
          stage[2112+tid]=s; }
        __syncthreads();
        if (tid<16){ float t2=0;
          #pragma unroll
          for (int u=0;u<16;u++) t2+=stage[2112+tid*16+u];
          stage[2368+tid]=t2*(1.0f/128.0f); }
        __syncthreads();
        if (pass==0){
            #pragma unroll
            for (int mi=0;mi<8;mi++) mu[mi]=stage[2368+moff+mi];
        } else {
            #pragma unroll
            for (int mi=0;mi<8;mi++) rs[mi]=rsqrtf(stage[2368+moff+mi]+1e-5f);
        }
    }
    __syncthreads();
}

// ---- FFMA weight packer ----
struct PackDesc { const float* src; float* dst; int OUT; int K; int L; int dstOut; int joff; };
struct PackArgs { PackDesc d[13]; };
__global__ void k_pack(PackArgs pa)
{
    PackDesc pd = pa.d[blockIdx.y];
    int total = pd.L*pd.OUT*pd.K;
    int K4 = pd.K>>2;
    for (int idx = blockIdx.x*256 + threadIdx.x; idx < total; idx += gridDim.x*256){
        int c = idx&3; int t = idx>>2;
        int j = t % pd.OUT; int q = t / pd.OUT;
        int k4 = q % K4;    int l = q / K4;
        size_t daddr = (((size_t)l*K4 + k4)*pd.dstOut + pd.joff + j)*4 + c;
        pd.dst[daddr] = pd.src[((size_t)l*pd.OUT + j)*pd.K + k4*4 + c];
    }
}

// ---- mma fragment weight packer (tf32 hi/lo) ----
__global__ void k_packmma(const float* __restrict__ src, float4* __restrict__ dst,
                          int OUT, int K, int L)
{
    int K8=K>>3, NT=OUT>>3;
    int total=L*K8*NT*32;
    for (int idx=blockIdx.x*256+threadIdx.x; idx<total; idx+=gridDim.x*256){
        int lane=idx&31; int t=idx>>5;
        int nt=t%NT; int t2=t/NT; int k4=t2%K8; int l=t2/K8;
        int n=nt*8+(lane>>2), k=k4*8+(lane&3);
        float w0=src[((size_t)l*OUT+n)*K+k];
        float w1=src[((size_t)l*OUT+n)*K+k+4];
        unsigned int h0=f2tf32u(w0), h1=f2tf32u(w1);
        float l0=w0-__uint_as_float(h0), l1=w1-__uint_as_float(h1);
        dst[idx]=make_float4(__uint_as_float(h0),__uint_as_float(h1),
                             __uint_as_float(f2tf32u(l0)),__uint_as_float(f2tf32u(l1)));
    }
}

// K1: c = af@Wcond^T ; a=c ; s_ln=LN(c)   (FFMA)
__global__ void __launch_bounds__(256) k_cond(const float* __restrict__ af)
{
    __shared__ __align__(16) float sA[128*SMS];
    int tid=threadIdx.x, j=tid&127, moff=(tid>>7)*8;
    int a0 = blockIdx.x*MB;
    for (int idx=tid; idx<128*MB; idx+=256){
        int m=idx>>7, k=idx&127;
        sA[k*SMS+m] = af[(size_t)(a0+m)*128 + k];
    }
    __syncthreads();
    float acc[1][8]; ZERON8(acc,1);
    gemv8<32,1>(gP_cond + j, 128, sA+moff, acc);
    #pragma unroll
    for (int mi=0;mi<8;mi++) g_a[(size_t)(a0+moff+mi)*128+j]=acc[0][mi];
    float mu[8], rs[8];
    rowstats256(acc[0], moff, sA, mu, rs);
    #pragma unroll
    for (int mi=0;mi<8;mi++) g_sln[(size_t)(a0+moff+mi)*128+j]=(acc[0][mi]-mu[mi])*rs[mi];
}

// K2: fused ph / pw
__global__ void __launch_bounds__(256) k_phpw()
{
    __shared__ float xs[16*132];
    int tid=threadIdx.x;
    bool isph = blockIdx.x < (NATOMS/16);
    int r0 = isph ? blockIdx.x*16 : (blockIdx.x-(NATOMS/16))*16;
    for (int idx=tid; idx<16*128; idx+=256){
        int r=idx>>7,k=idx&127;
        int row=r0+r;
        int atom;
        if (isph) atom=row;
        else { int nb=row>>7, kk=row&127; atom=nb*32+kk-48; atom=max(0,min(atom,NATOMS-1)); }
        xs[r*132+k]=fmaxf(g_sln[(size_t)atom*128+k],0.f);
    }
    __syncthreads();
    int o=tid&15, r=tid>>4;
    const float4* W = isph ? gP_ph : gP_pw;
    float acc=0;
    #pragma unroll 4
    for (int k4=0;k4<32;k4++){
        float4 w = W[k4*16+o];
        const float* xb=&xs[r*132+k4*4];
        acc += xb[0]*w.x+xb[1]*w.y+xb[2]*w.z+xb[3]*w.w;
    }
    if (isph) g_ph[(size_t)(r0+r)*16+o]=acc;
    else      g_pw[(size_t)(r0+r)*16+o]=acc;
}

// K3: pair bias
__global__ void __launch_bounds__(128) k_pb(const float* __restrict__ W1g,
                                            const float* __restrict__ W2g,
                                            const float* __restrict__ lnw,
                                            const float* __restrict__ lnb,
                                            const float* __restrict__ pbw)
{
    __shared__ float W1[256], W2[256], PBW[64], LW[16], LB[16], PH[16];
    int tid=threadIdx.x;
    int blk=blockIdx.x; int nb=blk>>5, q=blk&31;
    for (int idx=tid; idx<256; idx+=128){ W1[idx]=W1g[idx]; W2[idx]=W2g[idx]; }
    if (tid<64) PBW[tid]=pbw[tid];
    if (tid<16){ LW[tid]=lnw[tid]; LB[tid]=lnb[tid];
                 PH[tid]=g_ph[(size_t)(nb*32+q)*16+tid]; }
    __syncthreads();

    float p[16];
    { const float4* pwp=(const float4*)&g_pw[(size_t)(nb*128+tid)*16];
      float4 a=pwp[0],b=pwp[1],c=pwp[2],d=pwp[3];
      p[0]=a.x;p[1]=a.y;p[2]=a.z;p[3]=a.w; p[4]=b.x;p[5]=b.y;p[6]=b.z;p[7]=b.w;
      p[8]=c.x;p[9]=c.y;p[10]=c.z;p[11]=c.w; p[12]=d.x;p[13]=d.y;p[14]=d.z;p[15]=d.w; }
    #pragma unroll
    for (int i=0;i<16;i++) p[i]+=PH[i];

    float t[16], u[16];
    #pragma unroll
    for (int i=0;i<16;i++) t[i]=fmaxf(p[i],0.f);
    #pragma unroll
    for (int o=0;o<16;o++){
        float s=0;
        #pragma unroll
        for (int i=0;i<16;i++) s+=t[i]*W1[o*16+i];
        u[o]=fmaxf(s,0.f);
    }
    #pragma unroll
    for (int o=0;o<16;o++){
        float s=0;
        #pragma unroll
        for (int i=0;i<16;i++) s+=u[i]*W2[o*16+i];
        p[o]+=s;
    }
    float mu=0;
    #pragma unroll
    for (int i=0;i<16;i++) mu+=p[i];
    mu*=(1.0f/16.0f);
    float var=0;
    #pragma unroll
    for (int i=0;i<16;i++){ float d=p[i]-mu; var+=d*d; }
    float rsd=rsqrtf(var*(1.0f/16.0f)+1e-5f);
    float y[16];
    #pragma unroll
    for (int i=0;i<16;i++) y[i]=(p[i]-mu)*rsd*LW[i]+LB[i];

    int win = nb*32 + tid - 48;
    float neg = (win>=0 && win<NATOMS) ? 0.f : -1.0e9f;
    #pragma unroll
    for (int h=0;h<4;h++){
        float s=0;
        #pragma unroll
        for (int i=0;i<16;i++) s+=y[i]*PBW[h*16+i];
        g_pb[(size_t)((nb*4+h)*32+q)*128+tid]=s+neg;
    }
}

// K4: per-layer stage A — TF32x3 mma.sync (256 threads = 8 warps, 16 atoms/block)
__global__ void __launch_bounds__(256) k_stageA(const float* __restrict__ qbias, int l)
{
    __shared__ __align__(16) float sHi[16*132];
    __shared__ __align__(16) float sLo[16*132];
    __shared__ __align__(16) float sLn[16*132];
    __shared__ float sMu[16], sRs[16];
    int tid=threadIdx.x, lane=tid&31, wp=tid>>5;
    int g=lane>>2, tig=lane&3;
    int a0=blockIdx.x*MB;

    // load s_ln -> hi/lo frag tile [m][k]; load a -> sLn raw
    for (int i=tid;i<512;i+=256){
        int m=i>>5, kq=(i&31)*4;
        float4 v=*(const float4*)&g_sln[(size_t)(a0+m)*128+kq];
        float xs4[4]={v.x,v.y,v.z,v.w};
        #pragma unroll
        for(int e=0;e<4;e++){
            unsigned int hb=f2tf32u(xs4[e]); float h=__uint_as_float(hb);
            sHi[m*132+kq+e]=h;
            sLo[m*132+kq+e]=__uint_as_float(f2tf32u(xs4[e]-h));
        }
        float4 av=*(const float4*)&g_a[(size_t)(a0+m)*128+kq];
        *(float4*)&sLn[m*132+kq]=av;
    }
    __syncthreads();
    // LN(a) stats: warp wp handles rows 2wp, 2wp+1 (16-lane halves)
    {
        int r=2*wp+(lane>>4), c0=(lane&15)*8;
        float s=0.f,s2=0.f;
        #pragma unroll
        for(int u=0;u<8;u++){ float x=sLn[r*132+c0+u]; s+=x; s2+=x*x; }
        #pragma unroll
        for(int d=1;d<16;d<<=1){ s+=__shfl_xor_sync(0xffffffffu,s,d); s2+=__shfl_xor_sync(0xffffffffu,s2,d); }
        if((lane&15)==0){ float m_=s*(1.f/128.f), e2=s2*(1.f/128.f);
            sMu[r]=m_; sRs[r]=rsqrtf(e2-m_*m_+1e-5f); }
    }
    __syncthreads();
    {
        int r=2*wp+(lane>>4), c0=(lane&15)*8;
        float m_=sMu[r], rs_=sRs[r];
        #pragma unroll
        for(int u=0;u<8;u++) sLn[r*132+c0+u]=(sLn[r*132+c0+u]-m_)*rs_;
    }
    __syncthreads();

    // gemv1 (sln weights, OUT=256): warp tiles {2w,2w+1, 2w+16,2w+17}
    float c[4][4];
    #pragma unroll
    for(int t=0;t<4;t++){ c[t][0]=0;c[t][1]=0;c[t][2]=0;c[t][3]=0; }
    {
        const float4* B = gPM_sln + (size_t)l*16*32*32;
        #pragma unroll 2
        for (int k4=0;k4<16;k4++){
            int kb=k4*8;
            unsigned int ah0=__float_as_uint(sHi[g*132+kb+tig]);
            unsigned int ah1=__float_as_uint(sHi[(g+8)*132+kb+tig]);
            unsigned int ah2=__float_as_uint(sHi[g*132+kb+tig+4]);
            unsigned int ah3=__float_as_uint(sHi[(g+8)*132+kb+tig+4]);
            unsigned int al0=__float_as_uint(sLo[g*132+kb+tig]);
            unsigned int al1=__float_as_uint(sLo[(g+8)*132+kb+tig]);
            unsigned int al2=__float_as_uint(sLo[g*132+kb+tig+4]);
            unsigned int al3=__float_as_uint(sLo[(g+8)*132+kb+tig+4]);
            #pragma unroll
            for (int t=0;t<4;t++){
                int nt=(t<2)? (2*wp+t) : (2*wp+14+t);
                float4 b=B[((size_t)k4*32+nt)*32+lane];
                unsigned int bh0=__float_as_uint(b.x), bh1=__float_as_uint(b.y);
                unsigned int bl0=__float_as_uint(b.z), bl1=__float_as_uint(b.w);
                MMA8(c[t],ah0,ah1,ah2,ah3,bh0,bh1);
                MMA8(c[t],ah0,ah1,ah2,ah3,bl0,bl1);
                MMA8(c[t],al0,al1,al2,al3,bh0,bh1);
            }
        }
    }
    __syncthreads();   // all reads of sHi/sLo done; safe to overwrite with x
    #pragma unroll
    for (int i=0;i<2;i++){
        int nb=(2*wp+i)*8+2*tig;
        float x0=sigf(c[i][0])*sLn[g*132+nb]       + c[i+2][0];
        float x1=sigf(c[i][1])*sLn[g*132+nb+1]     + c[i+2][1];
        float x2=sigf(c[i][2])*sLn[(g+8)*132+nb]   + c[i+2][2];
        float x3=sigf(c[i][3])*sLn[(g+8)*132+nb+1] + c[i+2][3];
        unsigned int hb;
        hb=f2tf32u(x0); sHi[g*132+nb]      =__uint_as_float(hb); sLo[g*132+nb]      =__uint_as_float(f2tf32u(x0-__uint_as_float(hb)));
        hb=f2tf32u(x1); sHi[g*132+nb+1]    =__uint_as_float(hb); sLo[g*132+nb+1]    =__uint_as_float(f2tf32u(x1-__uint_as_float(hb)));
        hb=f2tf32u(x2); sHi[(g+8)*132+nb]  =__uint_as_float(hb); sLo[(g+8)*132+nb]  =__uint_as_float(f2tf32u(x2-__uint_as_float(hb)));
        hb=f2tf32u(x3); sHi[(g+8)*132+nb+1]=__uint_as_float(hb); sLo[(g+8)*132+nb+1]=__uint_as_float(f2tf32u(x3-__uint_as_float(hb)));
    }
    __syncthreads();

    // gemv2 (qkv weights, OUT=384): warp tiles {6w..6w+5}
    float q[6][4];
    #pragma unroll
    for(int t=0;t<6;t++){ q[t][0]=0;q[t][1]=0;q[t][2]=0;q[t][3]=0; }
    {
        const float4* B = gPM_qkv + (size_t)l*16*48*32;
        #pragma unroll 2
        for (int k4=0;k4<16;k4++){
            int kb=k4*8;
            unsigned int ah0=__float_as_uint(sHi[g*132+kb+tig]);
            unsigned int ah1=__float_as_uint(sHi[(g+8)*132+kb+tig]);
            unsigned int ah2=__float_as_uint(sHi[g*132+kb+tig+4]);
            unsigned int ah3=__float_as_uint(sHi[(g+8)*132+kb+tig+4]);
            unsigned int al0=__float_as_uint(sLo[g*132+kb+tig]);
            unsigned int al1=__float_as_uint(sLo[(g+8)*132+kb+tig]);
            unsigned int al2=__float_as_uint(sLo[g*132+kb+tig+4]);
            unsigned int al3=__float_as_uint(sLo[(g+8)*132+kb+tig+4]);
            #pragma unroll
            for (int t=0;t<6;t++){
                int nt=6*wp+t;
                float4 b=B[((size_t)k4*48+nt)*32+lane];
                unsigned int bh0=__float_as_uint(b.x), bh1=__float_as_uint(b.y);
                unsigned int bl0=__float_as_uint(b.z), bl1=__float_as_uint(b.w);
                MMA8(q[t],ah0,ah1,ah2,ah3,bh0,bh1);
                MMA8(q[t],ah0,ah1,ah2,ah3,bl0,bl1);
                MMA8(q[t],al0,al1,al2,al3,bh0,bh1);
            }
        }
    }
    #pragma unroll
    for (int t=0;t<6;t++){
        int nb=(6*wp+t)*8+2*tig;
        float qb0=0.f, qb1=0.f;
        if (nb<128){ qb0=qbias[l*128+nb]; qb1=qbias[l*128+nb+1]; }
        g_qkv[(size_t)(a0+g)*384+nb]     = q[t][0]+qb0;
        g_qkv[(size_t)(a0+g)*384+nb+1]   = q[t][1]+qb1;
        g_qkv[(size_t)(a0+g+8)*384+nb]   = q[t][2]+qb0;
        g_qkv[(size_t)(a0+g+8)*384+nb+1] = q[t][3]+qb1;
    }
}

// K5: windowed attention per (nb, head)
__global__ void __launch_bounds__(128) k_attn()
{
    extern __shared__ float sm[];
    float* vb  = sm;
    float* qT  = vb + 4224;
    float* sc  = qT + 1152;
    float* scT = sc + 4224;
    int blk=blockIdx.x; int nb=blk>>2, h=blk&3;
    int tid=threadIdx.x;

    for (int idx=tid; idx<128*32; idx+=128){
        int kk=idx>>5, d=idx&31;
        int atom=nb*32+kk-48; atom=max(0,min(atom,NATOMS-1));
        vb[kk*33+d]=g_qkv[(size_t)atom*384+256+h*32+d];
    }
    for (int idx=tid; idx<1024; idx+=128){
        int d=idx>>5, qq=idx&31;
        qT[d*36+qq]=g_qkv[(size_t)(nb*32+qq)*384 + h*32 + d];
    }
    float kreg[32];
    {
        int atom=nb*32+tid-48; atom=max(0,min(atom,NATOMS-1));
        const float4* kr=(const float4*)&g_qkv[(size_t)atom*384+128+h*32];
        #pragma unroll
        for (int i=0;i<8;i++){
            float4 v=kr[i];
            kreg[i*4]=v.x; kreg[i*4+1]=v.y; kreg[i*4+2]=v.z; kreg[i*4+3]=v.w;
        }
    }
    __syncthreads();

    float acc[32];
    #pragma unroll
    for (int i=0;i<32;i++) acc[i]=0.f;
    #pragma unroll 4
    for (int d=0;d<32;d++){
        float kd=kreg[d];
        const float4* qp=(const float4*)&qT[d*36];
        #pragma unroll
        for (int r=0;r<8;r++){
            float4 q4=qp[r];
            acc[r*4]  +=q4.x*kd;
            acc[r*4+1]+=q4.y*kd;
            acc[r*4+2]+=q4.z*kd;
            acc[r*4+3]+=q4.w*kd;
        }
    }
    const float scale=0.1767766952966369f;
    const float* pbp=&g_pb[(size_t)((nb*4+h)*32)*128];
    #pragma unroll 4
    for (int qq=0;qq<32;qq++)
        sc[qq*129+tid]=acc[qq]*scale + pbp[(size_t)qq*128+tid];
    __syncthreads();

    {
        int qq2=tid>>2, sub=tid&3;
        float mx=-1e30f;
        #pragma unroll 4
        for (int i=0;i<32;i++) mx=fmaxf(mx, sc[qq2*129+sub+4*i]);
        mx=fmaxf(mx,__shfl_xor_sync(0xffffffffu,mx,1));
        mx=fmaxf(mx,__shfl_xor_sync(0xffffffffu,mx,2));
        float s=0;
        #pragma unroll 4
        for (int i=0;i<32;i++){
            int id=qq2*129+sub+4*i;
            float e=__expf(sc[id]-mx); sc[id]=e; s+=e;
        }
        s+=__shfl_xor_sync(0xffffffffu,s,1);
        s+=__shfl_xor_sync(0xffffffffu,s,2);
        float inv=1.0f/s;
        #pragma unroll 4
        for (int i=0;i<32;i++) sc[qq2*129+sub+4*i]*=inv;
    }
    __syncthreads();

    for (int idx=tid; idx<4096; idx+=128){
        int qq=idx&31, kk=idx>>5;
        scT[kk*36+qq]=sc[qq*129+kk];
    }
    __syncthreads();

    #pragma unroll
    for (int i=0;i<32;i++) acc[i]=0.f;
    int d=tid&31, kg=tid>>5;
    #pragma unroll 4
    for (int ki=0;ki<32;ki++){
        int k=kg*32+ki;
        float v=vb[k*33+d];
        const float4* sp=(const float4*)&scT[k*36];
        #pragma unroll
        for (int r=0;r<8;r++){
            float4 s4=sp[r];
            acc[r*4]  +=s4.x*v;
            acc[r*4+1]+=s4.y*v;
            acc[r*4+2]+=s4.z*v;
            acc[r*4+3]+=s4.w*v;
        }
    }
    float* red = sc;
    #pragma unroll
    for (int qq=0;qq<32;qq++) red[kg*1056+qq*33+d]=acc[qq];
    __syncthreads();
    for (int idx=tid; idx<1024; idx+=128){
        int qq=idx>>5, dd=idx&31;
        float s=red[qq*33+dd]+red[1056+qq*33+dd]+red[2112+qq*33+dd]+red[3168+qq*33+dd];
        g_o[(size_t)(nb*32+qq)*128 + h*32 + dd]=s;
    }
}

// K7: per-layer stage C (FFMA, fused ga NC=3, ta NC=4)
__global__ void __launch_bounds__(256) k_stageC(const float* __restrict__ outb,
                                                const float* __restrict__ gateb, int l)
{
    __shared__ __align__(16) float sA[128*SMS];
    __shared__ __align__(16) float sB[128*SMS];
    __shared__ __align__(16) float sC[256*SMS];
    int tid=threadIdx.x, j=tid&127, moff=(tid>>7)*8;
    int a0=blockIdx.x*MB;
    for (int idx=tid; idx<128*MB; idx+=256){
        int m=idx>>7,k=idx&127;
        sA[k*SMS+m]=g_o  [(size_t)(a0+m)*128+k];
        sB[k*SMS+m]=g_sln[(size_t)(a0+m)*128+k];
    }
    float av[8];
    #pragma unroll
    for (int mi=0;mi<8;mi++) av[mi]=g_a[(size_t)(a0+moff+mi)*128+j];
    __syncthreads();

    float o1[1][8]; ZERON8(o1,1);
    gemv8<32,1>(gP_out + (size_t)l*32*128 + j, 128, sA+moff, o1);

    float ga[3][8]; ZERON8(ga,3);
    gemv8<32,3>(gP_ga + (size_t)l*32*384 + j, 384, sB+moff, ga);

    float ob=outb[l*128+j];
    float anew[8];
    #pragma unroll
    for (int mi=0;mi<8;mi++) anew[mi]=av[mi]+o1[0][mi]+ob;

    float mu[8],rs[8];
    rowstats256(anew, moff, sC, mu, rs);

    #pragma unroll
    for (int mi=0;mi<8;mi++)
        sA[j*SMS+moff+mi]=sigf(ga[1][mi])*((anew[mi]-mu[mi])*rs[mi])+ga[2][mi];
    __syncthreads();

    {
        float tp[4][8]; ZERON8(tp,4);
        gemv8<32,4>(gP_ta + (size_t)l*32*512 + j, 512, sA+moff, tp);
        #pragma unroll
        for (int mi=0;mi<8;mi++){
            float a0_=tp[0][mi], a1_=tp[1][mi];
            sC[(j)*SMS+moff+mi]      = a0_*sigf(a0_)*tp[2][mi];
            sC[(128+j)*SMS+moff+mi]  = a1_*sigf(a1_)*tp[3][mi];
        }
    }
    __syncthreads();

    float hv[1][8]; ZERON8(hv,1);
    gemv8<64,1>(gP_tb + (size_t)l*64*128 + j, 128, sC+moff, hv);

    float gb_=gateb[l*128+j];
    #pragma unroll
    for (int mi=0;mi<8;mi++)
        g_a[(size_t)(a0+moff+mi)*128+j]=anew[mi]+sigf(ga[0][mi]+gb_)*hv[0][mi];
}

// K8: atom_out = relu(a @ W_tok^T) -> g_qkv (reuse)
__global__ void __launch_bounds__(256) k_tokproj()
{
    __shared__ __align__(16) float sA[128*SMS];
    int tid=threadIdx.x, j=tid&127, moff=(tid>>7)*8;
    int a0=blockIdx.x*MB;
    for (int idx=tid; idx<128*MB; idx+=256){
        int m=idx>>7,k=idx&127;
        sA[k*SMS+m]=g_a[(size_t)(a0+m)*128+k];
    }
    __syncthreads();
    float q3[3][8]; ZERON8(q3,3);
    gemv8<32,3>(gP_tok + j, 384, sA+moff, q3);
    #pragma unroll
    for (int mi=0;mi<8;mi++){
        size_t b=(size_t)(a0+moff+mi)*384;
        g_qkv[b+j]    =fmaxf(q3[0][mi],0.f);
        g_qkv[b+128+j]=fmaxf(q3[1][mi],0.f);
        g_qkv[b+256+j]=fmaxf(q3[2][mi],0.f);
    }
}

// K9: deterministic segment mean
__global__ void __launch_bounds__(128) k_tokmean(const int* __restrict__ a2t)
{
    __shared__ int slo,shi;
    int t=blockIdx.x;
    if (threadIdx.x==0){
        int lo=0,hi=NATOMS;
        while(lo<hi){int mid=(lo+hi)>>1; if(a2t[mid]<t) lo=mid+1; else hi=mid;}
        slo=lo; int lo2=lo; hi=NATOMS;
        while(lo2<hi){int mid=(lo2+hi)>>1; if(a2t[mid]<t+1) lo2=mid+1; else hi=mid;}
        shi=lo2;
    }
    __syncthreads();
    int lo=slo,hi=shi;
    float inv=1.0f/fmaxf((float)(hi-lo),1.0f);
    #pragma unroll
    for (int s=0;s<3;s++){
        int d=s*128+threadIdx.x;
        float sum=0;
        for (int a=lo;a<hi;a++) sum+=g_qkv[(size_t)a*384+d];
        g_tok[(size_t)t*384+d]=sum*inv;
    }
}

// K10: s_trunk, s_struct -> d_out ; u -> g_u
__global__ void __launch_bounds__(256) k_trunkstruct(float* __restrict__ out)
{
    __shared__ __align__(16) float sT[384*SMS];
    int tid=threadIdx.x, j=tid&127, moff=(tid>>7)*8;
    int t0=blockIdx.x*MB;
    for (int idx=tid; idx<384*MB; idx+=256){
        int m=idx/384, k=idx%384;
        sT[k*SMS+m]=g_tok[(size_t)(t0+m)*384+k];
    }
    __syncthreads();
    {
        float c3[3][8]; ZERON8(c3,3);
        gemv8<96,3>(gP_trunk + j, 384, sT+moff, c3);
        #pragma unroll
        for (int mi=0;mi<8;mi++){
            size_t b=(size_t)(t0+moff+mi)*384;
            out[b+j]=c3[0][mi]; out[b+128+j]=c3[1][mi]; out[b+256+j]=c3[2][mi];
        }
    }
    {
        float* o2 = out + (size_t)NTOK*384;
        float c3[3][8]; ZERON8(c3,3);
        gemv8<96,3>(gP_struc + j, 384, sT+moff, c3);
        #pragma unroll
        for (int mi=0;mi<8;mi++){
            size_t b=(size_t)(t0+moff+mi)*384;
            o2[b+j]=c3[0][mi]; o2[b+128+j]=c3[1][mi]; o2[b+256+j]=c3[2][mi];
        }
    }
    {
        float c2[2][8]; ZERON8(c2,2);
        gemv8<96,2>(gP_outer + j, 256, sT+moff, c2);
        #pragma unroll
        for (int mi=0;mi<8;mi++){
            size_t b=(size_t)(t0+moff+mi)*256;
            g_u[b+j]=c2[0][mi]; g_u[b+128+j]=c2[1][mi];
        }
    }
}

// K11: pair epilogue
__global__ void __launch_bounds__(128) k_pair(const float* __restrict__ tpf,
                                              float* __restrict__ outp)
{
    __shared__ __align__(16) float tj[8*32];
    int i=blockIdx.x, c=threadIdx.x;
    float4 w[8];
    #pragma unroll
    for (int k4=0;k4<8;k4++) w[k4]=gP_pairin[k4*128+c];
    float uiv=g_u[(size_t)i*256+c];
    for (int j0=0;j0<NTOK;j0+=8){
        __syncthreads();
        for (int idx=c; idx<256; idx+=128)
            tj[idx]=tpf[((size_t)i*NTOK+j0)*32 + idx];
        __syncthreads();
        #pragma unroll
        for (int jj=0;jj<8;jj++){
            int j=j0+jj;
            float a=uiv+g_u[(size_t)j*256+128+c];
            const float4* tp=(const float4*)&tj[jj*32];
            #pragma unroll
            for (int k4=0;k4<8;k4++){
                float4 t4=tp[k4];
                a += w[k4].x*t4.x + w[k4].y*t4.y + w[k4].z*t4.z + w[k4].w*t4.w;
            }
            outp[((size_t)i*NTOK+j)*128+c]=a;
        }
    }
}

extern "C" void kernel_launch(void* const* d_in, const int* in_sizes, int n_in,
                              void* d_out, int out_size)
{
    const float* af      = (const float*)d_in[0];
    const float* tpf     = (const float*)d_in[1];
    const float* W_cond  = (const float*)d_in[2];
    const float* W_ph    = (const float*)d_in[3];
    const float* W_pw    = (const float*)d_in[4];
    const float* W_mlp1  = (const float*)d_in[5];
    const float* W_mlp2  = (const float*)d_in[6];
    const float* pb_ln_w = (const float*)d_in[7];
    const float* pb_ln_b = (const float*)d_in[8];
    const float* pb_w    = (const float*)d_in[9];
    const float* sln_w   = (const float*)d_in[10];
    const float* qkv_w   = (const float*)d_in[11];
    const float* q_bias  = (const float*)d_in[12];
    const float* out_w   = (const float*)d_in[13];
    const float* out_b   = (const float*)d_in[14];
    const float* ada_w   = (const float*)d_in[15];
    const float* ta_w    = (const float*)d_in[16];
    const float* tb_w    = (const float*)d_in[17];
    const float* gate_w  = (const float*)d_in[18];
    const float* gate_b  = (const float*)d_in[19];
    const float* W_tok   = (const float*)d_in[20];
    const float* W_trunk = (const float*)d_in[21];
    const float* W_struct= (const float*)d_in[22];
    const float* W_pairin= (const float*)d_in[23];
    const float* W_outer = (const float*)d_in[24];
    const int*   a2t     = (const int*)d_in[28];
    float* out = (float*)d_out;

    PackArgs pa;
    void* p;
    #define SETP(i,sym,srcp,OUTv,Kv,Lv,DOUTv,JOFFv) \
        cudaGetSymbolAddress(&p, sym); \
        pa.d[i] = PackDesc{ srcp, (float*)p, OUTv, Kv, Lv, DOUTv, JOFFv };
    SETP(0,  gP_cond,   W_cond,   128,128,1, 128,0);
    SETP(1,  gP_ph,     W_ph,      16,128,1,  16,0);
    SETP(2,  gP_pw,     W_pw,      16,128,1,  16,0);
    SETP(3,  gP_out,    out_w,    128,128,3, 128,0);
    SETP(4,  gP_ga,     gate_w,   128,128,3, 384,0);
    SETP(5,  gP_ga,     ada_w,    256,128,3, 384,128);
    SETP(6,  gP_ta,     ta_w,     512,128,3, 512,0);
    SETP(7,  gP_tb,     tb_w,     128,256,3, 128,0);
    SETP(8,  gP_tok,    W_tok,    384,128,1, 384,0);
    SETP(9,  gP_trunk,  W_trunk,  384,384,1, 384,0);
    SETP(10, gP_struc,  W_struct, 384,384,1, 384,0);
    SETP(11, gP_pairin, W_pairin, 128, 32,1, 128,0);
    SETP(12, gP_outer,  W_outer,  256,384,1, 256,0);
    #undef SETP

    void *pm_sln, *pm_qkv;
    cudaGetSymbolAddress(&pm_sln, gPM_sln);
    cudaGetSymbolAddress(&pm_qkv, gPM_qkv);

    const int NBLK = NATOMS/MB;              // 736
    const int ATTN_SMEM = (4224+1152+4224+4608)*4;  // 56832 B
    cudaFuncSetAttribute(k_attn, cudaFuncAttributeMaxDynamicSharedMemorySize, ATTN_SMEM);

    // stageA(l=0) is launch #6 (profiler samples #6 with -s 5 -c 1).
    k_pack<<<dim3(96,13),256>>>(pa);                                  // 1
    k_packmma<<<192,256>>>(sln_w, (float4*)pm_sln, 256,128,3);        // 2
    k_packmma<<<288,256>>>(qkv_w, (float4*)pm_qkv, 384,128,3);        // 3
    k_cond<<<NBLK,256>>>(af);                                         // 4
    k_phpw<<<NATOMS/16 + NB*128/16,256>>>();                          // 5
    k_stageA<<<NBLK,256>>>(q_bias,0);                                 // 6  <-- profiled
    k_pb  <<<NB*32,128>>>(W_mlp1,W_mlp2,pb_ln_w,pb_ln_b,pb_w);        // 7

    for (int l=0;l<NL;l++){
        if (l>0) k_stageA<<<NBLK,256>>>(q_bias,l);
        k_attn  <<<NB*4,128,ATTN_SMEM>>>();
        k_stageC<<<NBLK,256>>>(out_b,gate_b,l);
    }

    k_tokproj<<<NBLK,256>>>();
    k_tokmean<<<NTOK,128>>>(a2t);
    k_trunkstruct<<<NTOK/MB,256>>>(out);
    k_pair<<<NTOK,128>>>(tpf, out + (size_t)2*NTOK*384);
}

// round 12
// speedup vs baseline: 1.4241x; 1.1408x over previous
#include <cuda_runtime.h>

#define NATOMS 11776
#define NB     368
#define NTOK   512
#define NL     3
#define MB     16
#define SMS    20

// ---- scratch ----
__device__ float g_sln[NATOMS*128];
__device__ float g_a  [NATOMS*128];
__device__ float g_qkv[NATOMS*384];
__device__ float g_o  [NATOMS*128];
__device__ float g_ph [NATOMS*16];
__device__ float g_pw [NB*128*16];
__device__ float g_pb [NB*4*32*128];
__device__ float g_tok[NTOK*384];
__device__ float g_u  [NTOK*256];

// ---- FFMA packed weights ----
__device__ float4 gP_cond [32*128];
__device__ float4 gP_ph   [32*16];
__device__ float4 gP_pw   [32*16];
__device__ float4 gP_tok  [32*384];
__device__ float4 gP_trunk[96*384];
__device__ float4 gP_struc[96*384];
__device__ float4 gP_pairin[8*128];
__device__ float4 gP_outer[96*256];

// ---- mma fragment-packed weights (tf32 hi/lo) ----
__device__ float4 gPM_sln[NL*16*32*32];
__device__ float4 gPM_qkv[NL*16*48*32];
__device__ float4 gPM_out[NL*16*16*32];
__device__ float4 gPM_ga [NL*16*48*32];   // gate tiles 0-15, ada tiles 16-47
__device__ float4 gPM_ta [NL*16*64*32];
__device__ float4 gPM_tb [NL*32*16*32];   // K=256

__device__ __forceinline__ float sigf(float x){ return 1.0f/(1.0f+__expf(-x)); }
__device__ __forceinline__ unsigned int f2tf32u(float x){
    unsigned int r; asm("cvt.rna.tf32.f32 %0, %1;" : "=r"(r) : "f"(x)); return r;
}
#define MMA8(cc,A0,A1,A2,A3,B0,B1) \
  asm volatile("mma.sync.aligned.m16n8k8.row.col.f32.tf32.tf32.f32 " \
    "{%0,%1,%2,%3},{%4,%5,%6,%7},{%8,%9},{%0,%1,%2,%3};" \
    : "+f"(cc[0]),"+f"(cc[1]),"+f"(cc[2]),"+f"(cc[3]) \
    : "r"(A0),"r"(A1),"r"(A2),"r"(A3),"r"(B0),"r"(B1));

#define ZERO8(a) { _Pragma("unroll") for(int _m=0;_m<8;_m++) a[_m]=0.f; }
#define ZERON8(a,N) { _Pragma("unroll") for(int _n=0;_n<(N);_n++) ZERO8(a[_n]); }
#define HILO_STORE(Hq,Lq,addr,val) { unsigned int _hb=f2tf32u(val); \
    (Hq)[addr]=__uint_as_float(_hb); \
    (Lq)[addr]=__uint_as_float(f2tf32u((val)-__uint_as_float(_hb))); }

// FFMA register-blocked GEMV
template<int K4, int NC, int COFF=128>
__device__ __forceinline__ void gemv8(const float4* __restrict__ Wb, int out4,
                                      const float* __restrict__ sXm, float (*acc)[8])
{
    #pragma unroll 2
    for (int k4=0;k4<K4;k4++){
        float4 w[NC];
        #pragma unroll
        for (int n=0;n<NC;n++) w[n]=Wb[k4*out4 + n*COFF];
        const float* xb = sXm + (k4<<2)*SMS;
        #pragma unroll
        for (int c=0;c<4;c++){
            const float4* _p=(const float4*)(xb + c*SMS);
            float4 x0=_p[0], x1=_p[1];
            #pragma unroll
            for (int n=0;n<NC;n++){
                float wc=(c==0)?w[n].x:(c==1)?w[n].y:(c==2)?w[n].z:w[n].w;
                acc[n][0]+=x0.x*wc; acc[n][1]+=x0.y*wc; acc[n][2]+=x0.z*wc; acc[n][3]+=x0.w*wc;
                acc[n][4]+=x1.x*wc; acc[n][5]+=x1.y*wc; acc[n][6]+=x1.z*wc; acc[n][7]+=x1.w*wc;
            }
        }
    }
}

// per-atom mean/rstd, 16 atoms, 256 threads (FFMA kernels)
__device__ __forceinline__ void rowstats256(const float v[8], int moff, float* stage,
                                            float mu[8], float rs[8])
{
    const int tid=threadIdx.x, j=tid&127;
    for (int pass=0; pass<2; pass++){
        __syncthreads();
        #pragma unroll
        for (int mi=0;mi<8;mi++){
            float x=(pass==0)? v[mi] : (v[mi]-mu[mi]);
            stage[(moff+mi)*132 + j] = (pass==0)? x : x*x;
        }
        __syncthreads();
        { int row=tid>>4, seg=tid&15;
          float s=0;
          #pragma unroll
          for (int u=0;u<8;u++) s+=stage[row*132 + seg*8 + u];
          stage[2112+tid]=s; }
        __syncthreads();
        if (tid<16){ float t2=0;
          #pragma unroll
          for (int u=0;u<16;u++) t2+=stage[2112+tid*16+u];
          stage[2368+tid]=t2*(1.0f/128.0f); }
        __syncthreads();
        if (pass==0){
            #pragma unroll
            for (int mi=0;mi<8;mi++) mu[mi]=stage[2368+moff+mi];
        } else {
            #pragma unroll
            for (int mi=0;mi<8;mi++) rs[mi]=rsqrtf(stage[2368+moff+mi]+1e-5f);
        }
    }
    __syncthreads();
}

// ---- unified packer: y<8 FFMA, y>=8 mma-fragment ----
struct PackDesc  { const float* src; float* dst;  int OUT; int K; int L; int dstOut; int joff; };
struct PackMDesc { const float* src; float4* dst; int OUT; int K; int L; int dstNT; int ntoff; };
struct PackArgs  { PackDesc d[8]; PackMDesc m[7]; };
__global__ void k_packall(PackArgs pa)
{
    int y = blockIdx.y;
    if (y < 8){
        PackDesc pd = pa.d[y];
        int total = pd.L*pd.OUT*pd.K;
        int K4 = pd.K>>2;
        for (int idx = blockIdx.x*256 + threadIdx.x; idx < total; idx += gridDim.x*256){
            int c = idx&3; int t = idx>>2;
            int j = t % pd.OUT; int q = t / pd.OUT;
            int k4 = q % K4;    int l = q / K4;
            size_t daddr = (((size_t)l*K4 + k4)*pd.dstOut + pd.joff + j)*4 + c;
            pd.dst[daddr] = pd.src[((size_t)l*pd.OUT + j)*pd.K + k4*4 + c];
        }
    } else {
        PackMDesc pm = pa.m[y-8];
        int K8=pm.K>>3, NT=pm.OUT>>3;
        int total=pm.L*K8*NT*32;
        for (int idx=blockIdx.x*256+threadIdx.x; idx<total; idx+=gridDim.x*256){
            int lane=idx&31; int t=idx>>5;
            int nt=t%NT; int t2=t/NT; int k4=t2%K8; int l=t2/K8;
            int n=nt*8+(lane>>2), k=k4*8+(lane&3);
            float w0=pm.src[((size_t)l*pm.OUT+n)*pm.K+k];
            float w1=pm.src[((size_t)l*pm.OUT+n)*pm.K+k+4];
            unsigned int h0=f2tf32u(w0), h1=f2tf32u(w1);
            float l0=w0-__uint_as_float(h0), l1=w1-__uint_as_float(h1);
            pm.dst[(((size_t)l*K8+k4)*pm.dstNT + pm.ntoff + nt)*32 + lane] =
                make_float4(__uint_as_float(h0),__uint_as_float(h1),
                            __uint_as_float(f2tf32u(l0)),__uint_as_float(f2tf32u(l1)));
        }
    }
}

// K1: c = af@Wcond^T ; a=c ; s_ln=LN(c)   (FFMA)
__global__ void __launch_bounds__(256) k_cond(const float* __restrict__ af)
{
    __shared__ __align__(16) float sA[128*SMS];
    int tid=threadIdx.x, j=tid&127, moff=(tid>>7)*8;
    int a0 = blockIdx.x*MB;
    for (int idx=tid; idx<128*MB; idx+=256){
        int m=idx>>7, k=idx&127;
        sA[k*SMS+m] = af[(size_t)(a0+m)*128 + k];
    }
    __syncthreads();
    float acc[1][8]; ZERON8(acc,1);
    gemv8<32,1>(gP_cond + j, 128, sA+moff, acc);
    #pragma unroll
    for (int mi=0;mi<8;mi++) g_a[(size_t)(a0+moff+mi)*128+j]=acc[0][mi];
    float mu[8], rs[8];
    rowstats256(acc[0], moff, sA, mu, rs);
    #pragma unroll
    for (int mi=0;mi<8;mi++) g_sln[(size_t)(a0+moff+mi)*128+j]=(acc[0][mi]-mu[mi])*rs[mi];
}

// K2: fused ph / pw
__global__ void __launch_bounds__(256) k_phpw()
{
    __shared__ float xs[16*132];
    int tid=threadIdx.x;
    bool isph = blockIdx.x < (NATOMS/16);
    int r0 = isph ? blockIdx.x*16 : (blockIdx.x-(NATOMS/16))*16;
    for (int idx=tid; idx<16*128; idx+=256){
        int r=idx>>7,k=idx&127;
        int row=r0+r;
        int atom;
        if (isph) atom=row;
        else { int nb=row>>7, kk=row&127; atom=nb*32+kk-48; atom=max(0,min(atom,NATOMS-1)); }
        xs[r*132+k]=fmaxf(g_sln[(size_t)atom*128+k],0.f);
    }
    __syncthreads();
    int o=tid&15, r=tid>>4;
    const float4* W = isph ? gP_ph : gP_pw;
    float acc=0;
    #pragma unroll 4
    for (int k4=0;k4<32;k4++){
        float4 w = W[k4*16+o];
        const float* xb=&xs[r*132+k4*4];
        acc += xb[0]*w.x+xb[1]*w.y+xb[2]*w.z+xb[3]*w.w;
    }
    if (isph) g_ph[(size_t)(r0+r)*16+o]=acc;
    else      g_pw[(size_t)(r0+r)*16+o]=acc;
}

// K3: pair bias
__global__ void __launch_bounds__(128) k_pb(const float* __restrict__ W1g,
                                            const float* __restrict__ W2g,
                                            const float* __restrict__ lnw,
                                            const float* __restrict__ lnb,
                                            const float* __restrict__ pbw)
{
    __shared__ float W1[256], W2[256], PBW[64], LW[16], LB[16], PH[16];
    int tid=threadIdx.x;
    int blk=blockIdx.x; int nb=blk>>5, q=blk&31;
    for (int idx=tid; idx<256; idx+=128){ W1[idx]=W1g[idx]; W2[idx]=W2g[idx]; }
    if (tid<64) PBW[tid]=pbw[tid];
    if (tid<16){ LW[tid]=lnw[tid]; LB[tid]=lnb[tid];
                 PH[tid]=g_ph[(size_t)(nb*32+q)*16+tid]; }
    __syncthreads();

    float p[16];
    { const float4* pwp=(const float4*)&g_pw[(size_t)(nb*128+tid)*16];
      float4 a=pwp[0],b=pwp[1],c=pwp[2],d=pwp[3];
      p[0]=a.x;p[1]=a.y;p[2]=a.z;p[3]=a.w; p[4]=b.x;p[5]=b.y;p[6]=b.z;p[7]=b.w;
      p[8]=c.x;p[9]=c.y;p[10]=c.z;p[11]=c.w; p[12]=d.x;p[13]=d.y;p[14]=d.z;p[15]=d.w; }
    #pragma unroll
    for (int i=0;i<16;i++) p[i]+=PH[i];

    float t[16], u[16];
    #pragma unroll
    for (int i=0;i<16;i++) t[i]=fmaxf(p[i],0.f);
    #pragma unroll
    for (int o=0;o<16;o++){
        float s=0;
        #pragma unroll
        for (int i=0;i<16;i++) s+=t[i]*W1[o*16+i];
        u[o]=fmaxf(s,0.f);
    }
    #pragma unroll
    for (int o=0;o<16;o++){
        float s=0;
        #pragma unroll
        for (int i=0;i<16;i++) s+=u[i]*W2[o*16+i];
        p[o]+=s;
    }
    float mu=0;
    #pragma unroll
    for (int i=0;i<16;i++) mu+=p[i];
    mu*=(1.0f/16.0f);
    float var=0;
    #pragma unroll
    for (int i=0;i<16;i++){ float d=p[i]-mu; var+=d*d; }
    float rsd=rsqrtf(var*(1.0f/16.0f)+1e-5f);
    float y[16];
    #pragma unroll
    for (int i=0;i<16;i++) y[i]=(p[i]-mu)*rsd*LW[i]+LB[i];

    int win = nb*32 + tid - 48;
    float neg = (win>=0 && win<NATOMS) ? 0.f : -1.0e9f;
    #pragma unroll
    for (int h=0;h<4;h++){
        float s=0;
        #pragma unroll
        for (int i=0;i<16;i++) s+=y[i]*PBW[h*16+i];
        g_pb[(size_t)((nb*4+h)*32+q)*128+tid]=s+neg;
    }
}

// K4: per-layer stage A — TF32x3 mma (validated R10)
__global__ void __launch_bounds__(256) k_stageA(const float* __restrict__ qbias, int l)
{
    __shared__ __align__(16) float sHi[16*132];
    __shared__ __align__(16) float sLo[16*132];
    __shared__ __align__(16) float sLn[16*132];
    __shared__ float sMu[16], sRs[16];
    int tid=threadIdx.x, lane=tid&31, wp=tid>>5;
    int g=lane>>2, tig=lane&3;
    int a0=blockIdx.x*MB;

    for (int i=tid;i<512;i+=256){
        int m=i>>5, kq=(i&31)*4;
        float4 v=*(const float4*)&g_sln[(size_t)(a0+m)*128+kq];
        float xs4[4]={v.x,v.y,v.z,v.w};
        #pragma unroll
        for(int e=0;e<4;e++) HILO_STORE(sHi,sLo,m*132+kq+e,xs4[e]);
        float4 av=*(const float4*)&g_a[(size_t)(a0+m)*128+kq];
        *(float4*)&sLn[m*132+kq]=av;
    }
    __syncthreads();
    {
        int r=2*wp+(lane>>4), c0=(lane&15)*8;
        float s=0.f,s2=0.f;
        #pragma unroll
        for(int u=0;u<8;u++){ float x=sLn[r*132+c0+u]; s+=x; s2+=x*x; }
        #pragma unroll
        for(int d=1;d<16;d<<=1){ s+=__shfl_xor_sync(0xffffffffu,s,d); s2+=__shfl_xor_sync(0xffffffffu,s2,d); }
        if((lane&15)==0){ float m_=s*(1.f/128.f), e2=s2*(1.f/128.f);
            sMu[r]=m_; sRs[r]=rsqrtf(e2-m_*m_+1e-5f); }
    }
    __syncthreads();
    {
        int r=2*wp+(lane>>4), c0=(lane&15)*8;
        float m_=sMu[r], rs_=sRs[r];
        #pragma unroll
        for(int u=0;u<8;u++) sLn[r*132+c0+u]=(sLn[r*132+c0+u]-m_)*rs_;
    }
    __syncthreads();

    float c[4][4];
    #pragma unroll
    for(int t=0;t<4;t++){ c[t][0]=0;c[t][1]=0;c[t][2]=0;c[t][3]=0; }
    {
        const float4* B = gPM_sln + (size_t)l*16*32*32;
        #pragma unroll 2
        for (int k4=0;k4<16;k4++){
            int kb=k4*8;
            unsigned int ah0=__float_as_uint(sHi[g*132+kb+tig]);
            unsigned int ah1=__float_as_uint(sHi[(g+8)*132+kb+tig]);
            unsigned int ah2=__float_as_uint(sHi[g*132+kb+tig+4]);
            unsigned int ah3=__float_as_uint(sHi[(g+8)*132+kb+tig+4]);
            unsigned int al0=__float_as_uint(sLo[g*132+kb+tig]);
            unsigned int al1=__float_as_uint(sLo[(g+8)*132+kb+tig]);
            unsigned int al2=__float_as_uint(sLo[g*132+kb+tig+4]);
            unsigned int al3=__float_as_uint(sLo[(g+8)*132+kb+tig+4]);
            #pragma unroll
            for (int t=0;t<4;t++){
                int nt=(t<2)? (2*wp+t) : (2*wp+14+t);
                float4 b=B[((size_t)k4*32+nt)*32+lane];
                unsigned int bh0=__float_as_uint(b.x), bh1=__float_as_uint(b.y);
                unsigned int bl0=__float_as_uint(b.z), bl1=__float_as_uint(b.w);
                MMA8(c[t],ah0,ah1,ah2,ah3,bh0,bh1);
                MMA8(c[t],ah0,ah1,ah2,ah3,bl0,bl1);
                MMA8(c[t],al0,al1,al2,al3,bh0,bh1);
            }
        }
    }
    __syncthreads();
    #pragma unroll
    for (int i=0;i<2;i++){
        int nb=(2*wp+i)*8+2*tig;
        float x0=sigf(c[i][0])*sLn[g*132+nb]       + c[i+2][0];
        float x1=sigf(c[i][1])*sLn[g*132+nb+1]     + c[i+2][1];
        float x2=sigf(c[i][2])*sLn[(g+8)*132+nb]   + c[i+2][2];
        float x3=sigf(c[i][3])*sLn[(g+8)*132+nb+1] + c[i+2][3];
        HILO_STORE(sHi,sLo,g*132+nb,x0);
        HILO_STORE(sHi,sLo,g*132+nb+1,x1);
        HILO_STORE(sHi,sLo,(g+8)*132+nb,x2);
        HILO_STORE(sHi,sLo,(g+8)*132+nb+1,x3);
    }
    __syncthreads();

    float q[6][4];
    #pragma unroll
    for(int t=0;t<6;t++){ q[t][0]=0;q[t][1]=0;q[t][2]=0;q[t][3]=0; }
    {
        const float4* B = gPM_qkv + (size_t)l*16*48*32;
        #pragma unroll 2
        for (int k4=0;k4<16;k4++){
            int kb=k4*8;
            unsigned int ah0=__float_as_uint(sHi[g*132+kb+tig]);
            unsigned int ah1=__float_as_uint(sHi[(g+8)*132+kb+tig]);
            unsigned int ah2=__float_as_uint(sHi[g*132+kb+tig+4]);
            unsigned int ah3=__float_as_uint(sHi[(g+8)*132+kb+tig+4]);
            unsigned int al0=__float_as_uint(sLo[g*132+kb+tig]);
            unsigned int al1=__float_as_uint(sLo[(g+8)*132+kb+tig]);
            unsigned int al2=__float_as_uint(sLo[g*132+kb+tig+4]);
            unsigned int al3=__float_as_uint(sLo[(g+8)*132+kb+tig+4]);
            #pragma unroll
            for (int t=0;t<6;t++){
                int nt=6*wp+t;
                float4 b=B[((size_t)k4*48+nt)*32+lane];
                unsigned int bh0=__float_as_uint(b.x), bh1=__float_as_uint(b.y);
                unsigned int bl0=__float_as_uint(b.z), bl1=__float_as_uint(b.w);
                MMA8(q[t],ah0,ah1,ah2,ah3,bh0,bh1);
                MMA8(q[t],ah0,ah1,ah2,ah3,bl0,bl1);
                MMA8(q[t],al0,al1,al2,al3,bh0,bh1);
            }
        }
    }
    #pragma unroll
    for (int t=0;t<6;t++){
        int nb=(6*wp+t)*8+2*tig;
        float qb0=0.f, qb1=0.f;
        if (nb<128){ qb0=qbias[l*128+nb]; qb1=qbias[l*128+nb+1]; }
        g_qkv[(size_t)(a0+g)*384+nb]     = q[t][0]+qb0;
        g_qkv[(size_t)(a0+g)*384+nb+1]   = q[t][1]+qb1;
        g_qkv[(size_t)(a0+g+8)*384+nb]   = q[t][2]+qb0;
        g_qkv[(size_t)(a0+g+8)*384+nb+1] = q[t][3]+qb1;
    }
}

// K5: windowed attention per (nb, head)
__global__ void __launch_bounds__(128) k_attn()
{
    extern __shared__ float sm[];
    float* vb  = sm;
    float* qT  = vb + 4224;
    float* sc  = qT + 1152;
    float* scT = sc + 4224;
    int blk=blockIdx.x; int nb=blk>>2, h=blk&3;
    int tid=threadIdx.x;

    for (int idx=tid; idx<128*32; idx+=128){
        int kk=idx>>5, d=idx&31;
        int atom=nb*32+kk-48; atom=max(0,min(atom,NATOMS-1));
        vb[kk*33+d]=g_qkv[(size_t)atom*384+256+h*32+d];
    }
    for (int idx=tid; idx<1024; idx+=128){
        int d=idx>>5, qq=idx&31;
        qT[d*36+qq]=g_qkv[(size_t)(nb*32+qq)*384 + h*32 + d];
    }
    float kreg[32];
    {
        int atom=nb*32+tid-48; atom=max(0,min(atom,NATOMS-1));
        const float4* kr=(const float4*)&g_qkv[(size_t)atom*384+128+h*32];
        #pragma unroll
        for (int i=0;i<8;i++){
            float4 v=kr[i];
            kreg[i*4]=v.x; kreg[i*4+1]=v.y; kreg[i*4+2]=v.z; kreg[i*4+3]=v.w;
        }
    }
    __syncthreads();

    float acc[32];
    #pragma unroll
    for (int i=0;i<32;i++) acc[i]=0.f;
    #pragma unroll 4
    for (int d=0;d<32;d++){
        float kd=kreg[d];
        const float4* qp=(const float4*)&qT[d*36];
        #pragma unroll
        for (int r=0;r<8;r++){
            float4 q4=qp[r];
            acc[r*4]  +=q4.x*kd;
            acc[r*4+1]+=q4.y*kd;
            acc[r*4+2]+=q4.z*kd;
            acc[r*4+3]+=q4.w*kd;
        }
    }
    const float scale=0.1767766952966369f;
    const float* pbp=&g_pb[(size_t)((nb*4+h)*32)*128];
    #pragma unroll 4
    for (int qq=0;qq<32;qq++)
        sc[qq*129+tid]=acc[qq]*scale + pbp[(size_t)qq*128+tid];
    __syncthreads();

    {
        int qq2=tid>>2, sub=tid&3;
        float mx=-1e30f;
        #pragma unroll 4
        for (int i=0;i<32;i++) mx=fmaxf(mx, sc[qq2*129+sub+4*i]);
        mx=fmaxf(mx,__shfl_xor_sync(0xffffffffu,mx,1));
        mx=fmaxf(mx,__shfl_xor_sync(0xffffffffu,mx,2));
        float s=0;
        #pragma unroll 4
        for (int i=0;i<32;i++){
            int id=qq2*129+sub+4*i;
            float e=__expf(sc[id]-mx); sc[id]=e; s+=e;
        }
        s+=__shfl_xor_sync(0xffffffffu,s,1);
        s+=__shfl_xor_sync(0xffffffffu,s,2);
        float inv=1.0f/s;
        #pragma unroll 4
        for (int i=0;i<32;i++) sc[qq2*129+sub+4*i]*=inv;
    }
    __syncthreads();

    for (int idx=tid; idx<4096; idx+=128){
        int qq=idx&31, kk=idx>>5;
        scT[kk*36+qq]=sc[qq*129+kk];
    }
    __syncthreads();

    #pragma unroll
    for (int i=0;i<32;i++) acc[i]=0.f;
    int d=tid&31, kg=tid>>5;
    #pragma unroll 4
    for (int ki=0;ki<32;ki++){
        int k=kg*32+ki;
        float v=vb[k*33+d];
        const float4* sp=(const float4*)&scT[k*36];
        #pragma unroll
        for (int r=0;r<8;r++){
            float4 s4=sp[r];
            acc[r*4]  +=s4.x*v;
            acc[r*4+1]+=s4.y*v;
            acc[r*4+2]+=s4.z*v;
            acc[r*4+3]+=s4.w*v;
        }
    }
    float* red = sc;
    #pragma unroll
    for (int qq=0;qq<32;qq++) red[kg*1056+qq*33+d]=acc[qq];
    __syncthreads();
    for (int idx=tid; idx<1024; idx+=128){
        int qq=idx>>5, dd=idx&31;
        float s=red[qq*33+dd]+red[1056+qq*33+dd]+red[2112+qq*33+dd]+red[3168+qq*33+dd];
        g_o[(size_t)(nb*32+qq)*128 + h*32 + dd]=s;
    }
}

// K7: per-layer stage C — TF32x3 mma (256 threads = 8 warps, 16 atoms)
__global__ void __launch_bounds__(256) k_stageC(const float* __restrict__ outb,
                                                const float* __restrict__ gateb, int l)
{
    extern __shared__ __align__(16) float smc[];
    float* sHi = smc;              // 2112
    float* sLo = sHi + 2112;       // 2112
    float* sGhi= sLo + 2112;       // 4224 (16x264)
    float* sGlo= sGhi + 4224;      // 4224
    float* sRaw= sGlo + 4224;      // 2112
    __shared__ float sMu[16], sRs[16];
    int tid=threadIdx.x, lane=tid&31, wp=tid>>5;
    int g=lane>>2, tig=tid&3;
    tig=lane&3;
    int a0=blockIdx.x*MB;

    // phase 1: o tile -> sHi/sLo ; out mma -> co
    for (int i=tid;i<512;i+=256){
        int m=i>>5, kq=(i&31)*4;
        float4 v=*(const float4*)&g_o[(size_t)(a0+m)*128+kq];
        float xs4[4]={v.x,v.y,v.z,v.w};
        #pragma unroll
        for(int e=0;e<4;e++) HILO_STORE(sHi,sLo,m*132+kq+e,xs4[e]);
    }
    __syncthreads();
    float co[2][4];
    #pragma unroll
    for(int t=0;t<2;t++){ co[t][0]=0;co[t][1]=0;co[t][2]=0;co[t][3]=0; }
    {
        const float4* B = gPM_out + (size_t)l*16*16*32;
        #pragma unroll 2
        for (int k4=0;k4<16;k4++){
            int kb=k4*8;
            unsigned int ah0=__float_as_uint(sHi[g*132+kb+tig]);
            unsigned int ah1=__float_as_uint(sHi[(g+8)*132+kb+tig]);
            unsigned int ah2=__float_as_uint(sHi[g*132+kb+tig+4]);
            unsigned int ah3=__float_as_uint(sHi[(g+8)*132+kb+tig+4]);
            unsigned int al0=__float_as_uint(sLo[g*132+kb+tig]);
            unsigned int al1=__float_as_uint(sLo[(g+8)*132+kb+tig]);
            unsigned int al2=__float_as_uint(sLo[g*132+kb+tig+4]);
            unsigned int al3=__float_as_uint(sLo[(g+8)*132+kb+tig+4]);
            #pragma unroll
            for (int t=0;t<2;t++){
                int nt=2*wp+t;
                float4 b=B[((size_t)k4*16+nt)*32+lane];
                unsigned int bh0=__float_as_uint(b.x), bh1=__float_as_uint(b.y);
                unsigned int bl0=__float_as_uint(b.z), bl1=__float_as_uint(b.w);
                MMA8(co[t],ah0,ah1,ah2,ah3,bh0,bh1);
                MMA8(co[t],ah0,ah1,ah2,ah3,bl0,bl1);
                MMA8(co[t],al0,al1,al2,al3,bh0,bh1);
            }
        }
    }
    __syncthreads();

    // phase 2: s_ln tile -> sHi/sLo ; ga mma -> cga (gate, adaLo, adaHi aligned)
    for (int i=tid;i<512;i+=256){
        int m=i>>5, kq=(i&31)*4;
        float4 v=*(const float4*)&g_sln[(size_t)(a0+m)*128+kq];
        float xs4[4]={v.x,v.y,v.z,v.w};
        #pragma unroll
        for(int e=0;e<4;e++) HILO_STORE(sHi,sLo,m*132+kq+e,xs4[e]);
    }
    __syncthreads();
    float cga[6][4];
    #pragma unroll
    for(int t=0;t<6;t++){ cga[t][0]=0;cga[t][1]=0;cga[t][2]=0;cga[t][3]=0; }
    {
        const float4* B = gPM_ga + (size_t)l*16*48*32;
        #pragma unroll 2
        for (int k4=0;k4<16;k4++){
            int kb=k4*8;
            unsigned int ah0=__float_as_uint(sHi[g*132+kb+tig]);
            unsigned int ah1=__float_as_uint(sHi[(g+8)*132+kb+tig]);
            unsigned int ah2=__float_as_uint(sHi[g*132+kb+tig+4]);
            unsigned int ah3=__float_as_uint(sHi[(g+8)*132+kb+tig+4]);
            unsigned int al0=__float_as_uint(sLo[g*132+kb+tig]);
            unsigned int al1=__float_as_uint(sLo[(g+8)*132+kb+tig]);
            unsigned int al2=__float_as_uint(sLo[g*132+kb+tig+4]);
            unsigned int al3=__float_as_uint(sLo[(g+8)*132+kb+tig+4]);
            #pragma unroll
            for (int t=0;t<6;t++){
                int nt = (t<2)? (2*wp+t) : (t<4)? (16+2*wp+t-2) : (32+2*wp+t-4);
                float4 b=B[((size_t)k4*48+nt)*32+lane];
                unsigned int bh0=__float_as_uint(b.x), bh1=__float_as_uint(b.y);
                unsigned int bl0=__float_as_uint(b.z), bl1=__float_as_uint(b.w);
                MMA8(cga[t],ah0,ah1,ah2,ah3,bh0,bh1);
                MMA8(cga[t],ah0,ah1,ah2,ah3,bl0,bl1);
                MMA8(cga[t],al0,al1,al2,al3,bh0,bh1);
            }
        }
    }

    // anew at frag coords; stage to sRaw for LN
    float anew[2][4];
    #pragma unroll
    for (int i=0;i<2;i++){
        int nb=(2*wp+i)*8+2*tig;
        float ob0=outb[l*128+nb], ob1=outb[l*128+nb+1];
        anew[i][0]=g_a[(size_t)(a0+g)*128+nb]    +co[i][0]+ob0;
        anew[i][1]=g_a[(size_t)(a0+g)*128+nb+1]  +co[i][1]+ob1;
        anew[i][2]=g_a[(size_t)(a0+g+8)*128+nb]  +co[i][2]+ob0;
        anew[i][3]=g_a[(size_t)(a0+g+8)*128+nb+1]+co[i][3]+ob1;
        sRaw[g*132+nb]=anew[i][0];     sRaw[g*132+nb+1]=anew[i][1];
        sRaw[(g+8)*132+nb]=anew[i][2]; sRaw[(g+8)*132+nb+1]=anew[i][3];
    }
    __syncthreads();
    {
        int r=2*wp+(lane>>4), c0=(lane&15)*8;
        float s=0.f,s2=0.f;
        #pragma unroll
        for(int u=0;u<8;u++){ float x=sRaw[r*132+c0+u]; s+=x; s2+=x*x; }
        #pragma unroll
        for(int d=1;d<16;d<<=1){ s+=__shfl_xor_sync(0xffffffffu,s,d); s2+=__shfl_xor_sync(0xffffffffu,s2,d); }
        if((lane&15)==0){ float m_=s*(1.f/128.f), e2=s2*(1.f/128.f);
            sMu[r]=m_; sRs[r]=rsqrtf(e2-m_*m_+1e-5f); }
    }
    __syncthreads();

    // xt -> sHi/sLo (overwrite s_ln tile)
    #pragma unroll
    for (int i=0;i<2;i++){
        int nb=(2*wp+i)*8+2*tig;
        float mg0=sMu[g], rg0=sRs[g], mg8=sMu[g+8], rg8=sRs[g+8];
        float x0=sigf(cga[2+i][0])*((anew[i][0]-mg0)*rg0)+cga[4+i][0];
        float x1=sigf(cga[2+i][1])*((anew[i][1]-mg0)*rg0)+cga[4+i][1];
        float x2=sigf(cga[2+i][2])*((anew[i][2]-mg8)*rg8)+cga[4+i][2];
        float x3=sigf(cga[2+i][3])*((anew[i][3]-mg8)*rg8)+cga[4+i][3];
        HILO_STORE(sHi,sLo,g*132+nb,x0);
        HILO_STORE(sHi,sLo,g*132+nb+1,x1);
        HILO_STORE(sHi,sLo,(g+8)*132+nb,x2);
        HILO_STORE(sHi,sLo,(g+8)*132+nb+1,x3);
    }
    __syncthreads();

    // ta mma: ct[8][4] (lo tiles 4w+i, hi tiles 32+4w+i)
    float ct[8][4];
    #pragma unroll
    for(int t=0;t<8;t++){ ct[t][0]=0;ct[t][1]=0;ct[t][2]=0;ct[t][3]=0; }
    {
        const float4* B = gPM_ta + (size_t)l*16*64*32;
        #pragma unroll 2
        for (int k4=0;k4<16;k4++){
            int kb=k4*8;
            unsigned int ah0=__float_as_uint(sHi[g*132+kb+tig]);
            unsigned int ah1=__float_as_uint(sHi[(g+8)*132+kb+tig]);
            unsigned int ah2=__float_as_uint(sHi[g*132+kb+tig+4]);
            unsigned int ah3=__float_as_uint(sHi[(g+8)*132+kb+tig+4]);
            unsigned int al0=__float_as_uint(sLo[g*132+kb+tig]);
            unsigned int al1=__float_as_uint(sLo[(g+8)*132+kb+tig]);
            unsigned int al2=__float_as_uint(sLo[g*132+kb+tig+4]);
            unsigned int al3=__float_as_uint(sLo[(g+8)*132+kb+tig+4]);
            #pragma unroll
            for (int t=0;t<8;t++){
                int nt=(t<4)? (4*wp+t) : (32+4*wp+t-4);
                float4 b=B[((size_t)k4*64+nt)*32+lane];
                unsigned int bh0=__float_as_uint(b.x), bh1=__float_as_uint(b.y);
                unsigned int bl0=__float_as_uint(b.z), bl1=__float_as_uint(b.w);
                MMA8(ct[t],ah0,ah1,ah2,ah3,bh0,bh1);
                MMA8(ct[t],ah0,ah1,ah2,ah3,bl0,bl1);
                MMA8(ct[t],al0,al1,al2,al3,bh0,bh1);
            }
        }
    }
    // g = silu(lo)*hi -> sG tiles (16x264)
    #pragma unroll
    for (int i=0;i<4;i++){
        int nb=(4*wp+i)*8+2*tig;
        float g0=ct[i][0]*sigf(ct[i][0])*ct[4+i][0];
        float g1=ct[i][1]*sigf(ct[i][1])*ct[4+i][1];
        float g2=ct[i][2]*sigf(ct[i][2])*ct[4+i][2];
        float g3=ct[i][3]*sigf(ct[i][3])*ct[4+i][3];
        HILO_STORE(sGhi,sGlo,g*264+nb,g0);
        HILO_STORE(sGhi,sGlo,g*264+nb+1,g1);
        HILO_STORE(sGhi,sGlo,(g+8)*264+nb,g2);
        HILO_STORE(sGhi,sGlo,(g+8)*264+nb+1,g3);
    }
    __syncthreads();

    // tb mma: K=256 (K8=32), chv[2][4]
    float chv[2][4];
    #pragma unroll
    for(int t=0;t<2;t++){ chv[t][0]=0;chv[t][1]=0;chv[t][2]=0;chv[t][3]=0; }
    {
        const float4* B = gPM_tb + (size_t)l*32*16*32;
        #pragma unroll 2
        for (int k4=0;k4<32;k4++){
            int kb=k4*8;
            unsigned int ah0=__float_as_uint(sGhi[g*264+kb+tig]);
            unsigned int ah1=__float_as_uint(sGhi[(g+8)*264+kb+tig]);
            unsigned int ah2=__float_as_uint(sGhi[g*264+kb+tig+4]);
            unsigned int ah3=__float_as_uint(sGhi[(g+8)*264+kb+tig+4]);
            unsigned int al0=__float_as_uint(sGlo[g*264+kb+tig]);
            unsigned int al1=__float_as_uint(sGlo[(g+8)*264+kb+tig]);
            unsigned int al2=__float_as_uint(sGlo[g*264+kb+tig+4]);
            unsigned int al3=__float_as_uint(sGlo[(g+8)*264+kb+tig+4]);
            #pragma unroll
            for (int t=0;t<2;t++){
                int nt=2*wp+t;
                float4 b=B[((size_t)k4*16+nt)*32+lane];
                unsigned int bh0=__float_as_uint(b.x), bh1=__float_as_uint(b.y);
                unsigned int bl0=__float_as_uint(b.z), bl1=__float_as_uint(b.w);
                MMA8(chv[t],ah0,ah1,ah2,ah3,bh0,bh1);
                MMA8(chv[t],ah0,ah1,ah2,ah3,bl0,bl1);
                MMA8(chv[t],al0,al1,al2,al3,bh0,bh1);
            }
        }
    }
    // final: a = anew + sig(gate+gb)*hv
    #pragma unroll
    for (int i=0;i<2;i++){
        int nb=(2*wp+i)*8+2*tig;
        float gb0=gateb[l*128+nb], gb1=gateb[l*128+nb+1];
        g_a[(size_t)(a0+g)*128+nb]    =anew[i][0]+sigf(cga[i][0]+gb0)*chv[i][0];
        g_a[(size_t)(a0+g)*128+nb+1]  =anew[i][1]+sigf(cga[i][1]+gb1)*chv[i][1];
        g_a[(size_t)(a0+g+8)*128+nb]  =anew[i][2]+sigf(cga[i][2]+gb0)*chv[i][2];
        g_a[(size_t)(a0+g+8)*128+nb+1]=anew[i][3]+sigf(cga[i][3]+gb1)*chv[i][3];
    }
}

// K8: atom_out = relu(a @ W_tok^T) -> g_qkv (reuse)
__global__ void __launch_bounds__(256) k_tokproj()
{
    __shared__ __align__(16) float sA[128*SMS];
    int tid=threadIdx.x, j=tid&127, moff=(tid>>7)*8;
    int a0=blockIdx.x*MB;
    for (int idx=tid; idx<128*MB; idx+=256){
        int m=idx>>7,k=idx&127;
        sA[k*SMS+m]=g_a[(size_t)(a0+m)*128+k];
    }
    __syncthreads();
    float q3[3][8]; ZERON8(q3,3);
    gemv8<32,3>(gP_tok + j, 384, sA+moff, q3);
    #pragma unroll
    for (int mi=0;mi<8;mi++){
        size_t b=(size_t)(a0+moff+mi)*384;
        g_qkv[b+j]    =fmaxf(q3[0][mi],0.f);
        g_qkv[b+128+j]=fmaxf(q3[1][mi],0.f);
        g_qkv[b+256+j]=fmaxf(q3[2][mi],0.f);
    }
}

// K9: deterministic segment mean
__global__ void __launch_bounds__(128) k_tokmean(const int* __restrict__ a2t)
{
    __shared__ int slo,shi;
    int t=blockIdx.x;
    if (threadIdx.x==0){
        int lo=0,hi=NATOMS;
        while(lo<hi){int mid=(lo+hi)>>1; if(a2t[mid]<t) lo=mid+1; else hi=mid;}
        slo=lo; int lo2=lo; hi=NATOMS;
        while(lo2<hi){int mid=(lo2+hi)>>1; if(a2t[mid]<t+1) lo2=mid+1; else hi=mid;}
        shi=lo2;
    }
    __syncthreads();
    int lo=slo,hi=shi;
    float inv=1.0f/fmaxf((float)(hi-lo),1.0f);
    #pragma unroll
    for (int s=0;s<3;s++){
        int d=s*128+threadIdx.x;
        float sum=0;
        for (int a=lo;a<hi;a++) sum+=g_qkv[(size_t)a*384+d];
        g_tok[(size_t)t*384+d]=sum*inv;
    }
}

// K10: s_trunk, s_struct -> d_out ; u -> g_u
__global__ void __launch_bounds__(256) k_trunkstruct(float* __restrict__ out)
{
    __shared__ __align__(16) float sT[384*SMS];
    int tid=threadIdx.x, j=tid&127, moff=(tid>>7)*8;
    int t0=blockIdx.x*MB;
    for (int idx=tid; idx<384*MB; idx+=256){
        int m=idx/384, k=idx%384;
        sT[k*SMS+m]=g_tok[(size_t)(t0+m)*384+k];
    }
    __syncthreads();
    {
        float c3[3][8]; ZERON8(c3,3);
        gemv8<96,3>(gP_trunk + j, 384, sT+moff, c3);
        #pragma unroll
        for (int mi=0;mi<8;mi++){
            size_t b=(size_t)(t0+moff+mi)*384;
            out[b+j]=c3[0][mi]; out[b+128+j]=c3[1][mi]; out[b+256+j]=c3[2][mi];
        }
    }
    {
        float* o2 = out + (size_t)NTOK*384;
        float c3[3][8]; ZERON8(c3,3);
        gemv8<96,3>(gP_struc + j, 384, sT+moff, c3);
        #pragma unroll
        for (int mi=0;mi<8;mi++){
            size_t b=(size_t)(t0+moff+mi)*384;
            o2[b+j]=c3[0][mi]; o2[b+128+j]=c3[1][mi]; o2[b+256+j]=c3[2][mi];
        }
    }
    {
        float c2[2][8]; ZERON8(c2,2);
        gemv8<96,2>(gP_outer + j, 256, sT+moff, c2);
        #pragma unroll
        for (int mi=0;mi<8;mi++){
            size_t b=(size_t)(t0+moff+mi)*256;
            g_u[b+j]=c2[0][mi]; g_u[b+128+j]=c2[1][mi];
        }
    }
}

// K11: pair epilogue
__global__ void __launch_bounds__(128) k_pair(const float* __restrict__ tpf,
                                              float* __restrict__ outp)
{
    __shared__ __align__(16) float tj[8*32];
    int i=blockIdx.x, c=threadIdx.x;
    float4 w[8];
    #pragma unroll
    for (int k4=0;k4<8;k4++) w[k4]=gP_pairin[k4*128+c];
    float uiv=g_u[(size_t)i*256+c];
    for (int j0=0;j0<NTOK;j0+=8){
        __syncthreads();
        for (int idx=c; idx<256; idx+=128)
            tj[idx]=tpf[((size_t)i*NTOK+j0)*32 + idx];
        __syncthreads();
        #pragma unroll
        for (int jj=0;jj<8;jj++){
            int j=j0+jj;
            float a=uiv+g_u[(size_t)j*256+128+c];
            const float4* tp=(const float4*)&tj[jj*32];
            #pragma unroll
            for (int k4=0;k4<8;k4++){
                float4 t4=tp[k4];
                a += w[k4].x*t4.x + w[k4].y*t4.y + w[k4].z*t4.z + w[k4].w*t4.w;
            }
            outp[((size_t)i*NTOK+j)*128+c]=a;
        }
    }
}

extern "C" void kernel_launch(void* const* d_in, const int* in_sizes, int n_in,
                              void* d_out, int out_size)
{
    const float* af      = (const float*)d_in[0];
    const float* tpf     = (const float*)d_in[1];
    const float* W_cond  = (const float*)d_in[2];
    const float* W_ph    = (const float*)d_in[3];
    const float* W_pw    = (const float*)d_in[4];
    const float* W_mlp1  = (const float*)d_in[5];
    const float* W_mlp2  = (const float*)d_in[6];
    const float* pb_ln_w = (const float*)d_in[7];
    const float* pb_ln_b = (const float*)d_in[8];
    const float* pb_w    = (const float*)d_in[9];
    const float* sln_w   = (const float*)d_in[10];
    const float* qkv_w   = (const float*)d_in[11];
    const float* q_bias  = (const float*)d_in[12];
    const float* out_w   = (const float*)d_in[13];
    const float* out_b   = (const float*)d_in[14];
    const float* ada_w   = (const float*)d_in[15];
    const float* ta_w    = (const float*)d_in[16];
    const float* tb_w    = (const float*)d_in[17];
    const float* gate_w  = (const float*)d_in[18];
    const float* gate_b  = (const float*)d_in[19];
    const float* W_tok   = (const float*)d_in[20];
    const float* W_trunk = (const float*)d_in[21];
    const float* W_struct= (const float*)d_in[22];
    const float* W_pairin= (const float*)d_in[23];
    const float* W_outer = (const float*)d_in[24];
    const int*   a2t     = (const int*)d_in[28];
    float* out = (float*)d_out;

    PackArgs pa;
    void* p;
    #define SETP(i,sym,srcp,OUTv,Kv,Lv,DOUTv,JOFFv) \
        cudaGetSymbolAddress(&p, sym); \
        pa.d[i] = PackDesc{ srcp, (float*)p, OUTv, Kv, Lv, DOUTv, JOFFv };
    SETP(0, gP_cond,   W_cond,   128,128,1, 128,0);
    SETP(1, gP_ph,     W_ph,      16,128,1,  16,0);
    SETP(2, gP_pw,     W_pw,      16,128,1,  16,0);
    SETP(3, gP_tok,    W_tok,    384,128,1, 384,0);
    SETP(4, gP_trunk,  W_trunk,  384,384,1, 384,0);
    SETP(5, gP_struc,  W_struct, 384,384,1, 384,0);
    SETP(6, gP_pairin, W_pairin, 128, 32,1, 128,0);
    SETP(7, gP_outer,  W_outer,  256,384,1, 256,0);
    #undef SETP
    #define SETM(i,sym,srcp,OUTv,Kv,NTv,NToffv) \
        cudaGetSymbolAddress(&p, sym); \
        pa.m[i] = PackMDesc{ srcp, (float4*)p, OUTv, Kv, NL, NTv, NToffv };
    SETM(0, gPM_sln, sln_w, 256,128, 32,0);
    SETM(1, gPM_qkv, qkv_w, 384,128, 48,0);
    SETM(2, gPM_out, out_w, 128,128, 16,0);
    SETM(3, gPM_ga,  gate_w,128,128, 48,0);
    SETM(4, gPM_ga,  ada_w, 256,128, 48,16);
    SETM(5, gPM_ta,  ta_w,  512,128, 64,0);
    SETM(6, gPM_tb,  tb_w,  128,256, 16,0);
    #undef SETM

    const int NBLK = NATOMS/MB;              // 736
    const int ATTN_SMEM = (4224+1152+4224+4608)*4;  // 56832 B
    const int STC_SMEM  = (2112*3+4224*2)*4;        // 59136 B
    cudaFuncSetAttribute(k_attn,   cudaFuncAttributeMaxDynamicSharedMemorySize, ATTN_SMEM);
    cudaFuncSetAttribute(k_stageC, cudaFuncAttributeMaxDynamicSharedMemorySize, STC_SMEM);

    k_packall<<<dim3(96,15),256>>>(pa);              // 1
    k_cond<<<NBLK,256>>>(af);                        // 2
    k_phpw<<<NATOMS/16 + NB*128/16,256>>>();         // 3
    k_stageA<<<NBLK,256>>>(q_bias,0);                // 4
    k_pb  <<<NB*32,128>>>(W_mlp1,W_mlp2,pb_ln_w,pb_ln_b,pb_w);  // 5

    for (int l=0;l<NL;l++){
        k_attn  <<<NB*4,128,ATTN_SMEM>>>();          // 6 on l=0 <-- profiled
        k_stageC<<<NBLK,256,STC_SMEM>>>(out_b,gate_b,l);
        if (l+1<NL) k_stageA<<<NBLK,256>>>(q_bias,l+1);
    }

    k_tokproj<<<NBLK,256>>>();
    k_tokmean<<<NTOK,128>>>(a2t);
    k_trunkstruct<<<NTOK/MB,256>>>(out);
    k_pair<<<NTOK,128>>>(tpf, out + (size_t)2*NTOK*384);
}